// round 1
// baseline (speedup 1.0000x reference)
#include <cuda_runtime.h>
#include <math.h>

// Problem constants
#define Bc 8
#define Hc 8
#define Fc 768
#define Dc 128
#define Ec 256
#define Lc 13
#define Tc 1000
#define DCORR 8128

// ---------------- device scratch ----------------
__device__ float g_kw[Hc*Lc];
__device__ float g_vw[Hc*Lc];
__device__ float g_kraw[(size_t)Bc*Hc*Fc*Tc];   // [b][h][f][t]  t-contiguous
__device__ float g_vraw[(size_t)Bc*Hc*Fc*Tc];
__device__ float g_mhk[(size_t)Bc*Hc*Tc*Dc];    // [b][h][t][d]  d-contiguous
__device__ float g_mhv[(size_t)Bc*Hc*Tc*Dc];
__device__ float g_muk[Bc*Hc*Dc];
__device__ float g_sdk[Bc*Hc*Dc];
__device__ float g_muv[Bc*Hc*Dc];
__device__ float g_sdv[Bc*Hc*Dc];
__device__ float g_o1[Bc*Hc*Dc];                // [b][h*D+d] == reshape layout
__device__ float g_S[(size_t)Bc*Hc*Dc*Dc];      // raw cross products K^T V
__device__ float g_corr[(size_t)Bc*Hc*DCORR];
__device__ float g_outs[Bc*Hc*Ec];              // [b][h*E+e] == reshape layout
__device__ unsigned short g_iu[DCORR];          // packed (k<<8)|l

// ---------------- stage 0: softmax of mixing weights ----------------
__global__ void k_softmaxw(const float* __restrict__ wk, const float* __restrict__ wv) {
    int tid = threadIdx.x;
    if (tid >= 2*Hc) return;
    int h = tid % Hc;
    const float* src = (tid < Hc ? wk : wv) + h*Lc;
    float* dst = (tid < Hc ? g_kw : g_vw) + h*Lc;
    float m = -1e30f;
    for (int l = 0; l < Lc; l++) m = fmaxf(m, src[l]);
    float e[Lc]; float s = 0.f;
    for (int l = 0; l < Lc; l++) { e[l] = expf(src[l]-m); s += e[l]; }
    float inv = 1.f/s;
    for (int l = 0; l < Lc; l++) dst[l] = e[l]*inv;
}

// ---------------- stage 0b: upper-triangle index table ----------------
__global__ void k_iutab() {
    int k = threadIdx.x;
    if (k >= Dc) return;
    int base = k*(2*Dc-k-1)/2;
    for (int l = k+1; l < Dc; l++)
        g_iu[base + l - k - 1] = (unsigned short)((k << 8) | l);
}

// ---------------- stage 0c: zero S accumulator ----------------
__global__ void k_zeroS() {
    int i = blockIdx.x*blockDim.x + threadIdx.x;
    ((float4*)g_S)[i] = make_float4(0.f,0.f,0.f,0.f);
}

// ---------------- stage 1: L-contraction  x -> k_raw, v_raw ----------------
// grid (ceil(T/256)=4, F, B), block 256. One thread per (b,f,t).
__global__ __launch_bounds__(256) void k_raw(const float* __restrict__ x) {
    __shared__ float skw[Hc*Lc];
    __shared__ float svw[Hc*Lc];
    int tid = threadIdx.x;
    if (tid < Hc*Lc) { skw[tid] = g_kw[tid]; svw[tid] = g_vw[tid]; }
    __syncthreads();
    int t = blockIdx.x*256 + tid;
    int f = blockIdx.y;
    int b = blockIdx.z;
    if (t >= Tc) return;
    const float* xp = x + ((size_t)(b*Fc + f)*Tc + t)*Lc;
    float xv[Lc];
#pragma unroll
    for (int l = 0; l < Lc; l++) xv[l] = xp[l];
    int base = b*Hc*Fc*Tc + f*Tc + t;
#pragma unroll
    for (int h = 0; h < Hc; h++) {
        float kr = 0.f, vr = 0.f;
#pragma unroll
        for (int l = 0; l < Lc; l++) {
            kr += xv[l]*skw[h*Lc + l];
            vr += xv[l]*svw[h*Lc + l];
        }
        g_kraw[base + h*Fc*Tc] = kr;
        g_vraw[base + h*Fc*Tc] = vr;
    }
}

// ---------------- stage 2: per-(b,h) GEMM  mh = W @ raw + bias ----------------
// C[t,d] = sum_f A[f][t] * W[d][f],  A = raw (F x T, t-contig), W = (D x F, f-contig)
// grid (8 t-tiles, B*H, 2 {k,v}), block 256, 128x128 tile, 8x8 microtile.
__global__ __launch_bounds__(256) void k_gemm(
    const float* __restrict__ Wk, const float* __restrict__ bk,
    const float* __restrict__ Wv, const float* __restrict__ bv) {
    __shared__ float As[16][128];
    __shared__ float Ws[16][132];
    int tid = threadIdx.x;
    int bh = blockIdx.y;
    int h = bh % Hc;
    int t0 = blockIdx.x*128;
    bool isv = (blockIdx.z != 0);
    const float* A = (isv ? g_vraw : g_kraw) + (size_t)bh*Fc*Tc;
    const float* W = (isv ? Wv : Wk) + h*Dc*Fc;
    const float* bias = (isv ? bv : bk) + h*Dc;
    float* C = (isv ? g_mhv : g_mhk) + (size_t)bh*Tc*Dc;

    int ty = tid >> 4, tx = tid & 15;
    int wd = tid >> 1, wi0 = (tid & 1)*8;
    float acc[8][8];
#pragma unroll
    for (int r = 0; r < 8; r++)
#pragma unroll
        for (int c = 0; c < 8; c++) acc[r][c] = 0.f;

    for (int kk = 0; kk < Fc/16; kk++) {
        int f0 = kk*16;
        // load A tile (16 f-rows x 128 t) — coalesced float4, zero-padded past T
#pragma unroll
        for (int u = 0; u < 2; u++) {
            int v = tid + u*256;
            int i = v >> 5;
            int c4 = v & 31;
            int t = t0 + c4*4;
            float4 val = make_float4(0.f,0.f,0.f,0.f);
            if (t + 3 < Tc) val = *(const float4*)(A + (f0+i)*Tc + t);
            *(float4*)&As[i][c4*4] = val;
        }
        // load W tile transposed into Ws[f][d]
        {
            const float* wp = W + wd*Fc + f0 + wi0;
            float4 w0 = *(const float4*)(wp);
            float4 w1 = *(const float4*)(wp+4);
            Ws[wi0+0][wd] = w0.x; Ws[wi0+1][wd] = w0.y;
            Ws[wi0+2][wd] = w0.z; Ws[wi0+3][wd] = w0.w;
            Ws[wi0+4][wd] = w1.x; Ws[wi0+5][wd] = w1.y;
            Ws[wi0+6][wd] = w1.z; Ws[wi0+7][wd] = w1.w;
        }
        __syncthreads();
#pragma unroll
        for (int i = 0; i < 16; i++) {
            float4 a0 = *(float4*)&As[i][ty*8];
            float4 a1 = *(float4*)&As[i][ty*8+4];
            float4 b0 = *(float4*)&Ws[i][tx*8];
            float4 b1 = *(float4*)&Ws[i][tx*8+4];
            float ra[8] = {a0.x,a0.y,a0.z,a0.w,a1.x,a1.y,a1.z,a1.w};
            float rb[8] = {b0.x,b0.y,b0.z,b0.w,b1.x,b1.y,b1.z,b1.w};
#pragma unroll
            for (int r = 0; r < 8; r++)
#pragma unroll
                for (int c = 0; c < 8; c++) acc[r][c] += ra[r]*rb[c];
        }
        __syncthreads();
    }
    float bb[8];
#pragma unroll
    for (int c = 0; c < 8; c++) bb[c] = bias[tx*8 + c];
#pragma unroll
    for (int r = 0; r < 8; r++) {
        int t = t0 + ty*8 + r;
        if (t < Tc) {
            float4 o0 = make_float4(acc[r][0]+bb[0], acc[r][1]+bb[1], acc[r][2]+bb[2], acc[r][3]+bb[3]);
            float4 o1 = make_float4(acc[r][4]+bb[4], acc[r][5]+bb[5], acc[r][6]+bb[6], acc[r][7]+bb[7]);
            *(float4*)(C + (size_t)t*Dc + tx*8)   = o0;
            *(float4*)(C + (size_t)t*Dc + tx*8+4) = o1;
        }
    }
}

// ---------------- stage 3a: stats + attention + o1 ----------------
// grid B*H, block 256.
__global__ __launch_bounds__(256) void k_attn(const float* __restrict__ q) {
    __shared__ float s_sc[Tc];
    __shared__ float s_red[256];
    __shared__ float s_q[Dc];
    int tid = threadIdx.x;
    int bh = blockIdx.x;
    int h = bh % Hc;
    const float* K = g_mhk + (size_t)bh*Tc*Dc;
    const float* V = g_mhv + (size_t)bh*Tc*Dc;
    if (tid < Dc) s_q[tid] = q[h*Dc + tid];

    // per-d mean/std over t (ddof=1), threads 0..127 -> K, 128..255 -> V
    {
        int d = tid & 127;
        const float* M = (tid < 128) ? K : V;
        float s1 = 0.f, s2 = 0.f;
        for (int t = 0; t < Tc; t++) {
            float v = M[t*Dc + d];
            s1 += v; s2 += v*v;
        }
        float mu = s1 * (1.f/Tc);
        float var = (s2 - (float)Tc*mu*mu) * (1.f/(Tc-1));
        var = fmaxf(var, 0.f);
        float sd = sqrtf(var) + 1e-9f;
        if (tid < 128) { g_muk[bh*Dc+d] = mu; g_sdk[bh*Dc+d] = sd; }
        else           { g_muv[bh*Dc+d] = mu; g_sdv[bh*Dc+d] = sd; }
    }
    __syncthreads();

    // scores[t] = q . K[t] / sqrt(D)
    int w = tid >> 5, lane = tid & 31;
    for (int t = w; t < Tc; t += 8) {
        const float* kr = K + t*Dc;
        float s = 0.f;
#pragma unroll
        for (int j = 0; j < 4; j++) {
            int d = lane + j*32;
            s += kr[d]*s_q[d];
        }
        for (int off = 16; off; off >>= 1) s += __shfl_down_sync(0xffffffffu, s, off);
        if (lane == 0) s_sc[t] = s * 0.08838834764831845f;
    }
    __syncthreads();

    // softmax over t
    float lm = -1e30f;
    for (int t = tid; t < Tc; t += 256) lm = fmaxf(lm, s_sc[t]);
    s_red[tid] = lm; __syncthreads();
    for (int s = 128; s; s >>= 1) { if (tid < s) s_red[tid] = fmaxf(s_red[tid], s_red[tid+s]); __syncthreads(); }
    float m = s_red[0];
    __syncthreads();
    float ls = 0.f;
    for (int t = tid; t < Tc; t += 256) { float e = expf(s_sc[t]-m); s_sc[t] = e; ls += e; }
    s_red[tid] = ls; __syncthreads();
    for (int s = 128; s; s >>= 1) { if (tid < s) s_red[tid] += s_red[tid+s]; __syncthreads(); }
    float inv = 1.f / s_red[0];
    __syncthreads();

    // o1[d] = sum_t attn[t] * V[t][d]
    {
        int d = tid & 127;
        int half = tid >> 7;
        float acc = 0.f;
        int tb = half*500;
        for (int t = tb; t < tb+500; t++) acc += s_sc[t]*V[t*Dc + d];
        s_red[tid] = acc*inv;
        __syncthreads();
        if (tid < 128) g_o1[bh*Dc + tid] = s_red[tid] + s_red[tid+128];
    }
}

// ---------------- stage 3b: S[k][l] = sum_t K[t][k]*V[t][l] (t-split x4) ----------------
// grid (4, B*H), block 256, 8x8 microtile, atomicAdd combine.
__global__ __launch_bounds__(256) void k_smat() {
    __shared__ float Ks[8][128];
    __shared__ float Vs[8][128];
    int tid = threadIdx.x;
    int bh = blockIdx.y;
    int seg = blockIdx.x;
    const float* K = g_mhk + (size_t)bh*Tc*Dc;
    const float* V = g_mhv + (size_t)bh*Tc*Dc;
    int tbeg = seg*250;
    int ty = tid >> 4, tx = tid & 15;
    int lrow = tid >> 5, lc = (tid & 31)*4;
    float acc[8][8];
#pragma unroll
    for (int r = 0; r < 8; r++)
#pragma unroll
        for (int c = 0; c < 8; c++) acc[r][c] = 0.f;

    for (int ch = 0; ch < 32; ch++) {
        int rt = ch*8 + lrow;
        float4 kv = make_float4(0.f,0.f,0.f,0.f), vv = kv;
        if (rt < 250) {
            int t = tbeg + rt;
            kv = *(const float4*)(K + (size_t)t*Dc + lc);
            vv = *(const float4*)(V + (size_t)t*Dc + lc);
        }
        *(float4*)&Ks[lrow][lc] = kv;
        *(float4*)&Vs[lrow][lc] = vv;
        __syncthreads();
#pragma unroll
        for (int tt = 0; tt < 8; tt++) {
            float4 k0 = *(float4*)&Ks[tt][ty*8];
            float4 k1 = *(float4*)&Ks[tt][ty*8+4];
            float4 v0 = *(float4*)&Vs[tt][tx*8];
            float4 v1 = *(float4*)&Vs[tt][tx*8+4];
            float rk[8] = {k0.x,k0.y,k0.z,k0.w,k1.x,k1.y,k1.z,k1.w};
            float rv[8] = {v0.x,v0.y,v0.z,v0.w,v1.x,v1.y,v1.z,v1.w};
#pragma unroll
            for (int r = 0; r < 8; r++)
#pragma unroll
                for (int c = 0; c < 8; c++) acc[r][c] += rk[r]*rv[c];
        }
        __syncthreads();
    }
    float* Sp = g_S + (size_t)bh*Dc*Dc;
#pragma unroll
    for (int r = 0; r < 8; r++)
#pragma unroll
        for (int c = 0; c < 8; c++)
            atomicAdd(&Sp[(ty*8+r)*Dc + tx*8 + c], acc[r][c]);
}

// ---------------- stage 3c: normalized correlation, packed upper triangle ----------------
__global__ void k_corr() {
    int c = blockIdx.x*256 + threadIdx.x;
    int bh = blockIdx.y;
    if (c >= DCORR) return;
    int pr = g_iu[c];
    int k = pr >> 8, l = pr & 255;
    float muk = g_muk[bh*Dc + k], sdk = g_sdk[bh*Dc + k];
    float muv = g_muv[bh*Dc + l], sdv = g_sdv[bh*Dc + l];
    float S = g_S[(size_t)bh*Dc*Dc + k*Dc + l];
    g_corr[(size_t)bh*DCORR + c] = (S - (float)Tc*muk*muv) / ((float)Tc*sdk*sdv);
}

// ---------------- stage 4: outs[b,h,e] = corr . Wproj[h,e,:] + bproj ----------------
// grid (E/32, H), block 256 = (8 b x 32 e)
__global__ __launch_bounds__(256) void k_proj(
    const float* __restrict__ Wproj, const float* __restrict__ bproj) {
    __shared__ float sc[8][128];
    int tid = threadIdx.x;
    int h = blockIdx.y;
    int el = tid & 31;
    int b = tid >> 5;
    int e = blockIdx.x*32 + el;
    int lrow = tid >> 5;         // == b
    int lc = (tid & 31)*4;
    const float* wrow = Wproj + ((size_t)h*Ec + e)*DCORR;
    float acc = 0.f;
    for (int c0 = 0; c0 < DCORR; c0 += 128) {
        int lim = DCORR - c0; if (lim > 128) lim = 128;
        float4 cv = make_float4(0.f,0.f,0.f,0.f);
        if (lc < lim) cv = *(const float4*)(g_corr + ((size_t)lrow*Hc + h)*DCORR + c0 + lc);
        *(float4*)&sc[lrow][lc] = cv;
        __syncthreads();
#pragma unroll 8
        for (int j = 0; j < lim; j += 4) {
            float4 wv = *(const float4*)(wrow + c0 + j);
            float4 sv = *(const float4*)&sc[b][j];
            acc += wv.x*sv.x + wv.y*sv.y + wv.z*sv.z + wv.w*sv.w;
        }
        __syncthreads();
    }
    g_outs[b*(Hc*Ec) + h*Ec + e] = acc + bproj[h*Ec + e];
}

// ---------------- stage 5: final linears + mix ----------------
// grid B, block 256 (one thread per e)
__global__ __launch_bounds__(256) void k_final(
    const float* __restrict__ WT, const float* __restrict__ bT,
    const float* __restrict__ Wp, const float* __restrict__ bp,
    float* __restrict__ out) {
    __shared__ float so1[Hc*Dc];   // 1024
    __shared__ float sout[Hc*Ec];  // 2048
    int b = blockIdx.x;
    int tid = threadIdx.x;
    for (int j = tid; j < Hc*Dc; j += 256) so1[j]  = g_o1[b*Hc*Dc + j];
    for (int j = tid; j < Hc*Ec; j += 256) sout[j] = g_outs[b*Hc*Ec + j];
    __syncthreads();
    int e = tid;
    float aT = bT[e];
    float aF = bp[e];
    const float* wt = WT + (size_t)e*(Hc*Dc);
#pragma unroll 4
    for (int j = 0; j < Hc*Dc; j += 4) {
        float4 wv = *(const float4*)(wt + j);
        float4 sv = *(const float4*)&so1[j];
        aT += wv.x*sv.x + wv.y*sv.y + wv.z*sv.z + wv.w*sv.w;
    }
    const float* wp = Wp + (size_t)e*(Hc*Ec);
#pragma unroll 4
    for (int j = 0; j < Hc*Ec; j += 4) {
        float4 wv = *(const float4*)(wp + j);
        float4 sv = *(const float4*)&sout[j];
        aF += wv.x*sv.x + wv.y*sv.y + wv.z*sv.z + wv.w*sv.w;
    }
    out[b*Ec + e] = 0.5f*(aT + aF);
}

// ---------------- launch ----------------
extern "C" void kernel_launch(void* const* d_in, const int* in_sizes, int n_in,
                              void* d_out, int out_size) {
    const float* x     = (const float*)d_in[0];
    const float* wk    = (const float*)d_in[1];
    const float* wv    = (const float*)d_in[2];
    const float* q     = (const float*)d_in[3];
    const float* Wk    = (const float*)d_in[4];
    const float* bk    = (const float*)d_in[5];
    const float* Wv    = (const float*)d_in[6];
    const float* bv    = (const float*)d_in[7];
    const float* Wproj = (const float*)d_in[8];
    const float* bproj = (const float*)d_in[9];
    const float* WT    = (const float*)d_in[10];
    const float* bT    = (const float*)d_in[11];
    const float* Wp    = (const float*)d_in[12];
    const float* bp    = (const float*)d_in[13];
    float* out = (float*)d_out;

    k_softmaxw<<<1, 32>>>(wk, wv);
    k_iutab<<<1, 128>>>();
    k_zeroS<<<(Bc*Hc*Dc*Dc/4)/256, 256>>>();
    k_raw<<<dim3((Tc+255)/256, Fc, Bc), 256>>>(x);
    k_gemm<<<dim3((Tc+127)/128, Bc*Hc, 2), 256>>>(Wk, bk, Wv, bv);
    k_attn<<<Bc*Hc, 256>>>(q);
    k_smat<<<dim3(4, Bc*Hc), 256>>>();
    k_corr<<<dim3((DCORR+255)/256, Bc*Hc), 256>>>();
    k_proj<<<dim3(Ec/32, Hc), 256>>>(Wproj, bproj);
    k_final<<<Bc, 256>>>(WT, bT, Wp, bp, out);
}

// round 2
// speedup vs baseline: 1.1423x; 1.1423x over previous
#include <cuda_runtime.h>
#include <cuda_bf16.h>
#include <math.h>

// Problem constants
#define Bc 8
#define Hc 8
#define Fc 768
#define Dc 128
#define Ec 256
#define Lc 13
#define Tc 1000
#define DCORR 8128

// ---------------- device scratch ----------------
__device__ float g_kw[Hc*Lc];
__device__ float g_vw[Hc*Lc];
// packed bf16 (hi in low 16 bits, lo in high 16 bits), layout [b][h][t][f] (f contig)
__device__ unsigned g_kb[(size_t)Bc*Hc*Tc*Fc];
__device__ unsigned g_vb[(size_t)Bc*Hc*Tc*Fc];
__device__ unsigned g_wb[(size_t)2*Hc*Dc*Fc];   // [kv][h][d][f] packed bf16 hi/lo
__device__ float g_mhk[(size_t)Bc*Hc*Tc*Dc];    // [b][h][t][d]  d-contiguous
__device__ float g_mhv[(size_t)Bc*Hc*Tc*Dc];
__device__ float g_muk[Bc*Hc*Dc];
__device__ float g_sdk[Bc*Hc*Dc];
__device__ float g_muv[Bc*Hc*Dc];
__device__ float g_sdv[Bc*Hc*Dc];
__device__ float g_o1[Bc*Hc*Dc];
__device__ float g_S[(size_t)Bc*Hc*Dc*Dc];
__device__ float g_corr[(size_t)Bc*Hc*DCORR];
__device__ float g_outs[Bc*Hc*Ec];
__device__ unsigned short g_iu[DCORR];

__device__ __forceinline__ unsigned pack_hilo(float v) {
    __nv_bfloat16 h = __float2bfloat16(v);
    float fh = __bfloat162float(h);
    __nv_bfloat16 l = __float2bfloat16(v - fh);
    return (unsigned)__bfloat16_as_ushort(h) | ((unsigned)__bfloat16_as_ushort(l) << 16);
}

// ---------------- stage 0: softmax of mixing weights ----------------
__global__ void k_softmaxw(const float* __restrict__ wk, const float* __restrict__ wv) {
    int tid = threadIdx.x;
    if (tid >= 2*Hc) return;
    int h = tid % Hc;
    const float* src = (tid < Hc ? wk : wv) + h*Lc;
    float* dst = (tid < Hc ? g_kw : g_vw) + h*Lc;
    float m = -1e30f;
    for (int l = 0; l < Lc; l++) m = fmaxf(m, src[l]);
    float e[Lc]; float s = 0.f;
    for (int l = 0; l < Lc; l++) { e[l] = expf(src[l]-m); s += e[l]; }
    float inv = 1.f/s;
    for (int l = 0; l < Lc; l++) dst[l] = e[l]*inv;
}

// ---------------- stage 0b: upper-triangle index table ----------------
__global__ void k_iutab() {
    int k = threadIdx.x;
    if (k >= Dc) return;
    int base = k*(2*Dc-k-1)/2;
    for (int l = k+1; l < Dc; l++)
        g_iu[base + l - k - 1] = (unsigned short)((k << 8) | l);
}

// ---------------- stage 0c: zero S accumulator ----------------
__global__ void k_zeroS() {
    int i = blockIdx.x*blockDim.x + threadIdx.x;
    ((float4*)g_S)[i] = make_float4(0.f,0.f,0.f,0.f);
}

// ---------------- stage 0d: pack W to bf16 hi/lo ----------------
__global__ void k_wconv(const float* __restrict__ Wk, const float* __restrict__ Wv) {
    size_t i = (size_t)blockIdx.x*256 + threadIdx.x;
    const float* W = blockIdx.y ? Wv : Wk;
    g_wb[(size_t)blockIdx.y*(Hc*Dc*Fc) + i] = pack_hilo(W[i]);
}

// ---------------- stage 1: L-contraction -> packed bf16 raw [t][f] ----------------
// block (32 t, 8 f), grid (ceil(T/32), F/8, B). smem transpose for coalesced writes.
__global__ __launch_bounds__(256) void k_raw(const float* __restrict__ x) {
    __shared__ float skw[Hc*Lc];
    __shared__ float svw[Hc*Lc];
    __shared__ unsigned s_pk[2][Hc][8][32];   // [kv][h][f_local][t_local]
    int tid = threadIdx.y*32 + threadIdx.x;
    if (tid < Hc*Lc) { skw[tid] = g_kw[tid]; svw[tid] = g_vw[tid]; }
    __syncthreads();

    int tx = threadIdx.x;          // t lane
    int ty = threadIdx.y;          // f
    int t0 = blockIdx.x*32;
    int f0 = blockIdx.y*8;
    int b  = blockIdx.z;
    int t = t0 + tx;
    int f = f0 + ty;

    float xv[Lc];
    if (t < Tc) {
        const float* xp = x + ((size_t)(b*Fc + f)*Tc + t)*Lc;
#pragma unroll
        for (int l = 0; l < Lc; l++) xv[l] = xp[l];
    } else {
#pragma unroll
        for (int l = 0; l < Lc; l++) xv[l] = 0.f;
    }
#pragma unroll
    for (int h = 0; h < Hc; h++) {
        float kr = 0.f, vr = 0.f;
#pragma unroll
        for (int l = 0; l < Lc; l++) {
            kr += xv[l]*skw[h*Lc + l];
            vr += xv[l]*svw[h*Lc + l];
        }
        s_pk[0][h][ty][tx] = pack_hilo(kr);
        s_pk[1][h][ty][tx] = pack_hilo(vr);
    }
    __syncthreads();

    // write phase: warps write f-contiguous segments of 8
    int w = tid >> 5, lane = tid & 31;
    int fi = lane & 7;          // f local
    int tq = lane >> 3;         // 0..3
#pragma unroll
    for (int u = 0; u < 16; u++) {
        int job = u*8 + w;      // 0..127
        int tch = job & 7;
        int kv = (job >> 3) & 1;
        int h = job >> 4;
        int tl = tch*4 + tq;
        int tt = t0 + tl;
        if (tt < Tc) {
            unsigned* dst = (kv ? g_vb : g_kb) +
                ((size_t)(b*Hc + h)*Tc + tt)*Fc + f0 + fi;
            *dst = s_pk[kv][h][fi][tl];
        }
    }
}

// ---------------- stage 2: tensor-core GEMM (bf16 3-term split) ----------------
// C[t,d] = sum_f A[t,f]*W[d,f] + bias[d]
// tiles: M=64 (t), N=128 (d, all), K-chunk=32 (f). 8 warps, warp tile 32x32.
#define WS 20   // smem row stride in 32-bit words (40 bf16)

#define MMA_BF16(d, a, b) asm volatile( \
    "mma.sync.aligned.m16n8k16.row.col.f32.bf16.bf16.f32 " \
    "{%0,%1,%2,%3},{%4,%5,%6,%7},{%8,%9},{%0,%1,%2,%3};\n" \
    : "+f"(d[0]), "+f"(d[1]), "+f"(d[2]), "+f"(d[3]) \
    : "r"(a[0]), "r"(a[1]), "r"(a[2]), "r"(a[3]), "r"(b[0]), "r"(b[1]))

__global__ __launch_bounds__(256) void k_gemm(
    const float* __restrict__ bk, const float* __restrict__ bv) {
    __shared__ unsigned sAhi[64*WS];
    __shared__ unsigned sAlo[64*WS];
    __shared__ unsigned sBhi[128*WS];
    __shared__ unsigned sBlo[128*WS];

    int tid = threadIdx.x;
    int bh = blockIdx.y;
    int h = bh & 7;
    int t0 = blockIdx.x*64;
    bool isv = (blockIdx.z != 0);
    const unsigned* Apk = (isv ? g_vb : g_kb) + (size_t)bh*Tc*Fc;
    const unsigned* Bpk = g_wb + ((size_t)(isv ? 1 : 0)*Hc + h)*Dc*Fc;
    const float* bias = (isv ? bv : bk) + h*Dc;
    float* C = (isv ? g_mhv : g_mhk) + (size_t)bh*Tc*Dc;

    int warp = tid >> 5, lane = tid & 31;
    int g = lane >> 2, q = lane & 3;
    int wm0 = (warp >> 2)*32;   // 0 or 32
    int wn0 = (warp & 3)*32;    // 0,32,64,96

    float acc[2][4][4];
#pragma unroll
    for (int i = 0; i < 2; i++)
#pragma unroll
        for (int j = 0; j < 4; j++)
#pragma unroll
            for (int r = 0; r < 4; r++) acc[i][j][r] = 0.f;

    for (int kc = 0; kc < Fc; kc += 32) {
        // load A: 64 rows x 16 pairs
#pragma unroll
        for (int it = 0; it < 4; it++) {
            int idx = tid + it*256;
            int row = idx >> 4;
            int pr = idx & 15;
            int t = t0 + row;
            uint2 v = make_uint2(0u, 0u);
            if (t < Tc) v = *(const uint2*)(Apk + (size_t)t*Fc + kc + pr*2);
            sAhi[row*WS + pr] = __byte_perm(v.x, v.y, 0x5410);
            sAlo[row*WS + pr] = __byte_perm(v.x, v.y, 0x7632);
        }
        // load B: 128 rows x 16 pairs
#pragma unroll
        for (int it = 0; it < 8; it++) {
            int idx = tid + it*256;
            int row = idx >> 4;
            int pr = idx & 15;
            uint2 v = *(const uint2*)(Bpk + (size_t)row*Fc + kc + pr*2);
            sBhi[row*WS + pr] = __byte_perm(v.x, v.y, 0x5410);
            sBlo[row*WS + pr] = __byte_perm(v.x, v.y, 0x7632);
        }
        __syncthreads();

#pragma unroll
        for (int ks = 0; ks < 2; ks++) {
            unsigned ah[2][4], al[2][4], bhf[4][2], blf[4][2];
#pragma unroll
            for (int i = 0; i < 2; i++) {
                int base = (wm0 + i*16 + g)*WS + ks*8 + q;
                ah[i][0] = sAhi[base];       ah[i][1] = sAhi[base + 8*WS];
                ah[i][2] = sAhi[base + 4];   ah[i][3] = sAhi[base + 8*WS + 4];
                al[i][0] = sAlo[base];       al[i][1] = sAlo[base + 8*WS];
                al[i][2] = sAlo[base + 4];   al[i][3] = sAlo[base + 8*WS + 4];
            }
#pragma unroll
            for (int j = 0; j < 4; j++) {
                int base = (wn0 + j*8 + g)*WS + ks*8 + q;
                bhf[j][0] = sBhi[base]; bhf[j][1] = sBhi[base + 4];
                blf[j][0] = sBlo[base]; blf[j][1] = sBlo[base + 4];
            }
#pragma unroll
            for (int i = 0; i < 2; i++)
#pragma unroll
                for (int j = 0; j < 4; j++) {
                    MMA_BF16(acc[i][j], ah[i], bhf[j]);
                    MMA_BF16(acc[i][j], ah[i], blf[j]);
                    MMA_BF16(acc[i][j], al[i], bhf[j]);
                }
        }
        __syncthreads();
    }

    // epilogue
#pragma unroll
    for (int j = 0; j < 4; j++) {
        int d = wn0 + j*8 + (q << 1);
        float2 bia = *(const float2*)(bias + d);
#pragma unroll
        for (int i = 0; i < 2; i++) {
            int t = t0 + wm0 + i*16 + g;
            if (t < Tc) {
                float2 o = make_float2(acc[i][j][0] + bia.x, acc[i][j][1] + bia.y);
                *(float2*)(C + (size_t)t*Dc + d) = o;
            }
            if (t + 8 < Tc) {
                float2 o = make_float2(acc[i][j][2] + bia.x, acc[i][j][3] + bia.y);
                *(float2*)(C + (size_t)(t+8)*Dc + d) = o;
            }
        }
    }
}

// ---------------- stage 3a: stats + attention + o1 ----------------
__global__ __launch_bounds__(256) void k_attn(const float* __restrict__ q) {
    __shared__ float s_sc[Tc];
    __shared__ float s_red[256];
    __shared__ float s_q[Dc];
    int tid = threadIdx.x;
    int bh = blockIdx.x;
    int h = bh % Hc;
    const float* K = g_mhk + (size_t)bh*Tc*Dc;
    const float* V = g_mhv + (size_t)bh*Tc*Dc;
    if (tid < Dc) s_q[tid] = q[h*Dc + tid];

    {
        int d = tid & 127;
        const float* M = (tid < 128) ? K : V;
        float s1 = 0.f, s2 = 0.f;
        for (int t = 0; t < Tc; t++) {
            float v = M[t*Dc + d];
            s1 += v; s2 += v*v;
        }
        float mu = s1 * (1.f/Tc);
        float var = (s2 - (float)Tc*mu*mu) * (1.f/(Tc-1));
        var = fmaxf(var, 0.f);
        float sd = sqrtf(var) + 1e-9f;
        if (tid < 128) { g_muk[bh*Dc+d] = mu; g_sdk[bh*Dc+d] = sd; }
        else           { g_muv[bh*Dc+d] = mu; g_sdv[bh*Dc+d] = sd; }
    }
    __syncthreads();

    int w = tid >> 5, lane = tid & 31;
    for (int t = w; t < Tc; t += 8) {
        const float* kr = K + t*Dc;
        float s = 0.f;
#pragma unroll
        for (int j = 0; j < 4; j++) {
            int d = lane + j*32;
            s += kr[d]*s_q[d];
        }
        for (int off = 16; off; off >>= 1) s += __shfl_down_sync(0xffffffffu, s, off);
        if (lane == 0) s_sc[t] = s * 0.08838834764831845f;
    }
    __syncthreads();

    float lm = -1e30f;
    for (int t = tid; t < Tc; t += 256) lm = fmaxf(lm, s_sc[t]);
    s_red[tid] = lm; __syncthreads();
    for (int s = 128; s; s >>= 1) { if (tid < s) s_red[tid] = fmaxf(s_red[tid], s_red[tid+s]); __syncthreads(); }
    float m = s_red[0];
    __syncthreads();
    float ls = 0.f;
    for (int t = tid; t < Tc; t += 256) { float e = expf(s_sc[t]-m); s_sc[t] = e; ls += e; }
    s_red[tid] = ls; __syncthreads();
    for (int s = 128; s; s >>= 1) { if (tid < s) s_red[tid] += s_red[tid+s]; __syncthreads(); }
    float inv = 1.f / s_red[0];
    __syncthreads();

    {
        int d = tid & 127;
        int half = tid >> 7;
        float acc = 0.f;
        int tb = half*500;
        for (int t = tb; t < tb+500; t++) acc += s_sc[t]*V[t*Dc + d];
        s_red[tid] = acc*inv;
        __syncthreads();
        if (tid < 128) g_o1[bh*Dc + tid] = s_red[tid] + s_red[tid+128];
    }
}

// ---------------- stage 3b: S[k][l] = sum_t K[t][k]*V[t][l] ----------------
__global__ __launch_bounds__(256) void k_smat() {
    __shared__ float Ks[8][128];
    __shared__ float Vs[8][128];
    int tid = threadIdx.x;
    int bh = blockIdx.y;
    int seg = blockIdx.x;
    const float* K = g_mhk + (size_t)bh*Tc*Dc;
    const float* V = g_mhv + (size_t)bh*Tc*Dc;
    int tbeg = seg*250;
    int ty = tid >> 4, tx = tid & 15;
    int lrow = tid >> 5, lc = (tid & 31)*4;
    float acc[8][8];
#pragma unroll
    for (int r = 0; r < 8; r++)
#pragma unroll
        for (int c = 0; c < 8; c++) acc[r][c] = 0.f;

    for (int ch = 0; ch < 32; ch++) {
        int rt = ch*8 + lrow;
        float4 kv = make_float4(0.f,0.f,0.f,0.f), vv = kv;
        if (rt < 250) {
            int t = tbeg + rt;
            kv = *(const float4*)(K + (size_t)t*Dc + lc);
            vv = *(const float4*)(V + (size_t)t*Dc + lc);
        }
        *(float4*)&Ks[lrow][lc] = kv;
        *(float4*)&Vs[lrow][lc] = vv;
        __syncthreads();
#pragma unroll
        for (int tt = 0; tt < 8; tt++) {
            float4 k0 = *(float4*)&Ks[tt][ty*8];
            float4 k1 = *(float4*)&Ks[tt][ty*8+4];
            float4 v0 = *(float4*)&Vs[tt][tx*8];
            float4 v1 = *(float4*)&Vs[tt][tx*8+4];
            float rk[8] = {k0.x,k0.y,k0.z,k0.w,k1.x,k1.y,k1.z,k1.w};
            float rv[8] = {v0.x,v0.y,v0.z,v0.w,v1.x,v1.y,v1.z,v1.w};
#pragma unroll
            for (int r = 0; r < 8; r++)
#pragma unroll
                for (int c = 0; c < 8; c++) acc[r][c] += rk[r]*rv[c];
        }
        __syncthreads();
    }
    float* Sp = g_S + (size_t)bh*Dc*Dc;
#pragma unroll
    for (int r = 0; r < 8; r++)
#pragma unroll
        for (int c = 0; c < 8; c++)
            atomicAdd(&Sp[(ty*8+r)*Dc + tx*8 + c], acc[r][c]);
}

// ---------------- stage 3c: normalized correlation ----------------
__global__ void k_corr() {
    int c = blockIdx.x*256 + threadIdx.x;
    int bh = blockIdx.y;
    if (c >= DCORR) return;
    int pr = g_iu[c];
    int k = pr >> 8, l = pr & 255;
    float muk = g_muk[bh*Dc + k], sdk = g_sdk[bh*Dc + k];
    float muv = g_muv[bh*Dc + l], sdv = g_sdv[bh*Dc + l];
    float S = g_S[(size_t)bh*Dc*Dc + k*Dc + l];
    g_corr[(size_t)bh*DCORR + c] = (S - (float)Tc*muk*muv) / ((float)Tc*sdk*sdv);
}

// ---------------- stage 4: outs = corr . Wproj + bproj ----------------
__global__ __launch_bounds__(256) void k_proj(
    const float* __restrict__ Wproj, const float* __restrict__ bproj) {
    __shared__ float sc[8][128];
    int tid = threadIdx.x;
    int h = blockIdx.y;
    int el = tid & 31;
    int b = tid >> 5;
    int e = blockIdx.x*32 + el;
    int lrow = tid >> 5;
    int lc = (tid & 31)*4;
    const float* wrow = Wproj + ((size_t)h*Ec + e)*DCORR;
    float acc = 0.f;
    for (int c0 = 0; c0 < DCORR; c0 += 128) {
        int lim = DCORR - c0; if (lim > 128) lim = 128;
        float4 cv = make_float4(0.f,0.f,0.f,0.f);
        if (lc < lim) cv = *(const float4*)(g_corr + ((size_t)lrow*Hc + h)*DCORR + c0 + lc);
        *(float4*)&sc[lrow][lc] = cv;
        __syncthreads();
#pragma unroll 8
        for (int j = 0; j < lim; j += 4) {
            float4 wv = *(const float4*)(wrow + c0 + j);
            float4 sv = *(const float4*)&sc[b][j];
            acc += wv.x*sv.x + wv.y*sv.y + wv.z*sv.z + wv.w*sv.w;
        }
        __syncthreads();
    }
    g_outs[b*(Hc*Ec) + h*Ec + e] = acc + bproj[h*Ec + e];
}

// ---------------- stage 5: final linears + mix ----------------
__global__ __launch_bounds__(256) void k_final(
    const float* __restrict__ WT, const float* __restrict__ bT,
    const float* __restrict__ Wp, const float* __restrict__ bp,
    float* __restrict__ out) {
    __shared__ float so1[Hc*Dc];
    __shared__ float sout[Hc*Ec];
    int b = blockIdx.x;
    int tid = threadIdx.x;
    for (int j = tid; j < Hc*Dc; j += 256) so1[j]  = g_o1[b*Hc*Dc + j];
    for (int j = tid; j < Hc*Ec; j += 256) sout[j] = g_outs[b*Hc*Ec + j];
    __syncthreads();
    int e = tid;
    float aT = bT[e];
    float aF = bp[e];
    const float* wt = WT + (size_t)e*(Hc*Dc);
#pragma unroll 4
    for (int j = 0; j < Hc*Dc; j += 4) {
        float4 wv = *(const float4*)(wt + j);
        float4 sv = *(const float4*)&so1[j];
        aT += wv.x*sv.x + wv.y*sv.y + wv.z*sv.z + wv.w*sv.w;
    }
    const float* wp = Wp + (size_t)e*(Hc*Ec);
#pragma unroll 4
    for (int j = 0; j < Hc*Ec; j += 4) {
        float4 wv = *(const float4*)(wp + j);
        float4 sv = *(const float4*)&sout[j];
        aF += wv.x*sv.x + wv.y*sv.y + wv.z*sv.z + wv.w*sv.w;
    }
    out[b*Ec + e] = 0.5f*(aT + aF);
}

// ---------------- launch ----------------
extern "C" void kernel_launch(void* const* d_in, const int* in_sizes, int n_in,
                              void* d_out, int out_size) {
    const float* x     = (const float*)d_in[0];
    const float* wk    = (const float*)d_in[1];
    const float* wv    = (const float*)d_in[2];
    const float* q     = (const float*)d_in[3];
    const float* Wk    = (const float*)d_in[4];
    const float* bk    = (const float*)d_in[5];
    const float* Wv    = (const float*)d_in[6];
    const float* bv    = (const float*)d_in[7];
    const float* Wproj = (const float*)d_in[8];
    const float* bproj = (const float*)d_in[9];
    const float* WT    = (const float*)d_in[10];
    const float* bT    = (const float*)d_in[11];
    const float* Wp    = (const float*)d_in[12];
    const float* bp    = (const float*)d_in[13];
    float* out = (float*)d_out;

    k_softmaxw<<<1, 32>>>(wk, wv);
    k_iutab<<<1, 128>>>();
    k_zeroS<<<(Bc*Hc*Dc*Dc/4)/256, 256>>>();
    k_wconv<<<dim3((Hc*Dc*Fc)/256, 2), 256>>>(Wk, Wv);
    k_raw<<<dim3((Tc+31)/32, Fc/8, Bc), dim3(32, 8)>>>(x);
    k_gemm<<<dim3((Tc+63)/64, Bc*Hc, 2), 256>>>(bk, bv);
    k_attn<<<Bc*Hc, 256>>>(q);
    k_smat<<<dim3(4, Bc*Hc), 256>>>();
    k_corr<<<dim3((DCORR+255)/256, Bc*Hc), 256>>>();
    k_proj<<<dim3(Ec/32, Hc), 256>>>(Wproj, bproj);
    k_final<<<Bc, 256>>>(WT, bT, Wp, bp, out);
}

// round 4
// speedup vs baseline: 1.2095x; 1.0589x over previous
#include <cuda_runtime.h>
#include <cuda_bf16.h>
#include <math.h>
#include <stdint.h>

// Problem constants
#define Bc 8
#define Hc 8
#define Fc 768
#define Dc 128
#define Ec 256
#define Lc 13
#define Tc 1000
#define DCORR 8128

// ---------------- device scratch ----------------
__device__ float g_kw[Hc*Lc];
__device__ float g_vw[Hc*Lc];
// bf16 hi/lo planes, layout [kv][b][h][t][f] (f contiguous)
__device__ __nv_bfloat16 g_ahi[(size_t)2*Bc*Hc*Tc*Fc];
__device__ __nv_bfloat16 g_alo[(size_t)2*Bc*Hc*Tc*Fc];
// weights planes [kv][h][d][f]
__device__ __nv_bfloat16 g_whi[(size_t)2*Hc*Dc*Fc];
__device__ __nv_bfloat16 g_wlo[(size_t)2*Hc*Dc*Fc];
__device__ float g_mhk[(size_t)Bc*Hc*Tc*Dc];    // [b][h][t][d]
__device__ float g_mhv[(size_t)Bc*Hc*Tc*Dc];
__device__ float g_muk[Bc*Hc*Dc];
__device__ float g_sdk[Bc*Hc*Dc];
__device__ float g_muv[Bc*Hc*Dc];
__device__ float g_sdv[Bc*Hc*Dc];
__device__ float g_o1[Bc*Hc*Dc];
__device__ float g_S[(size_t)Bc*Hc*Dc*Dc];
__device__ float g_corr[(size_t)Bc*Hc*DCORR];
__device__ float g_outs[Bc*Hc*Ec];

__device__ __forceinline__ uint32_t smem_u32(const void* p) {
    uint32_t a;
    asm("{ .reg .u64 t; cvta.to.shared.u64 t, %1; cvt.u32.u64 %0, t; }" : "=r"(a) : "l"(p));
    return a;
}

#define CP_COMMIT()  asm volatile("cp.async.commit_group;" ::: "memory")
#define CP_WAIT(n)   asm volatile("cp.async.wait_group %0;" :: "n"(n) : "memory")

#define LDSM4(r0, r1, r2, r3, a) \
    asm volatile("ldmatrix.sync.aligned.m8n8.x4.shared.b16 {%0,%1,%2,%3}, [%4];" \
        : "=r"(r0), "=r"(r1), "=r"(r2), "=r"(r3) : "r"(a))

#define MMA_BF16(d, a, b) asm volatile( \
    "mma.sync.aligned.m16n8k16.row.col.f32.bf16.bf16.f32 " \
    "{%0,%1,%2,%3},{%4,%5,%6,%7},{%8,%9},{%0,%1,%2,%3};\n" \
    : "+f"((d)[0]), "+f"((d)[1]), "+f"((d)[2]), "+f"((d)[3]) \
    : "r"((a)[0]), "r"((a)[1]), "r"((a)[2]), "r"((a)[3]), "r"((b)[0]), "r"((b)[1]))

__device__ __forceinline__ unsigned pack_hilo(float v) {
    __nv_bfloat16 h = __float2bfloat16(v);
    float fh = __bfloat162float(h);
    __nv_bfloat16 l = __float2bfloat16(v - fh);
    return (unsigned)__bfloat16_as_ushort(h) | ((unsigned)__bfloat16_as_ushort(l) << 16);
}

// ---------------- stage 0: softmax of mixing weights ----------------
__global__ void k_softmaxw(const float* __restrict__ wk, const float* __restrict__ wv) {
    int tid = threadIdx.x;
    if (tid >= 2*Hc) return;
    int h = tid % Hc;
    const float* src = (tid < Hc ? wk : wv) + h*Lc;
    float* dst = (tid < Hc ? g_kw : g_vw) + h*Lc;
    float m = -1e30f;
    for (int l = 0; l < Lc; l++) m = fmaxf(m, src[l]);
    float e[Lc]; float s = 0.f;
    for (int l = 0; l < Lc; l++) { e[l] = expf(src[l]-m); s += e[l]; }
    float inv = 1.f/s;
    for (int l = 0; l < Lc; l++) dst[l] = e[l]*inv;
}

// ---------------- stage 0b: pack W to bf16 hi/lo planes ----------------
__global__ void k_wconv(const float* __restrict__ Wk, const float* __restrict__ Wv) {
    size_t i = (size_t)blockIdx.x*256 + threadIdx.x;
    const float* W = blockIdx.y ? Wv : Wk;
    unsigned pk = pack_hilo(W[i]);
    size_t o = (size_t)blockIdx.y*(Hc*Dc*Fc) + i;
    g_whi[o] = __ushort_as_bfloat16((unsigned short)(pk & 0xffff));
    g_wlo[o] = __ushort_as_bfloat16((unsigned short)(pk >> 16));
}

// ---------------- stage 1: L-contraction -> bf16 hi/lo planes [t][f] ----------------
__global__ __launch_bounds__(256) void k_raw(const float* __restrict__ x) {
    __shared__ float skw[Hc*Lc];
    __shared__ float svw[Hc*Lc];
    __shared__ unsigned s_pk[2][Hc][16][17];   // [kv][h][f][t]
    int tx = threadIdx.x;      // t
    int ty = threadIdx.y;      // f
    int tid = ty*16 + tx;
    if (tid < Hc*Lc) { skw[tid] = g_kw[tid]; svw[tid] = g_vw[tid]; }
    __syncthreads();

    int t0 = blockIdx.x*16;
    int f0 = blockIdx.y*16;
    int b  = blockIdx.z;
    int t = t0 + tx;
    int f = f0 + ty;

    float xv[Lc];
    if (t < Tc) {
        const float* xp = x + ((size_t)(b*Fc + f)*Tc + t)*Lc;
#pragma unroll
        for (int l = 0; l < Lc; l++) xv[l] = xp[l];
    } else {
#pragma unroll
        for (int l = 0; l < Lc; l++) xv[l] = 0.f;
    }
#pragma unroll
    for (int h = 0; h < Hc; h++) {
        float kr = 0.f, vr = 0.f;
#pragma unroll
        for (int l = 0; l < Lc; l++) {
            kr += xv[l]*skw[h*Lc + l];
            vr += xv[l]*svw[h*Lc + l];
        }
        s_pk[0][h][ty][tx] = pack_hilo(kr);
        s_pk[1][h][ty][tx] = pack_hilo(vr);
    }
    __syncthreads();

    int w = tid >> 5, lane = tid & 31;
    int fl = lane & 15;
    int th = lane >> 4;
#pragma unroll
    for (int it = 0; it < 4; it++) {
        int job = w*4 + it;            // 0..31
        int kv = job >> 4;
        int plane = (job >> 3) & 1;
        int h = job & 7;
        __nv_bfloat16* arr = plane ? g_alo : g_ahi;
        size_t rowbase = ((size_t)(kv*Bc + b)*Hc + h)*Tc;
#pragma unroll
        for (int ti = 0; ti < 8; ti++) {
            int tl = ti*2 + th;
            int tt = t0 + tl;
            if (tt < Tc) {
                unsigned pk = s_pk[kv][h][fl][tl];
                unsigned short v = plane ? (unsigned short)(pk >> 16) : (unsigned short)(pk & 0xffff);
                arr[(rowbase + tt)*Fc + f0 + fl] = __ushort_as_bfloat16(v);
            }
        }
    }
}

// ---------------- stage 2: mma.sync GEMM, ldmatrix + cp.async 3-stage ----------------
// C[t,d] = sum_f A[t,f]*W[d,f] + bias[d]; tile M=128(t) x N=128(d) x K=32(f).
// 8 warps, warp tile 32(m) x 64(n). 3-term bf16 hi/lo split.
#define RS 80                       // smem row stride bytes (32 bf16 + 16B pad)
#define PLANE_B (128*RS)            // 10240
#define STAGE_B (4*PLANE_B)         // 40960: Ahi, Alo, Bhi, Blo
#define NSTAGE 3
#define GSMEM (NSTAGE*STAGE_B)      // 122880
#define NCH (Fc/32)                 // 24

__device__ __forceinline__ void prefetch_chunk(
    int c, int stage, uint32_t sb, int t0, int tid,
    const __nv_bfloat16* __restrict__ Ahi, const __nv_bfloat16* __restrict__ Alo,
    const __nv_bfloat16* __restrict__ Bhi, const __nv_bfloat16* __restrict__ Blo) {
    int kc = c*32;
    uint32_t stb = sb + stage*STAGE_B;
#pragma unroll
    for (int it = 0; it < 8; it++) {
        int idx = tid + it*256;        // 0..2047
        int plane = idx >> 9;
        int row = (idx >> 2) & 127;
        int seg = idx & 3;
        uint32_t dst = stb + plane*PLANE_B + row*RS + seg*16;
        const __nv_bfloat16* src;
        unsigned sz = 16;
        if (plane < 2) {
            int t = t0 + row;
            if (t >= Tc) { t = 0; sz = 0; }
            src = (plane ? Alo : Ahi) + (size_t)t*Fc + kc + seg*8;
        } else {
            src = (plane == 2 ? Bhi : Blo) + (size_t)row*Fc + kc + seg*8;
        }
        asm volatile("cp.async.cg.shared.global [%0], [%1], 16, %2;"
                     :: "r"(dst), "l"(src), "r"(sz));
    }
    CP_COMMIT();
}

__global__ __launch_bounds__(256, 1) void k_gemm(
    const float* __restrict__ bk, const float* __restrict__ bv) {
    extern __shared__ __align__(1024) char dynsmem[];
    uint32_t sb = smem_u32(dynsmem);

    int tid = threadIdx.x;
    int warp = tid >> 5, lane = tid & 31;
    int bh = blockIdx.y;
    int h = bh & 7;
    int kv = blockIdx.z;
    int t0 = blockIdx.x*128;

    const __nv_bfloat16* Ahi = g_ahi + (size_t)(kv*Bc*Hc + bh)*Tc*Fc;
    const __nv_bfloat16* Alo = g_alo + (size_t)(kv*Bc*Hc + bh)*Tc*Fc;
    const __nv_bfloat16* Bhi = g_whi + (size_t)(kv*Hc + h)*Dc*Fc;
    const __nv_bfloat16* Blo = g_wlo + (size_t)(kv*Hc + h)*Dc*Fc;
    const float* bias = (kv ? bv : bk) + h*Dc;
    float* C = (kv ? g_mhv : g_mhk) + (size_t)bh*Tc*Dc;

    int m0w = (warp >> 1)*32;       // 0,32,64,96
    int n0w = (warp & 1)*64;        // 0,64

    // per-lane ldmatrix address components
    int arow = (lane & 7) + ((lane >> 3) & 1)*8;
    int akb  = ((lane >> 4) & 1)*16;
    int brow = (lane & 7) + ((lane >> 4) & 1)*8;
    int bkb  = ((lane >> 3) & 1)*16;

    float acc[2][8][4];
#pragma unroll
    for (int i = 0; i < 2; i++)
#pragma unroll
        for (int j = 0; j < 8; j++)
#pragma unroll
            for (int r = 0; r < 4; r++) acc[i][j][r] = 0.f;

    prefetch_chunk(0, 0, sb, t0, tid, Ahi, Alo, Bhi, Blo);
    prefetch_chunk(1, 1, sb, t0, tid, Ahi, Alo, Bhi, Blo);

#pragma unroll 1
    for (int c = 0; c < NCH; c++) {
        if (c < NCH-1) CP_WAIT(1); else CP_WAIT(0);
        __syncthreads();
        if (c + 2 < NCH)
            prefetch_chunk(c+2, (c+2)%NSTAGE, sb, t0, tid, Ahi, Alo, Bhi, Blo);

        uint32_t st = sb + (c%NSTAGE)*STAGE_B;
#pragma unroll
        for (int ks = 0; ks < 2; ks++) {
            unsigned ah[2][4], al[2][4];
#pragma unroll
            for (int mi = 0; mi < 2; mi++) {
                uint32_t a0 = st + (uint32_t)((m0w + mi*16 + arow)*RS + ks*32 + akb);
                LDSM4(ah[mi][0], ah[mi][1], ah[mi][2], ah[mi][3], a0);
                LDSM4(al[mi][0], al[mi][1], al[mi][2], al[mi][3], a0 + PLANE_B);
            }
            unsigned bhf[8][2], blf[8][2];
#pragma unroll
            for (int ni = 0; ni < 4; ni++) {
                uint32_t b0 = st + 2*PLANE_B + (uint32_t)((n0w + ni*16 + brow)*RS + ks*32 + bkb);
                unsigned r0, r1, r2, r3;
                LDSM4(r0, r1, r2, r3, b0);
                bhf[2*ni][0] = r0; bhf[2*ni][1] = r1;
                bhf[2*ni+1][0] = r2; bhf[2*ni+1][1] = r3;
                LDSM4(r0, r1, r2, r3, b0 + PLANE_B);
                blf[2*ni][0] = r0; blf[2*ni][1] = r1;
                blf[2*ni+1][0] = r2; blf[2*ni+1][1] = r3;
            }
#pragma unroll
            for (int mi = 0; mi < 2; mi++)
#pragma unroll
                for (int nj = 0; nj < 8; nj++) {
                    MMA_BF16(acc[mi][nj], ah[mi], bhf[nj]);
                    MMA_BF16(acc[mi][nj], ah[mi], blf[nj]);
                    MMA_BF16(acc[mi][nj], al[mi], bhf[nj]);
                }
        }
    }

    // epilogue: c-frag layout: lane g=lane>>2 rows {g, g+8}, cols 2q..2q+1
    int g = lane >> 2, q = lane & 3;
#pragma unroll
    for (int nj = 0; nj < 8; nj++) {
        int d = n0w + nj*8 + q*2;
        float2 bb = *(const float2*)(bias + d);
#pragma unroll
        for (int mi = 0; mi < 2; mi++) {
            int t = t0 + m0w + mi*16 + g;
            if (t < Tc) {
                float2 o = make_float2(acc[mi][nj][0] + bb.x, acc[mi][nj][1] + bb.y);
                *(float2*)(C + (size_t)t*Dc + d) = o;
            }
            if (t + 8 < Tc) {
                float2 o = make_float2(acc[mi][nj][2] + bb.x, acc[mi][nj][3] + bb.y);
                *(float2*)(C + (size_t)(t+8)*Dc + d) = o;
            }
        }
    }
}

// ---------------- stage 0c: zero S accumulator ----------------
__global__ void k_zeroS() {
    int i = blockIdx.x*blockDim.x + threadIdx.x;
    ((float4*)g_S)[i] = make_float4(0.f,0.f,0.f,0.f);
}

// ---------------- stage 3a: stats + attention + o1 ----------------
__global__ __launch_bounds__(256) void k_attn(const float* __restrict__ q) {
    __shared__ float s_sc[Tc];
    __shared__ float s_red[256];
    __shared__ float s_q[Dc];
    int tid = threadIdx.x;
    int bh = blockIdx.x;
    int h = bh % Hc;
    const float* K = g_mhk + (size_t)bh*Tc*Dc;
    const float* V = g_mhv + (size_t)bh*Tc*Dc;
    if (tid < Dc) s_q[tid] = q[h*Dc + tid];

    {
        int d = tid & 127;
        const float* M = (tid < 128) ? K : V;
        float s1 = 0.f, s2 = 0.f;
        for (int t = 0; t < Tc; t++) {
            float v = M[t*Dc + d];
            s1 += v; s2 += v*v;
        }
        float mu = s1 * (1.f/Tc);
        float var = (s2 - (float)Tc*mu*mu) * (1.f/(Tc-1));
        var = fmaxf(var, 0.f);
        float sd = sqrtf(var) + 1e-9f;
        if (tid < 128) { g_muk[bh*Dc+d] = mu; g_sdk[bh*Dc+d] = sd; }
        else           { g_muv[bh*Dc+d] = mu; g_sdv[bh*Dc+d] = sd; }
    }
    __syncthreads();

    int w = tid >> 5, lane = tid & 31;
    for (int t = w; t < Tc; t += 8) {
        const float* kr = K + t*Dc;
        float s = 0.f;
#pragma unroll
        for (int j = 0; j < 4; j++) {
            int d = lane + j*32;
            s += kr[d]*s_q[d];
        }
        for (int off = 16; off; off >>= 1) s += __shfl_down_sync(0xffffffffu, s, off);
        if (lane == 0) s_sc[t] = s * 0.08838834764831845f;
    }
    __syncthreads();

    float lm = -1e30f;
    for (int t = tid; t < Tc; t += 256) lm = fmaxf(lm, s_sc[t]);
    s_red[tid] = lm; __syncthreads();
    for (int s = 128; s; s >>= 1) { if (tid < s) s_red[tid] = fmaxf(s_red[tid], s_red[tid+s]); __syncthreads(); }
    float m = s_red[0];
    __syncthreads();
    float ls = 0.f;
    for (int t = tid; t < Tc; t += 256) { float e = expf(s_sc[t]-m); s_sc[t] = e; ls += e; }
    s_red[tid] = ls; __syncthreads();
    for (int s = 128; s; s >>= 1) { if (tid < s) s_red[tid] += s_red[tid+s]; __syncthreads(); }
    float inv = 1.f / s_red[0];
    __syncthreads();

    {
        int d = tid & 127;
        int half = tid >> 7;
        float acc = 0.f;
        int tb = half*500;
        for (int t = tb; t < tb+500; t++) acc += s_sc[t]*V[t*Dc + d];
        s_red[tid] = acc*inv;
        __syncthreads();
        if (tid < 128) g_o1[bh*Dc + tid] = s_red[tid] + s_red[tid+128];
    }
}

// ---------------- stage 3b: S[k][l] = sum_t K[t][k]*V[t][l] ----------------
__global__ __launch_bounds__(256) void k_smat() {
    __shared__ float Ks[8][128];
    __shared__ float Vs[8][128];
    int tid = threadIdx.x;
    int bh = blockIdx.y;
    int seg = blockIdx.x;
    const float* K = g_mhk + (size_t)bh*Tc*Dc;
    const float* V = g_mhv + (size_t)bh*Tc*Dc;
    int tbeg = seg*250;
    int ty = tid >> 4, tx = tid & 15;
    int lrow = tid >> 5, lc = (tid & 31)*4;
    float acc[8][8];
#pragma unroll
    for (int r = 0; r < 8; r++)
#pragma unroll
        for (int c = 0; c < 8; c++) acc[r][c] = 0.f;

    for (int ch = 0; ch < 32; ch++) {
        int rt = ch*8 + lrow;
        float4 kval = make_float4(0.f,0.f,0.f,0.f), vval = kval;
        if (rt < 250) {
            int t = tbeg + rt;
            kval = *(const float4*)(K + (size_t)t*Dc + lc);
            vval = *(const float4*)(V + (size_t)t*Dc + lc);
        }
        *(float4*)&Ks[lrow][lc] = kval;
        *(float4*)&Vs[lrow][lc] = vval;
        __syncthreads();
#pragma unroll
        for (int tt = 0; tt < 8; tt++) {
            float4 k0 = *(float4*)&Ks[tt][ty*8];
            float4 k1 = *(float4*)&Ks[tt][ty*8+4];
            float4 v0 = *(float4*)&Vs[tt][tx*8];
            float4 v1 = *(float4*)&Vs[tt][tx*8+4];
            float rk[8] = {k0.x,k0.y,k0.z,k0.w,k1.x,k1.y,k1.z,k1.w};
            float rv[8] = {v0.x,v0.y,v0.z,v0.w,v1.x,v1.y,v1.z,v1.w};
#pragma unroll
            for (int r = 0; r < 8; r++)
#pragma unroll
                for (int c = 0; c < 8; c++) acc[r][c] += rk[r]*rv[c];
        }
        __syncthreads();
    }
    float* Sp = g_S + (size_t)bh*Dc*Dc;
#pragma unroll
    for (int r = 0; r < 8; r++)
#pragma unroll
        for (int c = 0; c < 8; c++)
            atomicAdd(&Sp[(ty*8+r)*Dc + tx*8 + c], acc[r][c]);
}

// ---------------- stage 3c: normalized correlation ----------------
__global__ void k_corr() {
    int c = blockIdx.x*256 + threadIdx.x;
    int bh = blockIdx.y;
    if (c >= DCORR) return;
    float disc = 65025.0f - 8.0f*(float)c;
    int k = (int)((255.0f - sqrtf(disc))*0.5f);
    if (k < 0) k = 0;
    if (k > 126) k = 126;
    while (k > 0 && k*(255-k)/2 > c) k--;
    while ((k+1)*(254-k)/2 <= c) k++;
    int l = k + 1 + (c - k*(255-k)/2);
    float muk = g_muk[bh*Dc + k], sdk = g_sdk[bh*Dc + k];
    float muv = g_muv[bh*Dc + l], sdv = g_sdv[bh*Dc + l];
    float S = g_S[(size_t)bh*Dc*Dc + k*Dc + l];
    g_corr[(size_t)bh*DCORR + c] = (S - (float)Tc*muk*muv) / ((float)Tc*sdk*sdv);
}

// ---------------- stage 4: outs = corr . Wproj + bproj ----------------
__global__ __launch_bounds__(256) void k_proj(
    const float* __restrict__ Wproj, const float* __restrict__ bproj) {
    __shared__ float sc[8][128];
    int tid = threadIdx.x;
    int h = blockIdx.y;
    int el = tid & 31;
    int b = tid >> 5;
    int e = blockIdx.x*32 + el;
    int lrow = tid >> 5;
    int lc = (tid & 31)*4;
    const float* wrow = Wproj + ((size_t)h*Ec + e)*DCORR;
    float acc = 0.f;
    for (int c0 = 0; c0 < DCORR; c0 += 128) {
        int lim = DCORR - c0; if (lim > 128) lim = 128;
        float4 cv = make_float4(0.f,0.f,0.f,0.f);
        if (lc < lim) cv = *(const float4*)(g_corr + ((size_t)lrow*Hc + h)*DCORR + c0 + lc);
        *(float4*)&sc[lrow][lc] = cv;
        __syncthreads();
#pragma unroll 8
        for (int j = 0; j < lim; j += 4) {
            float4 wv = *(const float4*)(wrow + c0 + j);
            float4 sv = *(const float4*)&sc[b][j];
            acc += wv.x*sv.x + wv.y*sv.y + wv.z*sv.z + wv.w*sv.w;
        }
        __syncthreads();
    }
    g_outs[b*(Hc*Ec) + h*Ec + e] = acc + bproj[h*Ec + e];
}

// ---------------- stage 5: final linears + mix ----------------
__global__ __launch_bounds__(256) void k_final(
    const float* __restrict__ WT, const float* __restrict__ bT,
    const float* __restrict__ Wp, const float* __restrict__ bp,
    float* __restrict__ out) {
    __shared__ float so1[Hc*Dc];
    __shared__ float sout[Hc*Ec];
    int b = blockIdx.x;
    int tid = threadIdx.x;
    for (int j = tid; j < Hc*Dc; j += 256) so1[j]  = g_o1[b*Hc*Dc + j];
    for (int j = tid; j < Hc*Ec; j += 256) sout[j] = g_outs[b*Hc*Ec + j];
    __syncthreads();
    int e = tid;
    float aT = bT[e];
    float aF = bp[e];
    const float* wt = WT + (size_t)e*(Hc*Dc);
#pragma unroll 4
    for (int j = 0; j < Hc*Dc; j += 4) {
        float4 wv = *(const float4*)(wt + j);
        float4 sv = *(const float4*)&so1[j];
        aT += wv.x*sv.x + wv.y*sv.y + wv.z*sv.z + wv.w*sv.w;
    }
    const float* wp = Wp + (size_t)e*(Hc*Ec);
#pragma unroll 4
    for (int j = 0; j < Hc*Ec; j += 4) {
        float4 wv = *(const float4*)(wp + j);
        float4 sv = *(const float4*)&sout[j];
        aF += wv.x*sv.x + wv.y*sv.y + wv.z*sv.z + wv.w*sv.w;
    }
    out[b*Ec + e] = 0.5f*(aT + aF);
}

// ---------------- launch ----------------
extern "C" void kernel_launch(void* const* d_in, const int* in_sizes, int n_in,
                              void* d_out, int out_size) {
    const float* x     = (const float*)d_in[0];
    const float* wk    = (const float*)d_in[1];
    const float* wv    = (const float*)d_in[2];
    const float* q     = (const float*)d_in[3];
    const float* Wk    = (const float*)d_in[4];
    const float* bk    = (const float*)d_in[5];
    const float* Wv    = (const float*)d_in[6];
    const float* bv    = (const float*)d_in[7];
    const float* Wproj = (const float*)d_in[8];
    const float* bproj = (const float*)d_in[9];
    const float* WT    = (const float*)d_in[10];
    const float* bT    = (const float*)d_in[11];
    const float* Wp    = (const float*)d_in[12];
    const float* bp    = (const float*)d_in[13];
    float* out = (float*)d_out;

    cudaFuncSetAttribute(k_gemm, cudaFuncAttributeMaxDynamicSharedMemorySize, GSMEM);

    k_softmaxw<<<1, 32>>>(wk, wv);
    k_wconv<<<dim3((Hc*Dc*Fc)/256, 2), 256>>>(Wk, Wv);
    k_raw<<<dim3((Tc+15)/16, Fc/16, Bc), dim3(16, 16)>>>(x);
    k_gemm<<<dim3(8, Bc*Hc, 2), 256, GSMEM>>>(bk, bv);   // 4th launch -> ncu target
    k_zeroS<<<(Bc*Hc*Dc*Dc/4)/256, 256>>>();
    k_attn<<<Bc*Hc, 256>>>(q);
    k_smat<<<dim3(4, Bc*Hc), 256>>>();
    k_corr<<<dim3((DCORR+255)/256, Bc*Hc), 256>>>();
    k_proj<<<dim3(Ec/32, Hc), 256>>>(Wproj, bproj);
    k_final<<<Bc, 256>>>(WT, bT, Wp, bp, out);
}

// round 5
// speedup vs baseline: 1.5594x; 1.2893x over previous
#include <cuda_runtime.h>
#include <cuda_bf16.h>
#include <math.h>
#include <stdint.h>

// Problem constants
#define Bc 8
#define Hc 8
#define Fc 768
#define Dc 128
#define Ec 256
#define Lc 13
#define Tc 1000
#define DCORR 8128

// ---------------- device scratch ----------------
__device__ float g_kw[Hc*Lc];
__device__ float g_vw[Hc*Lc];
__device__ __nv_bfloat16 g_ahi[(size_t)2*Bc*Hc*Tc*Fc];
__device__ __nv_bfloat16 g_alo[(size_t)2*Bc*Hc*Tc*Fc];
__device__ __nv_bfloat16 g_whi[(size_t)2*Hc*Dc*Fc];
__device__ __nv_bfloat16 g_wlo[(size_t)2*Hc*Dc*Fc];
__device__ float g_mhk[(size_t)Bc*Hc*Tc*Dc];
__device__ float g_mhv[(size_t)Bc*Hc*Tc*Dc];
__device__ float g_s1[2*Bc*Hc*Dc];       // fused stats: sum v
__device__ float g_s2[2*Bc*Hc*Dc];       // sum v^2
__device__ float g_muk[Bc*Hc*Dc];
__device__ float g_sdk[Bc*Hc*Dc];
__device__ float g_muv[Bc*Hc*Dc];
__device__ float g_sdv[Bc*Hc*Dc];
__device__ float g_o1[Bc*Hc*Dc];
__device__ float g_S[(size_t)Bc*Hc*Dc*Dc];
__device__ float g_corr[(size_t)Bc*Hc*DCORR];
__device__ float g_outs[Bc*Hc*Ec];

__device__ __forceinline__ uint32_t smem_u32(const void* p) {
    uint32_t a;
    asm("{ .reg .u64 t; cvta.to.shared.u64 t, %1; cvt.u32.u64 %0, t; }" : "=r"(a) : "l"(p));
    return a;
}

#define CP_COMMIT()  asm volatile("cp.async.commit_group;" ::: "memory")
#define CP_WAIT(n)   asm volatile("cp.async.wait_group %0;" :: "n"(n) : "memory")

#define LDSM4(r0, r1, r2, r3, a) \
    asm volatile("ldmatrix.sync.aligned.m8n8.x4.shared.b16 {%0,%1,%2,%3}, [%4];" \
        : "=r"(r0), "=r"(r1), "=r"(r2), "=r"(r3) : "r"(a))

#define MMA_BF16(d, a, b) asm volatile( \
    "mma.sync.aligned.m16n8k16.row.col.f32.bf16.bf16.f32 " \
    "{%0,%1,%2,%3},{%4,%5,%6,%7},{%8,%9},{%0,%1,%2,%3};\n" \
    : "+f"((d)[0]), "+f"((d)[1]), "+f"((d)[2]), "+f"((d)[3]) \
    : "r"((a)[0]), "r"((a)[1]), "r"((a)[2]), "r"((a)[3]), "r"((b)[0]), "r"((b)[1]))

// ---------------- stage 0: softmax of mixing weights ----------------
__global__ void k_softmaxw(const float* __restrict__ wk, const float* __restrict__ wv) {
    int tid = threadIdx.x;
    if (tid >= 2*Hc) return;
    int h = tid % Hc;
    const float* src = (tid < Hc ? wk : wv) + h*Lc;
    float* dst = (tid < Hc ? g_kw : g_vw) + h*Lc;
    float m = -1e30f;
    for (int l = 0; l < Lc; l++) m = fmaxf(m, src[l]);
    float e[Lc]; float s = 0.f;
    for (int l = 0; l < Lc; l++) { e[l] = expf(src[l]-m); s += e[l]; }
    float inv = 1.f/s;
    for (int l = 0; l < Lc; l++) dst[l] = e[l]*inv;
}

// ---------------- stage 0c: zero S + stats accumulators ----------------
// grid 1056 x 256: first 262144 f4 -> g_S, next 4096 -> g_s1, next 4096 -> g_s2
__global__ void k_zero() {
    int i = blockIdx.x*blockDim.x + threadIdx.x;
    float4 z = make_float4(0.f,0.f,0.f,0.f);
    if (i < 262144) { ((float4*)g_S)[i] = z; return; }
    int j = i - 262144;
    if (j < 4096) { ((float4*)g_s1)[j] = z; return; }
    ((float4*)g_s2)[j - 4096] = z;
}

// ---------------- stage 0b: pack W to bf16 hi/lo planes ----------------
__global__ void k_wconv(const float* __restrict__ Wk, const float* __restrict__ Wv) {
    size_t i = (size_t)blockIdx.x*256 + threadIdx.x;
    const float* W = blockIdx.y ? Wv : Wk;
    float v = W[i];
    __nv_bfloat16 h16 = __float2bfloat16(v);
    __nv_bfloat16 l16 = __float2bfloat16(v - __bfloat162float(h16));
    size_t o = (size_t)blockIdx.y*(Hc*Dc*Fc) + i;
    g_whi[o] = h16;
    g_wlo[o] = l16;
}

// ---------------- stage 1: L-contraction -> bf16 hi/lo planes [t][f] ----------------
// block (16 t, 16 f). smem transpose; write-out as packed 32-bit (2 bf16).
__global__ __launch_bounds__(256) void k_raw(const float* __restrict__ x) {
    __shared__ float skw[Hc*Lc];
    __shared__ float svw[Hc*Lc];
    __shared__ __align__(16) unsigned short s_hi[2][Hc][16][18];   // [kv][h][t][f]
    __shared__ __align__(16) unsigned short s_lo[2][Hc][16][18];
    int tx = threadIdx.x;      // t
    int ty = threadIdx.y;      // f
    int tid = ty*16 + tx;
    if (tid < Hc*Lc) { skw[tid] = g_kw[tid]; svw[tid] = g_vw[tid]; }
    __syncthreads();

    int t0 = blockIdx.x*16;
    int f0 = blockIdx.y*16;
    int b  = blockIdx.z;
    int t = t0 + tx;
    int f = f0 + ty;

    float xv[Lc];
    if (t < Tc) {
        const float* xp = x + ((size_t)(b*Fc + f)*Tc + t)*Lc;
#pragma unroll
        for (int l = 0; l < Lc; l++) xv[l] = xp[l];
    } else {
#pragma unroll
        for (int l = 0; l < Lc; l++) xv[l] = 0.f;
    }
#pragma unroll
    for (int h = 0; h < Hc; h++) {
        float kr = 0.f, vr = 0.f;
#pragma unroll
        for (int l = 0; l < Lc; l++) {
            kr += xv[l]*skw[h*Lc + l];
            vr += xv[l]*svw[h*Lc + l];
        }
        __nv_bfloat16 kh = __float2bfloat16(kr);
        __nv_bfloat16 kl = __float2bfloat16(kr - __bfloat162float(kh));
        __nv_bfloat16 vh = __float2bfloat16(vr);
        __nv_bfloat16 vl = __float2bfloat16(vr - __bfloat162float(vh));
        s_hi[0][h][tx][ty] = __bfloat16_as_ushort(kh);
        s_lo[0][h][tx][ty] = __bfloat16_as_ushort(kl);
        s_hi[1][h][tx][ty] = __bfloat16_as_ushort(vh);
        s_lo[1][h][tx][ty] = __bfloat16_as_ushort(vl);
    }
    __syncthreads();

    // write phase: 32 jobs (kv, plane, h); per job 16t x 16f as 4B packed stores
    int w = tid >> 5, lane = tid & 31;
    int f2 = lane & 7;            // word (2 bf16) within row
    int tr = lane >> 3;           // 0..3
#pragma unroll
    for (int it = 0; it < 4; it++) {
        int job = w*4 + it;       // 0..31
        int kv = job >> 4;
        int plane = (job >> 3) & 1;
        int h = job & 7;
        __nv_bfloat16* arr = plane ? g_alo : g_ahi;
        size_t rowbase = ((size_t)(kv*Bc + b)*Hc + h)*Tc;
#pragma unroll
        for (int ti = 0; ti < 4; ti++) {
            int tl = ti*4 + tr;
            int tt = t0 + tl;
            if (tt < Tc) {
                const unsigned short* srow = plane ? &s_lo[kv][h][tl][0] : &s_hi[kv][h][tl][0];
                unsigned val = *(const unsigned*)(srow + f2*2);
                *(unsigned*)(arr + (rowbase + tt)*Fc + f0 + f2*2) = val;
            }
        }
    }
}

// ---------------- stage 2: mma.sync GEMM + fused stats ----------------
#define RS 80
#define PLANE_B (128*RS)
#define STAGE_B (4*PLANE_B)
#define NSTAGE 3
#define GSMEM (NSTAGE*STAGE_B)
#define NCH (Fc/32)

__device__ __forceinline__ void prefetch_chunk(
    int c, int stage, uint32_t sb, int t0, int tid,
    const __nv_bfloat16* __restrict__ Ahi, const __nv_bfloat16* __restrict__ Alo,
    const __nv_bfloat16* __restrict__ Bhi, const __nv_bfloat16* __restrict__ Blo) {
    int kc = c*32;
    uint32_t stb = sb + stage*STAGE_B;
#pragma unroll
    for (int it = 0; it < 8; it++) {
        int idx = tid + it*256;
        int plane = idx >> 9;
        int row = (idx >> 2) & 127;
        int seg = idx & 3;
        uint32_t dst = stb + plane*PLANE_B + row*RS + seg*16;
        const __nv_bfloat16* src;
        unsigned sz = 16;
        if (plane < 2) {
            int t = t0 + row;
            if (t >= Tc) { t = 0; sz = 0; }
            src = (plane ? Alo : Ahi) + (size_t)t*Fc + kc + seg*8;
        } else {
            src = (plane == 2 ? Bhi : Blo) + (size_t)row*Fc + kc + seg*8;
        }
        asm volatile("cp.async.cg.shared.global [%0], [%1], 16, %2;"
                     :: "r"(dst), "l"(src), "r"(sz));
    }
    CP_COMMIT();
}

__global__ __launch_bounds__(256, 1) void k_gemm(
    const float* __restrict__ bk, const float* __restrict__ bv) {
    extern __shared__ __align__(1024) char dynsmem[];
    uint32_t sb = smem_u32(dynsmem);

    int tid = threadIdx.x;
    int warp = tid >> 5, lane = tid & 31;
    int bh = blockIdx.y;
    int h = bh & 7;
    int kv = blockIdx.z;
    int t0 = blockIdx.x*128;

    const __nv_bfloat16* Ahi = g_ahi + (size_t)(kv*Bc*Hc + bh)*Tc*Fc;
    const __nv_bfloat16* Alo = g_alo + (size_t)(kv*Bc*Hc + bh)*Tc*Fc;
    const __nv_bfloat16* Bhi = g_whi + (size_t)(kv*Hc + h)*Dc*Fc;
    const __nv_bfloat16* Blo = g_wlo + (size_t)(kv*Hc + h)*Dc*Fc;
    const float* bias = (kv ? bv : bk) + h*Dc;
    float* C = (kv ? g_mhv : g_mhk) + (size_t)bh*Tc*Dc;

    int m0w = (warp >> 1)*32;
    int n0w = (warp & 1)*64;

    int arow = (lane & 7) + ((lane >> 3) & 1)*8;
    int akb  = ((lane >> 4) & 1)*16;
    int brow = (lane & 7) + ((lane >> 4) & 1)*8;
    int bkb  = ((lane >> 3) & 1)*16;

    float acc[2][8][4];
#pragma unroll
    for (int i = 0; i < 2; i++)
#pragma unroll
        for (int j = 0; j < 8; j++)
#pragma unroll
            for (int r = 0; r < 4; r++) acc[i][j][r] = 0.f;

    prefetch_chunk(0, 0, sb, t0, tid, Ahi, Alo, Bhi, Blo);
    prefetch_chunk(1, 1, sb, t0, tid, Ahi, Alo, Bhi, Blo);

#pragma unroll 1
    for (int c = 0; c < NCH; c++) {
        if (c < NCH-1) CP_WAIT(1); else CP_WAIT(0);
        __syncthreads();
        if (c + 2 < NCH)
            prefetch_chunk(c+2, (c+2)%NSTAGE, sb, t0, tid, Ahi, Alo, Bhi, Blo);

        uint32_t st = sb + (c%NSTAGE)*STAGE_B;
#pragma unroll
        for (int ks = 0; ks < 2; ks++) {
            unsigned ah[2][4], al[2][4];
#pragma unroll
            for (int mi = 0; mi < 2; mi++) {
                uint32_t a0 = st + (uint32_t)((m0w + mi*16 + arow)*RS + ks*32 + akb);
                LDSM4(ah[mi][0], ah[mi][1], ah[mi][2], ah[mi][3], a0);
                LDSM4(al[mi][0], al[mi][1], al[mi][2], al[mi][3], a0 + PLANE_B);
            }
            unsigned bhf[8][2], blf[8][2];
#pragma unroll
            for (int ni = 0; ni < 4; ni++) {
                uint32_t b0 = st + 2*PLANE_B + (uint32_t)((n0w + ni*16 + brow)*RS + ks*32 + bkb);
                unsigned r0, r1, r2, r3;
                LDSM4(r0, r1, r2, r3, b0);
                bhf[2*ni][0] = r0; bhf[2*ni][1] = r1;
                bhf[2*ni+1][0] = r2; bhf[2*ni+1][1] = r3;
                LDSM4(r0, r1, r2, r3, b0 + PLANE_B);
                blf[2*ni][0] = r0; blf[2*ni][1] = r1;
                blf[2*ni+1][0] = r2; blf[2*ni+1][1] = r3;
            }
#pragma unroll
            for (int mi = 0; mi < 2; mi++)
#pragma unroll
                for (int nj = 0; nj < 8; nj++) {
                    MMA_BF16(acc[mi][nj], ah[mi], bhf[nj]);
                    MMA_BF16(acc[mi][nj], ah[mi], blf[nj]);
                    MMA_BF16(acc[mi][nj], al[mi], bhf[nj]);
                }
        }
    }

    // smem reuse for stats (all ldmatrix reads complete after barrier)
    __syncthreads();
    float* s1s = (float*)dynsmem;
    float* s2s = s1s + 128;
    if (tid < 128) { s1s[tid] = 0.f; s2s[tid] = 0.f; }
    __syncthreads();

    int g = lane >> 2, q = lane & 3;
#pragma unroll
    for (int nj = 0; nj < 8; nj++) {
        int d = n0w + nj*8 + q*2;
        float2 bb = *(const float2*)(bias + d);
        float a1 = 0.f, a2 = 0.f, c1 = 0.f, c2 = 0.f;
#pragma unroll
        for (int mi = 0; mi < 2; mi++) {
            int t = t0 + m0w + mi*16 + g;
            if (t < Tc) {
                float v0 = acc[mi][nj][0] + bb.x;
                float v1 = acc[mi][nj][1] + bb.y;
                *(float2*)(C + (size_t)t*Dc + d) = make_float2(v0, v1);
                a1 += v0; a2 += v0*v0; c1 += v1; c2 += v1*v1;
            }
            if (t + 8 < Tc) {
                float v0 = acc[mi][nj][2] + bb.x;
                float v1 = acc[mi][nj][3] + bb.y;
                *(float2*)(C + (size_t)(t+8)*Dc + d) = make_float2(v0, v1);
                a1 += v0; a2 += v0*v0; c1 += v1; c2 += v1*v1;
            }
        }
        atomicAdd(&s1s[d], a1);  atomicAdd(&s2s[d], a2);
        atomicAdd(&s1s[d+1], c1); atomicAdd(&s2s[d+1], c2);
    }
    __syncthreads();
    if (tid < 128) {
        size_t o = ((size_t)kv*Bc*Hc + bh)*Dc + tid;
        atomicAdd(&g_s1[o], s1s[tid]);
        atomicAdd(&g_s2[o], s2s[tid]);
    }
}

// ---------------- stats finalize + outs init ----------------
// grid 65: blocks 0..63 -> per-bh stats; block 64 -> g_outs = bproj
__global__ void k_statfin(const float* __restrict__ bproj) {
    int bid = blockIdx.x;
    int tid = threadIdx.x;
    if (bid < 64) {
        int kv = tid >> 7;
        int d = tid & 127;
        size_t o = ((size_t)kv*64 + bid)*Dc + d;
        float s1 = g_s1[o], s2 = g_s2[o];
        float mu = s1 * (1.f/Tc);
        float var = (s2 - (float)Tc*mu*mu) * (1.f/(Tc-1));
        var = fmaxf(var, 0.f);
        float sd = sqrtf(var) + 1e-9f;
        if (kv == 0) { g_muk[bid*Dc + d] = mu; g_sdk[bid*Dc + d] = sd; }
        else         { g_muv[bid*Dc + d] = mu; g_sdv[bid*Dc + d] = sd; }
    } else {
        for (int i = tid; i < Bc*Hc*Ec; i += 256)
            g_outs[i] = bproj[i & (Hc*Ec - 1)];
    }
}

// ---------------- stage 3a: attention + o1 (stats fused into gemm) ----------------
__global__ __launch_bounds__(256) void k_attn(const float* __restrict__ q) {
    __shared__ float s_sc[Tc];
    __shared__ float s_red[256];
    __shared__ float s_q[Dc];
    int tid = threadIdx.x;
    int bh = blockIdx.x;
    int h = bh % Hc;
    const float* K = g_mhk + (size_t)bh*Tc*Dc;
    const float* V = g_mhv + (size_t)bh*Tc*Dc;
    if (tid < Dc) s_q[tid] = q[h*Dc + tid];
    __syncthreads();

    int w = tid >> 5, lane = tid & 31;
    for (int t = w; t < Tc; t += 8) {
        const float* kr = K + t*Dc;
        float s = 0.f;
#pragma unroll
        for (int j = 0; j < 4; j++) {
            int d = lane + j*32;
            s += kr[d]*s_q[d];
        }
        for (int off = 16; off; off >>= 1) s += __shfl_down_sync(0xffffffffu, s, off);
        if (lane == 0) s_sc[t] = s * 0.08838834764831845f;
    }
    __syncthreads();

    float lm = -1e30f;
    for (int t = tid; t < Tc; t += 256) lm = fmaxf(lm, s_sc[t]);
    s_red[tid] = lm; __syncthreads();
    for (int s = 128; s; s >>= 1) { if (tid < s) s_red[tid] = fmaxf(s_red[tid], s_red[tid+s]); __syncthreads(); }
    float m = s_red[0];
    __syncthreads();
    float ls = 0.f;
    for (int t = tid; t < Tc; t += 256) { float e = expf(s_sc[t]-m); s_sc[t] = e; ls += e; }
    s_red[tid] = ls; __syncthreads();
    for (int s = 128; s; s >>= 1) { if (tid < s) s_red[tid] += s_red[tid+s]; __syncthreads(); }
    float inv = 1.f / s_red[0];
    __syncthreads();

    {
        int d = tid & 127;
        int half = tid >> 7;
        float acc = 0.f;
        int tb = half*500;
        for (int t = tb; t < tb+500; t++) acc += s_sc[t]*V[t*Dc + d];
        s_red[tid] = acc*inv;
        __syncthreads();
        if (tid < 128) g_o1[bh*Dc + tid] = s_red[tid] + s_red[tid+128];
    }
}

// ---------------- stage 3b: S[k][l] = sum_t K[t][k]*V[t][l] ----------------
__global__ __launch_bounds__(256) void k_smat() {
    __shared__ float Ks[8][128];
    __shared__ float Vs[8][128];
    int tid = threadIdx.x;
    int bh = blockIdx.y;
    int seg = blockIdx.x;
    const float* K = g_mhk + (size_t)bh*Tc*Dc;
    const float* V = g_mhv + (size_t)bh*Tc*Dc;
    int tbeg = seg*250;
    int ty = tid >> 4, tx = tid & 15;
    int lrow = tid >> 5, lc = (tid & 31)*4;
    float acc[8][8];
#pragma unroll
    for (int r = 0; r < 8; r++)
#pragma unroll
        for (int c = 0; c < 8; c++) acc[r][c] = 0.f;

    for (int ch = 0; ch < 32; ch++) {
        int rt = ch*8 + lrow;
        float4 kval = make_float4(0.f,0.f,0.f,0.f), vval = kval;
        if (rt < 250) {
            int t = tbeg + rt;
            kval = *(const float4*)(K + (size_t)t*Dc + lc);
            vval = *(const float4*)(V + (size_t)t*Dc + lc);
        }
        *(float4*)&Ks[lrow][lc] = kval;
        *(float4*)&Vs[lrow][lc] = vval;
        __syncthreads();
#pragma unroll
        for (int tt = 0; tt < 8; tt++) {
            float4 k0 = *(float4*)&Ks[tt][ty*8];
            float4 k1 = *(float4*)&Ks[tt][ty*8+4];
            float4 v0 = *(float4*)&Vs[tt][tx*8];
            float4 v1 = *(float4*)&Vs[tt][tx*8+4];
            float rk[8] = {k0.x,k0.y,k0.z,k0.w,k1.x,k1.y,k1.z,k1.w};
            float rv[8] = {v0.x,v0.y,v0.z,v0.w,v1.x,v1.y,v1.z,v1.w};
#pragma unroll
            for (int r = 0; r < 8; r++)
#pragma unroll
                for (int c = 0; c < 8; c++) acc[r][c] += rk[r]*rv[c];
        }
        __syncthreads();
    }
    float* Sp = g_S + (size_t)bh*Dc*Dc;
#pragma unroll
    for (int r = 0; r < 8; r++)
#pragma unroll
        for (int c = 0; c < 8; c++)
            atomicAdd(&Sp[(ty*8+r)*Dc + tx*8 + c], acc[r][c]);
}

// ---------------- stage 3c: normalized correlation ----------------
__global__ void k_corr() {
    int c = blockIdx.x*256 + threadIdx.x;
    int bh = blockIdx.y;
    if (c >= DCORR) return;
    float disc = 65025.0f - 8.0f*(float)c;
    int k = (int)((255.0f - sqrtf(disc))*0.5f);
    if (k < 0) k = 0;
    if (k > 126) k = 126;
    while (k > 0 && k*(255-k)/2 > c) k--;
    while ((k+1)*(254-k)/2 <= c) k++;
    int l = k + 1 + (c - k*(255-k)/2);
    float muk = g_muk[bh*Dc + k], sdk = g_sdk[bh*Dc + k];
    float muv = g_muv[bh*Dc + l], sdv = g_sdv[bh*Dc + l];
    float S = g_S[(size_t)bh*Dc*Dc + k*Dc + l];
    g_corr[(size_t)bh*DCORR + c] = (S - (float)Tc*muk*muv) / ((float)Tc*sdk*sdv);
}

// ---------------- stage 4: outs += corr . Wproj (c-split, atomic) ----------------
// grid (E/32, H, 4), block 256 = (8 b x 32 e)
__global__ __launch_bounds__(256) void k_proj(const float* __restrict__ Wproj) {
    __shared__ float sc[8][128];
    int tid = threadIdx.x;
    int h = blockIdx.y;
    int cs = blockIdx.z;
    int el = tid & 31;
    int b = tid >> 5;
    int e = blockIdx.x*32 + el;
    int lrow = tid >> 5;
    int lc = (tid & 31)*4;
    int start = cs*2032, end = start + 2032;
    const float* wrow = Wproj + ((size_t)h*Ec + e)*DCORR;
    float acc = 0.f;
    for (int c0 = start; c0 < end; c0 += 128) {
        int lim = end - c0; if (lim > 128) lim = 128;
        float4 cv = make_float4(0.f,0.f,0.f,0.f);
        if (lc < lim) cv = *(const float4*)(g_corr + ((size_t)lrow*Hc + h)*DCORR + c0 + lc);
        *(float4*)&sc[lrow][lc] = cv;
        __syncthreads();
#pragma unroll 8
        for (int j = 0; j < lim; j += 4) {
            float4 wv = *(const float4*)(wrow + c0 + j);
            float4 sv = *(const float4*)&sc[b][j];
            acc += wv.x*sv.x + wv.y*sv.y + wv.z*sv.z + wv.w*sv.w;
        }
        __syncthreads();
    }
    atomicAdd(&g_outs[b*(Hc*Ec) + h*Ec + e], acc);
}

// ---------------- stage 5: final linears + mix ----------------
// grid (B, E/32), block 256 = (32 e x 8 j-slices)
__global__ __launch_bounds__(256) void k_final(
    const float* __restrict__ WT, const float* __restrict__ bT,
    const float* __restrict__ Wp, const float* __restrict__ bp,
    float* __restrict__ out) {
    __shared__ float so1[Hc*Dc];
    __shared__ float sout[Hc*Ec];
    __shared__ float sred[256];
    int b = blockIdx.x, ec = blockIdx.y;
    int tid = threadIdx.x;
    for (int j = tid; j < Hc*Dc; j += 256) so1[j]  = g_o1[b*Hc*Dc + j];
    for (int j = tid; j < Hc*Ec; j += 256) sout[j] = g_outs[b*Hc*Ec + j];
    __syncthreads();
    int e_l = tid >> 3, js = tid & 7;
    int e = ec*32 + e_l;
    float a = 0.f;
    const float* wt = WT + (size_t)e*(Hc*Dc) + js*128;
    const float* s1p = so1 + js*128;
#pragma unroll 4
    for (int j = 0; j < 128; j += 4) {
        float4 wv = *(const float4*)(wt + j);
        float4 sv = *(const float4*)(s1p + j);
        a += wv.x*sv.x + wv.y*sv.y + wv.z*sv.z + wv.w*sv.w;
    }
    const float* wp = Wp + (size_t)e*(Hc*Ec) + js*256;
    const float* s2p = sout + js*256;
#pragma unroll 4
    for (int j = 0; j < 256; j += 4) {
        float4 wv = *(const float4*)(wp + j);
        float4 sv = *(const float4*)(s2p + j);
        a += wv.x*sv.x + wv.y*sv.y + wv.z*sv.z + wv.w*sv.w;
    }
    if (js == 0) a += bT[e] + bp[e];
    sred[tid] = a;
    __syncthreads();
    if (tid < 32) {
        float s = 0.f;
#pragma unroll
        for (int k = 0; k < 8; k++) s += sred[tid*8 + k];
        out[b*Ec + ec*32 + tid] = 0.5f*s;
    }
}

// ---------------- launch ----------------
extern "C" void kernel_launch(void* const* d_in, const int* in_sizes, int n_in,
                              void* d_out, int out_size) {
    const float* x     = (const float*)d_in[0];
    const float* wk    = (const float*)d_in[1];
    const float* wv    = (const float*)d_in[2];
    const float* q     = (const float*)d_in[3];
    const float* Wk    = (const float*)d_in[4];
    const float* bk    = (const float*)d_in[5];
    const float* Wv    = (const float*)d_in[6];
    const float* bv    = (const float*)d_in[7];
    const float* Wproj = (const float*)d_in[8];
    const float* bproj = (const float*)d_in[9];
    const float* WT    = (const float*)d_in[10];
    const float* bT    = (const float*)d_in[11];
    const float* Wp    = (const float*)d_in[12];
    const float* bp    = (const float*)d_in[13];
    float* out = (float*)d_out;

    cudaFuncSetAttribute(k_gemm, cudaFuncAttributeMaxDynamicSharedMemorySize, GSMEM);

    k_softmaxw<<<1, 32>>>(wk, wv);
    k_zero<<<1056, 256>>>();
    k_wconv<<<dim3((Hc*Dc*Fc)/256, 2), 256>>>(Wk, Wv);
    k_raw<<<dim3((Tc+15)/16, Fc/16, Bc), dim3(16, 16)>>>(x);   // 4th launch -> ncu
    k_gemm<<<dim3(8, Bc*Hc, 2), 256, GSMEM>>>(bk, bv);
    k_statfin<<<65, 256>>>(bproj);
    k_attn<<<Bc*Hc, 256>>>(q);
    k_smat<<<dim3(4, Bc*Hc), 256>>>();
    k_corr<<<dim3((DCORR+255)/256, Bc*Hc), 256>>>();
    k_proj<<<dim3(Ec/32, Hc, 4), 256>>>(Wproj);
    k_final<<<dim3(Bc, Ec/32), 256>>>(WT, bT, Wp, bp, out);
}

// round 6
// speedup vs baseline: 1.9472x; 1.2487x over previous
#include <cuda_runtime.h>
#include <cuda_bf16.h>
#include <math.h>
#include <stdint.h>

// Problem constants
#define Bc 8
#define Hc 8
#define Fc 768
#define Dc 128
#define Ec 256
#define Lc 13
#define Tc 1000
#define DCORR 8128
#define TP 1024                 // padded T
#define DT (128*TP)             // plane size per (kv,bh)

// ---------------- device scratch ----------------
__device__ float g_kw[Hc*Lc];
__device__ float g_vw[Hc*Lc];
__device__ __nv_bfloat16 g_ahi[(size_t)2*Bc*Hc*Tc*Fc];   // raw activations [kv][bh][t][f]
__device__ __nv_bfloat16 g_alo[(size_t)2*Bc*Hc*Tc*Fc];
__device__ __nv_bfloat16 g_whi[(size_t)2*Hc*Dc*Fc];      // weights [kv][h][d][f]
__device__ __nv_bfloat16 g_wlo[(size_t)2*Hc*Dc*Fc];
__device__ __nv_bfloat16 g_chi[(size_t)2*Bc*Hc*DT];      // GEMM out planes [kv][bh][d][t]
__device__ __nv_bfloat16 g_clo[(size_t)2*Bc*Hc*DT];
__device__ float g_s1[2*Bc*Hc*Dc];
__device__ float g_s2[2*Bc*Hc*Dc];
__device__ float g_muk[Bc*Hc*Dc];
__device__ float g_sdk[Bc*Hc*Dc];
__device__ float g_muv[Bc*Hc*Dc];
__device__ float g_sdv[Bc*Hc*Dc];
__device__ float g_o1[Bc*Hc*Dc];
__device__ float g_S[(size_t)Bc*Hc*Dc*Dc];
__device__ float g_corr[(size_t)Bc*Hc*DCORR];
__device__ float g_outs[Bc*Hc*Ec];

__device__ __forceinline__ uint32_t smem_u32(const void* p) {
    uint32_t a;
    asm("{ .reg .u64 t; cvta.to.shared.u64 t, %1; cvt.u32.u64 %0, t; }" : "=r"(a) : "l"(p));
    return a;
}
#define CP_COMMIT()  asm volatile("cp.async.commit_group;" ::: "memory")
#define CP_WAIT(n)   asm volatile("cp.async.wait_group %0;" :: "n"(n) : "memory")
#define LDSM4(r0, r1, r2, r3, a) \
    asm volatile("ldmatrix.sync.aligned.m8n8.x4.shared.b16 {%0,%1,%2,%3}, [%4];" \
        : "=r"(r0), "=r"(r1), "=r"(r2), "=r"(r3) : "r"(a))
#define MMA_BF16(d, a, b) asm volatile( \
    "mma.sync.aligned.m16n8k16.row.col.f32.bf16.bf16.f32 " \
    "{%0,%1,%2,%3},{%4,%5,%6,%7},{%8,%9},{%0,%1,%2,%3};\n" \
    : "+f"((d)[0]), "+f"((d)[1]), "+f"((d)[2]), "+f"((d)[3]) \
    : "r"((a)[0]), "r"((a)[1]), "r"((a)[2]), "r"((a)[3]), "r"((b)[0]), "r"((b)[1]))

// hi+lo bf16 reconstruction of 4 packed values
__device__ __forceinline__ float4 un4(uint2 h, uint2 l) {
    float4 r;
    r.x = __int_as_float(h.x << 16)        + __int_as_float(l.x << 16);
    r.y = __int_as_float(h.x & 0xffff0000u) + __int_as_float(l.x & 0xffff0000u);
    r.z = __int_as_float(h.y << 16)        + __int_as_float(l.y << 16);
    r.w = __int_as_float(h.y & 0xffff0000u) + __int_as_float(l.y & 0xffff0000u);
    return r;
}

// ---------------- stage 0: softmax of mixing weights ----------------
__global__ void k_softmaxw(const float* __restrict__ wk, const float* __restrict__ wv) {
    int tid = threadIdx.x;
    if (tid >= 2*Hc) return;
    int h = tid % Hc;
    const float* src = (tid < Hc ? wk : wv) + h*Lc;
    float* dst = (tid < Hc ? g_kw : g_vw) + h*Lc;
    float m = -1e30f;
    for (int l = 0; l < Lc; l++) m = fmaxf(m, src[l]);
    float e[Lc]; float s = 0.f;
    for (int l = 0; l < Lc; l++) { e[l] = expf(src[l]-m); s += e[l]; }
    float inv = 1.f/s;
    for (int l = 0; l < Lc; l++) dst[l] = e[l]*inv;
}

// ---------------- zero S + stats ----------------
__global__ void k_zero() {
    int i = blockIdx.x*blockDim.x + threadIdx.x;
    float4 z = make_float4(0.f,0.f,0.f,0.f);
    if (i < 262144) { ((float4*)g_S)[i] = z; return; }
    int j = i - 262144;
    if (j < 4096) { ((float4*)g_s1)[j] = z; return; }
    ((float4*)g_s2)[j - 4096] = z;
}

// ---------------- pack W to bf16 hi/lo ----------------
__global__ void k_wconv(const float* __restrict__ Wk, const float* __restrict__ Wv) {
    size_t i = (size_t)blockIdx.x*256 + threadIdx.x;
    const float* W = blockIdx.y ? Wv : Wk;
    float v = W[i];
    __nv_bfloat16 h16 = __float2bfloat16(v);
    __nv_bfloat16 l16 = __float2bfloat16(v - __bfloat162float(h16));
    size_t o = (size_t)blockIdx.y*(Hc*Dc*Fc) + i;
    g_whi[o] = h16;
    g_wlo[o] = l16;
}

// ---------------- stage 1: L-contraction -> bf16 hi/lo [t][f] ----------------
// block (16 t, 16 f); x staged via coalesced float4 into smem.
__global__ __launch_bounds__(256) void k_raw(const float* __restrict__ x) {
    __shared__ float skw[Hc*Lc];
    __shared__ float svw[Hc*Lc];
    __shared__ float xs[16][212];                               // [f][t*13+l]
    __shared__ __align__(16) unsigned short s_hi[2][Hc][16][18]; // [kv][h][t][f]
    __shared__ __align__(16) unsigned short s_lo[2][Hc][16][18];
    int tx = threadIdx.x;      // t
    int ty = threadIdx.y;      // f
    int tid = ty*16 + tx;
    if (tid < Hc*Lc) { skw[tid] = g_kw[tid]; svw[tid] = g_vw[tid]; }

    int t0 = blockIdx.x*16;
    int f0 = blockIdx.y*16;
    int b  = blockIdx.z;

    // stage x tile: 16 f-rows x 52 float4 (208 floats), coalesced
    int maxf4 = (Tc - t0 >= 16) ? 52 : ((Tc - t0)*13) >> 2;
#pragma unroll
    for (int it = 0; it < 4; it++) {
        int idx = tid + it*256;
        if (idx < 832) {
            int row = idx / 52, col = idx % 52;
            if (col < maxf4) {
                const float* src = x + ((size_t)(b*Fc + f0 + row)*Tc + t0)*13;
                *(float4*)&xs[row][col*4] = ((const float4*)src)[col];
            }
        }
    }
    __syncthreads();

    float xv[Lc];
#pragma unroll
    for (int l = 0; l < Lc; l++) xv[l] = xs[ty][tx*13 + l];

#pragma unroll
    for (int h = 0; h < Hc; h++) {
        float kr = 0.f, vr = 0.f;
#pragma unroll
        for (int l = 0; l < Lc; l++) {
            kr += xv[l]*skw[h*Lc + l];
            vr += xv[l]*svw[h*Lc + l];
        }
        __nv_bfloat16 kh = __float2bfloat16(kr);
        __nv_bfloat16 kl = __float2bfloat16(kr - __bfloat162float(kh));
        __nv_bfloat16 vh = __float2bfloat16(vr);
        __nv_bfloat16 vl = __float2bfloat16(vr - __bfloat162float(vh));
        s_hi[0][h][tx][ty] = __bfloat16_as_ushort(kh);
        s_lo[0][h][tx][ty] = __bfloat16_as_ushort(kl);
        s_hi[1][h][tx][ty] = __bfloat16_as_ushort(vh);
        s_lo[1][h][tx][ty] = __bfloat16_as_ushort(vl);
    }
    __syncthreads();

    // write: 32 jobs (kv, plane, h); 4B packed stores, lanes along f
    int w = tid >> 5, lane = tid & 31;
    int f2 = lane & 7;
    int tr = lane >> 3;
#pragma unroll
    for (int it = 0; it < 4; it++) {
        int job = w*4 + it;
        int kv = job >> 4;
        int plane = (job >> 3) & 1;
        int h = job & 7;
        __nv_bfloat16* arr = plane ? g_alo : g_ahi;
        size_t rowbase = ((size_t)(kv*Bc + b)*Hc + h)*Tc;
#pragma unroll
        for (int ti = 0; ti < 4; ti++) {
            int tl = ti*4 + tr;
            int tt = t0 + tl;
            if (tt < Tc) {
                const unsigned short* srow = plane ? &s_lo[kv][h][tl][0] : &s_hi[kv][h][tl][0];
                unsigned val = *(const unsigned*)(srow + f2*2);
                *(unsigned*)(arr + (rowbase + tt)*Fc + f0 + f2*2) = val;
            }
        }
    }
}

// ---------------- stage 2: mma.sync GEMM -> [d][t] bf16 planes + stats ----------------
#define RS 80
#define PLANE_B (128*RS)
#define STAGE_B (4*PLANE_B)
#define NSTAGE 3
#define GSMEM (NSTAGE*STAGE_B)
#define NCH (Fc/32)

__device__ __forceinline__ void prefetch_chunk(
    int c, int stage, uint32_t sb, int t0, int tid,
    const __nv_bfloat16* __restrict__ Ahi, const __nv_bfloat16* __restrict__ Alo,
    const __nv_bfloat16* __restrict__ Bhi, const __nv_bfloat16* __restrict__ Blo) {
    int kc = c*32;
    uint32_t stb = sb + stage*STAGE_B;
#pragma unroll
    for (int it = 0; it < 8; it++) {
        int idx = tid + it*256;
        int plane = idx >> 9;
        int row = (idx >> 2) & 127;
        int seg = idx & 3;
        uint32_t dst = stb + plane*PLANE_B + row*RS + seg*16;
        const __nv_bfloat16* src;
        unsigned sz = 16;
        if (plane < 2) {
            int t = t0 + row;
            if (t >= Tc) { t = 0; sz = 0; }
            src = (plane ? Alo : Ahi) + (size_t)t*Fc + kc + seg*8;
        } else {
            src = (plane == 2 ? Bhi : Blo) + (size_t)row*Fc + kc + seg*8;
        }
        asm volatile("cp.async.cg.shared.global [%0], [%1], 16, %2;"
                     :: "r"(dst), "l"(src), "r"(sz));
    }
    CP_COMMIT();
}

__global__ __launch_bounds__(256, 1) void k_gemm(
    const float* __restrict__ bk, const float* __restrict__ bv) {
    extern __shared__ __align__(1024) char dynsmem[];
    uint32_t sb = smem_u32(dynsmem);

    int tid = threadIdx.x;
    int warp = tid >> 5, lane = tid & 31;
    int bh = blockIdx.y;
    int h = bh & 7;
    int kv = blockIdx.z;
    int t0 = blockIdx.x*128;

    const __nv_bfloat16* Ahi = g_ahi + (size_t)(kv*Bc*Hc + bh)*Tc*Fc;
    const __nv_bfloat16* Alo = g_alo + (size_t)(kv*Bc*Hc + bh)*Tc*Fc;
    const __nv_bfloat16* Bhi = g_whi + (size_t)(kv*Hc + h)*Dc*Fc;
    const __nv_bfloat16* Blo = g_wlo + (size_t)(kv*Hc + h)*Dc*Fc;
    const float* bias = (kv ? bv : bk) + h*Dc;

    int m0w = (warp >> 1)*32;
    int n0w = (warp & 1)*64;
    int arow = (lane & 7) + ((lane >> 3) & 1)*8;
    int akb  = ((lane >> 4) & 1)*16;
    int brow = (lane & 7) + ((lane >> 4) & 1)*8;
    int bkb  = ((lane >> 3) & 1)*16;

    float acc[2][8][4];
#pragma unroll
    for (int i = 0; i < 2; i++)
#pragma unroll
        for (int j = 0; j < 8; j++)
#pragma unroll
            for (int r = 0; r < 4; r++) acc[i][j][r] = 0.f;

    prefetch_chunk(0, 0, sb, t0, tid, Ahi, Alo, Bhi, Blo);
    prefetch_chunk(1, 1, sb, t0, tid, Ahi, Alo, Bhi, Blo);

#pragma unroll 1
    for (int c = 0; c < NCH; c++) {
        if (c < NCH-1) CP_WAIT(1); else CP_WAIT(0);
        __syncthreads();
        if (c + 2 < NCH)
            prefetch_chunk(c+2, (c+2)%NSTAGE, sb, t0, tid, Ahi, Alo, Bhi, Blo);

        uint32_t st = sb + (c%NSTAGE)*STAGE_B;
#pragma unroll
        for (int ks = 0; ks < 2; ks++) {
            unsigned ah[2][4], al[2][4];
#pragma unroll
            for (int mi = 0; mi < 2; mi++) {
                uint32_t a0 = st + (uint32_t)((m0w + mi*16 + arow)*RS + ks*32 + akb);
                LDSM4(ah[mi][0], ah[mi][1], ah[mi][2], ah[mi][3], a0);
                LDSM4(al[mi][0], al[mi][1], al[mi][2], al[mi][3], a0 + PLANE_B);
            }
            unsigned bhf[8][2], blf[8][2];
#pragma unroll
            for (int ni = 0; ni < 4; ni++) {
                uint32_t b0 = st + 2*PLANE_B + (uint32_t)((n0w + ni*16 + brow)*RS + ks*32 + bkb);
                unsigned r0, r1, r2, r3;
                LDSM4(r0, r1, r2, r3, b0);
                bhf[2*ni][0] = r0; bhf[2*ni][1] = r1;
                bhf[2*ni+1][0] = r2; bhf[2*ni+1][1] = r3;
                LDSM4(r0, r1, r2, r3, b0 + PLANE_B);
                blf[2*ni][0] = r0; blf[2*ni][1] = r1;
                blf[2*ni+1][0] = r2; blf[2*ni+1][1] = r3;
            }
#pragma unroll
            for (int mi = 0; mi < 2; mi++)
#pragma unroll
                for (int nj = 0; nj < 8; nj++) {
                    MMA_BF16(acc[mi][nj], ah[mi], bhf[nj]);
                    MMA_BF16(acc[mi][nj], ah[mi], blf[nj]);
                    MMA_BF16(acc[mi][nj], al[mi], bhf[nj]);
                }
        }
    }

    // epilogue: transpose through smem to [d][t], emit bf16 hi/lo planes + stats
    __syncthreads();
    float* Cs = (float*)dynsmem;           // [128 d][132]
    int g = lane >> 2, q = lane & 3;
#pragma unroll
    for (int nj = 0; nj < 8; nj++) {
        int d = n0w + nj*8 + q*2;
        float2 bb = *(const float2*)(bias + d);
#pragma unroll
        for (int mi = 0; mi < 2; mi++) {
            int r = m0w + mi*16 + g;
            Cs[d*132 + r]         = acc[mi][nj][0] + bb.x;
            Cs[(d+1)*132 + r]     = acc[mi][nj][1] + bb.y;
            Cs[d*132 + r + 8]     = acc[mi][nj][2] + bb.x;
            Cs[(d+1)*132 + r + 8] = acc[mi][nj][3] + bb.y;
        }
    }
    __syncthreads();

    __nv_bfloat16* Phi = g_chi + ((size_t)kv*64 + bh)*DT;
    __nv_bfloat16* Plo = g_clo + ((size_t)kv*64 + bh)*DT;
    size_t so = ((size_t)kv*64 + bh)*Dc;
    int tb = t0 + lane*4;
#pragma unroll 1
    for (int rr = 0; rr < 16; rr++) {
        int d = warp*16 + rr;
        float4 v = *(float4*)&Cs[d*132 + lane*4];
        v.x = (tb+0 < Tc) ? v.x : 0.f;
        v.y = (tb+1 < Tc) ? v.y : 0.f;
        v.z = (tb+2 < Tc) ? v.z : 0.f;
        v.w = (tb+3 < Tc) ? v.w : 0.f;
        // split hi/lo
        __nv_bfloat162 h01 = __floats2bfloat162_rn(v.x, v.y);
        __nv_bfloat162 h23 = __floats2bfloat162_rn(v.z, v.w);
        unsigned uh01 = *(unsigned*)&h01, uh23 = *(unsigned*)&h23;
        float f0 = __int_as_float(uh01 << 16);
        float f1 = __int_as_float(uh01 & 0xffff0000u);
        float f2 = __int_as_float(uh23 << 16);
        float f3 = __int_as_float(uh23 & 0xffff0000u);
        __nv_bfloat162 l01 = __floats2bfloat162_rn(v.x - f0, v.y - f1);
        __nv_bfloat162 l23 = __floats2bfloat162_rn(v.z - f2, v.w - f3);
        *(uint2*)(Phi + (size_t)d*TP + tb) = make_uint2(uh01, uh23);
        *(uint2*)(Plo + (size_t)d*TP + tb) = make_uint2(*(unsigned*)&l01, *(unsigned*)&l23);
        // stats
        float p1 = v.x + v.y + v.z + v.w;
        float p2 = v.x*v.x + v.y*v.y + v.z*v.z + v.w*v.w;
        for (int off = 16; off; off >>= 1) {
            p1 += __shfl_down_sync(~0u, p1, off);
            p2 += __shfl_down_sync(~0u, p2, off);
        }
        if (lane == 0) {
            atomicAdd(&g_s1[so + d], p1);
            atomicAdd(&g_s2[so + d], p2);
        }
    }
}

// ---------------- stats finalize + outs init ----------------
__global__ void k_statfin(const float* __restrict__ bproj) {
    int bid = blockIdx.x;
    int tid = threadIdx.x;
    if (bid < 64) {
        int kv = tid >> 7;
        int d = tid & 127;
        size_t o = ((size_t)kv*64 + bid)*Dc + d;
        float s1 = g_s1[o], s2 = g_s2[o];
        float mu = s1 * (1.f/Tc);
        float var = (s2 - (float)Tc*mu*mu) * (1.f/(Tc-1));
        var = fmaxf(var, 0.f);
        float sd = sqrtf(var) + 1e-9f;
        if (kv == 0) { g_muk[bid*Dc + d] = mu; g_sdk[bid*Dc + d] = sd; }
        else         { g_muv[bid*Dc + d] = mu; g_sdv[bid*Dc + d] = sd; }
    } else {
        for (int i = tid; i < Bc*Hc*Ec; i += 256)
            g_outs[i] = bproj[i & (Hc*Ec - 1)];
    }
}

// ---------------- stage 3a: attention + o1 (coalesced [d][t]) ----------------
__global__ __launch_bounds__(256) void k_attn(const float* __restrict__ q) {
    __shared__ float s_sc[TP];
    __shared__ float s_red[256];
    __shared__ float s_q[Dc];
    int tid = threadIdx.x;
    int bh = blockIdx.x;
    int h = bh & 7;
    const __nv_bfloat16* Khi = g_chi + (size_t)bh*DT;
    const __nv_bfloat16* Klo = g_clo + (size_t)bh*DT;
    const __nv_bfloat16* Vhi = g_chi + (size_t)(64 + bh)*DT;
    const __nv_bfloat16* Vlo = g_clo + (size_t)(64 + bh)*DT;
    if (tid < Dc) s_q[tid] = q[h*Dc + tid];
    __syncthreads();

    // scores: thread owns 4 consecutive t
    if (tid < 250) {
        float a0 = 0.f, a1 = 0.f, a2 = 0.f, a3 = 0.f;
#pragma unroll 4
        for (int d = 0; d < Dc; d++) {
            uint2 ph = *(const uint2*)(Khi + (size_t)d*TP + tid*4);
            uint2 pl = *(const uint2*)(Klo + (size_t)d*TP + tid*4);
            float qd = s_q[d];
            float4 kv4 = un4(ph, pl);
            a0 += qd*kv4.x; a1 += qd*kv4.y; a2 += qd*kv4.z; a3 += qd*kv4.w;
        }
        const float sc = 0.08838834764831845f;
        *(float4*)&s_sc[tid*4] = make_float4(a0*sc, a1*sc, a2*sc, a3*sc);
    }
    if (tid < 24) s_sc[1000 + tid] = 0.f;
    __syncthreads();

    // softmax over 1000
    float lm = -1e30f;
    for (int t = tid; t < Tc; t += 256) lm = fmaxf(lm, s_sc[t]);
    s_red[tid] = lm; __syncthreads();
    for (int s = 128; s; s >>= 1) { if (tid < s) s_red[tid] = fmaxf(s_red[tid], s_red[tid+s]); __syncthreads(); }
    float m = s_red[0];
    __syncthreads();
    float ls = 0.f;
    for (int t = tid; t < Tc; t += 256) { float e = expf(s_sc[t]-m); s_sc[t] = e; ls += e; }
    s_red[tid] = ls; __syncthreads();
    for (int s = 128; s; s >>= 1) { if (tid < s) s_red[tid] += s_red[tid+s]; __syncthreads(); }
    float inv = 1.f / s_red[0];
    __syncthreads();

    // o1: warp per 16 d-rows, lanes along t
    int w = tid >> 5, lane = tid & 31;
#pragma unroll 1
    for (int rr = 0; rr < 16; rr++) {
        int d = w*16 + rr;
        float acc = 0.f;
#pragma unroll
        for (int cc = 0; cc < 8; cc++) {
            int grp = lane + cc*32;
            uint2 ph = *(const uint2*)(Vhi + (size_t)d*TP + grp*4);
            uint2 pl = *(const uint2*)(Vlo + (size_t)d*TP + grp*4);
            float4 vv = un4(ph, pl);
            float4 aa = *(float4*)&s_sc[grp*4];
            acc += aa.x*vv.x + aa.y*vv.y + aa.z*vv.z + aa.w*vv.w;
        }
        for (int off = 16; off; off >>= 1) acc += __shfl_down_sync(~0u, acc, off);
        if (lane == 0) g_o1[bh*Dc + d] = acc * inv;
    }
}

// ---------------- stage 3b: S = K^T V via tensor cores on [d][t] planes ----------------
#define NCHS 16    // 512 t per segment / 32

__device__ __forceinline__ void prefetch_smat(
    int c, int stage, uint32_t sb, int tid,
    const __nv_bfloat16* __restrict__ Ahi, const __nv_bfloat16* __restrict__ Alo,
    const __nv_bfloat16* __restrict__ Bhi, const __nv_bfloat16* __restrict__ Blo) {
    int kc = c*32;
    uint32_t stb = sb + stage*STAGE_B;
#pragma unroll
    for (int it = 0; it < 8; it++) {
        int idx = tid + it*256;
        int plane = idx >> 9;
        int row = (idx >> 2) & 127;
        int seg = idx & 3;
        uint32_t dst = stb + plane*PLANE_B + row*RS + seg*16;
        const __nv_bfloat16* src =
            (plane == 0 ? Ahi : plane == 1 ? Alo : plane == 2 ? Bhi : Blo)
            + (size_t)row*TP + kc + seg*8;
        asm volatile("cp.async.cg.shared.global [%0], [%1], 16;" :: "r"(dst), "l"(src));
    }
    CP_COMMIT();
}

__global__ __launch_bounds__(256, 1) void k_smat() {
    extern __shared__ __align__(1024) char dynsmem[];
    uint32_t sb = smem_u32(dynsmem);
    int tid = threadIdx.x;
    int warp = tid >> 5, lane = tid & 31;
    int bh = blockIdx.y;
    int seg = blockIdx.x;           // t segment 0/1
    const __nv_bfloat16* Ahi = g_chi + (size_t)bh*DT + seg*512;
    const __nv_bfloat16* Alo = g_clo + (size_t)bh*DT + seg*512;
    const __nv_bfloat16* Bhi = g_chi + (size_t)(64 + bh)*DT + seg*512;
    const __nv_bfloat16* Blo = g_clo + (size_t)(64 + bh)*DT + seg*512;

    int m0w = (warp >> 1)*32;
    int n0w = (warp & 1)*64;
    int arow = (lane & 7) + ((lane >> 3) & 1)*8;
    int akb  = ((lane >> 4) & 1)*16;
    int brow = (lane & 7) + ((lane >> 4) & 1)*8;
    int bkb  = ((lane >> 3) & 1)*16;

    float acc[2][8][4];
#pragma unroll
    for (int i = 0; i < 2; i++)
#pragma unroll
        for (int j = 0; j < 8; j++)
#pragma unroll
            for (int r = 0; r < 4; r++) acc[i][j][r] = 0.f;

    prefetch_smat(0, 0, sb, tid, Ahi, Alo, Bhi, Blo);
    prefetch_smat(1, 1, sb, tid, Ahi, Alo, Bhi, Blo);

#pragma unroll 1
    for (int c = 0; c < NCHS; c++) {
        if (c < NCHS-1) CP_WAIT(1); else CP_WAIT(0);
        __syncthreads();
        if (c + 2 < NCHS)
            prefetch_smat(c+2, (c+2)%NSTAGE, sb, tid, Ahi, Alo, Bhi, Blo);

        uint32_t st = sb + (c%NSTAGE)*STAGE_B;
#pragma unroll
        for (int ks = 0; ks < 2; ks++) {
            unsigned ah[2][4], al[2][4];
#pragma unroll
            for (int mi = 0; mi < 2; mi++) {
                uint32_t a0 = st + (uint32_t)((m0w + mi*16 + arow)*RS + ks*32 + akb);
                LDSM4(ah[mi][0], ah[mi][1], ah[mi][2], ah[mi][3], a0);
                LDSM4(al[mi][0], al[mi][1], al[mi][2], al[mi][3], a0 + PLANE_B);
            }
            unsigned bhf[8][2], blf[8][2];
#pragma unroll
            for (int ni = 0; ni < 4; ni++) {
                uint32_t b0 = st + 2*PLANE_B + (uint32_t)((n0w + ni*16 + brow)*RS + ks*32 + bkb);
                unsigned r0, r1, r2, r3;
                LDSM4(r0, r1, r2, r3, b0);
                bhf[2*ni][0] = r0; bhf[2*ni][1] = r1;
                bhf[2*ni+1][0] = r2; bhf[2*ni+1][1] = r3;
                LDSM4(r0, r1, r2, r3, b0 + PLANE_B);
                blf[2*ni][0] = r0; blf[2*ni][1] = r1;
                blf[2*ni+1][0] = r2; blf[2*ni+1][1] = r3;
            }
#pragma unroll
            for (int mi = 0; mi < 2; mi++)
#pragma unroll
                for (int nj = 0; nj < 8; nj++) {
                    MMA_BF16(acc[mi][nj], ah[mi], bhf[nj]);
                    MMA_BF16(acc[mi][nj], ah[mi], blf[nj]);
                    MMA_BF16(acc[mi][nj], al[mi], bhf[nj]);
                }
        }
    }

    float* Sp = g_S + (size_t)bh*Dc*Dc;
    int g = lane >> 2, q = lane & 3;
#pragma unroll
    for (int nj = 0; nj < 8; nj++) {
        int l = n0w + nj*8 + q*2;
#pragma unroll
        for (int mi = 0; mi < 2; mi++) {
            int k0 = m0w + mi*16 + g;
            atomicAdd(&Sp[k0*Dc + l],       acc[mi][nj][0]);
            atomicAdd(&Sp[k0*Dc + l + 1],   acc[mi][nj][1]);
            atomicAdd(&Sp[(k0+8)*Dc + l],   acc[mi][nj][2]);
            atomicAdd(&Sp[(k0+8)*Dc + l+1], acc[mi][nj][3]);
        }
    }
}

// ---------------- stage 3c: normalized correlation ----------------
__global__ void k_corr() {
    int c = blockIdx.x*256 + threadIdx.x;
    int bh = blockIdx.y;
    if (c >= DCORR) return;
    float disc = 65025.0f - 8.0f*(float)c;
    int k = (int)((255.0f - sqrtf(disc))*0.5f);
    if (k < 0) k = 0;
    if (k > 126) k = 126;
    while (k > 0 && k*(255-k)/2 > c) k--;
    while ((k+1)*(254-k)/2 <= c) k++;
    int l = k + 1 + (c - k*(255-k)/2);
    float muk = g_muk[bh*Dc + k], sdk = g_sdk[bh*Dc + k];
    float muv = g_muv[bh*Dc + l], sdv = g_sdv[bh*Dc + l];
    float S = g_S[(size_t)bh*Dc*Dc + k*Dc + l];
    g_corr[(size_t)bh*DCORR + c] = (S - (float)Tc*muk*muv) / ((float)Tc*sdk*sdv);
}

// ---------------- stage 4: outs += corr . Wproj ----------------
__global__ __launch_bounds__(256) void k_proj(const float* __restrict__ Wproj) {
    __shared__ float sc[8][128];
    int tid = threadIdx.x;
    int h = blockIdx.y;
    int cs = blockIdx.z;
    int el = tid & 31;
    int b = tid >> 5;
    int e = blockIdx.x*32 + el;
    int lrow = tid >> 5;
    int lc = (tid & 31)*4;
    int start = cs*2032, end = start + 2032;
    const float* wrow = Wproj + ((size_t)h*Ec + e)*DCORR;
    float acc = 0.f;
    for (int c0 = start; c0 < end; c0 += 128) {
        int lim = end - c0; if (lim > 128) lim = 128;
        float4 cv = make_float4(0.f,0.f,0.f,0.f);
        if (lc < lim) cv = *(const float4*)(g_corr + ((size_t)lrow*Hc + h)*DCORR + c0 + lc);
        *(float4*)&sc[lrow][lc] = cv;
        __syncthreads();
#pragma unroll 8
        for (int j = 0; j < lim; j += 4) {
            float4 wv = *(const float4*)(wrow + c0 + j);
            float4 sv = *(const float4*)&sc[b][j];
            acc += wv.x*sv.x + wv.y*sv.y + wv.z*sv.z + wv.w*sv.w;
        }
        __syncthreads();
    }
    atomicAdd(&g_outs[b*(Hc*Ec) + h*Ec + e], acc);
}

// ---------------- stage 5: final linears + mix ----------------
__global__ __launch_bounds__(256) void k_final(
    const float* __restrict__ WT, const float* __restrict__ bT,
    const float* __restrict__ Wp, const float* __restrict__ bp,
    float* __restrict__ out) {
    __shared__ float so1[Hc*Dc];
    __shared__ float sout[Hc*Ec];
    __shared__ float sred[256];
    int b = blockIdx.x, ec = blockIdx.y;
    int tid = threadIdx.x;
    for (int j = tid; j < Hc*Dc; j += 256) so1[j]  = g_o1[b*Hc*Dc + j];
    for (int j = tid; j < Hc*Ec; j += 256) sout[j] = g_outs[b*Hc*Ec + j];
    __syncthreads();
    int e_l = tid >> 3, js = tid & 7;
    int e = ec*32 + e_l;
    float a = 0.f;
    const float* wt = WT + (size_t)e*(Hc*Dc) + js*128;
    const float* s1p = so1 + js*128;
#pragma unroll 4
    for (int j = 0; j < 128; j += 4) {
        float4 wv = *(const float4*)(wt + j);
        float4 sv = *(const float4*)(s1p + j);
        a += wv.x*sv.x + wv.y*sv.y + wv.z*sv.z + wv.w*sv.w;
    }
    const float* wp = Wp + (size_t)e*(Hc*Ec) + js*256;
    const float* s2p = sout + js*256;
#pragma unroll 4
    for (int j = 0; j < 256; j += 4) {
        float4 wv = *(const float4*)(wp + j);
        float4 sv = *(const float4*)(s2p + j);
        a += wv.x*sv.x + wv.y*sv.y + wv.z*sv.z + wv.w*sv.w;
    }
    if (js == 0) a += bT[e] + bp[e];
    sred[tid] = a;
    __syncthreads();
    if (tid < 32) {
        float s = 0.f;
#pragma unroll
        for (int k = 0; k < 8; k++) s += sred[tid*8 + k];
        out[b*Ec + ec*32 + tid] = 0.5f*s;
    }
}

// ---------------- launch ----------------
extern "C" void kernel_launch(void* const* d_in, const int* in_sizes, int n_in,
                              void* d_out, int out_size) {
    const float* x     = (const float*)d_in[0];
    const float* wk    = (const float*)d_in[1];
    const float* wv    = (const float*)d_in[2];
    const float* q     = (const float*)d_in[3];
    const float* Wk    = (const float*)d_in[4];
    const float* bk    = (const float*)d_in[5];
    const float* Wv    = (const float*)d_in[6];
    const float* bv    = (const float*)d_in[7];
    const float* Wproj = (const float*)d_in[8];
    const float* bproj = (const float*)d_in[9];
    const float* WT    = (const float*)d_in[10];
    const float* bT    = (const float*)d_in[11];
    const float* Wp    = (const float*)d_in[12];
    const float* bp    = (const float*)d_in[13];
    float* out = (float*)d_out;

    cudaFuncSetAttribute(k_gemm, cudaFuncAttributeMaxDynamicSharedMemorySize, GSMEM);
    cudaFuncSetAttribute(k_smat, cudaFuncAttributeMaxDynamicSharedMemorySize, GSMEM);

    k_softmaxw<<<1, 32>>>(wk, wv);
    k_zero<<<1056, 256>>>();
    k_wconv<<<dim3((Hc*Dc*Fc)/256, 2), 256>>>(Wk, Wv);
    k_raw<<<dim3((Tc+15)/16, Fc/16, Bc), dim3(16, 16)>>>(x);   // 4th launch -> ncu
    k_gemm<<<dim3(8, Bc*Hc, 2), 256, GSMEM>>>(bk, bv);
    k_statfin<<<65, 256>>>(bproj);
    k_attn<<<Bc*Hc, 256>>>(q);
    k_smat<<<dim3(2, Bc*Hc), 256, GSMEM>>>();
    k_corr<<<dim3((DCORR+255)/256, Bc*Hc), 256>>>();
    k_proj<<<dim3(Ec/32, Hc, 4), 256>>>(Wproj);
    k_final<<<dim3(Bc, Ec/32), 256>>>(WT, bT, Wp, bp, out);
}

// round 7
// speedup vs baseline: 2.0506x; 1.0531x over previous
#include <cuda_runtime.h>
#include <cuda_bf16.h>
#include <math.h>
#include <stdint.h>

// Problem constants
#define Bc 8
#define Hc 8
#define Fc 768
#define Dc 128
#define Ec 256
#define Lc 13
#define Tc 1000
#define DCORR 8128
#define TP 1024                 // padded T
#define DT (128*TP)             // plane size per (kv,bh)

// ---------------- device scratch ----------------
__device__ float g_kw[Hc*Lc];
__device__ float g_vw[Hc*Lc];
__device__ __nv_bfloat16 g_ahi[(size_t)2*Bc*Hc*Tc*Fc];   // raw activations [kv][bh][t][f]
__device__ __nv_bfloat16 g_alo[(size_t)2*Bc*Hc*Tc*Fc];
__device__ __nv_bfloat16 g_whi[(size_t)2*Hc*Dc*Fc];      // weights [kv][h][d][f]
__device__ __nv_bfloat16 g_wlo[(size_t)2*Hc*Dc*Fc];
__device__ __nv_bfloat16 g_chi[(size_t)2*Bc*Hc*DT];      // GEMM out planes [kv][bh][d][t]
__device__ __nv_bfloat16 g_clo[(size_t)2*Bc*Hc*DT];
__device__ float g_s1[2*Bc*Hc*Dc];
__device__ float g_s2[2*Bc*Hc*Dc];
__device__ float g_muk[Bc*Hc*Dc];
__device__ float g_sdk[Bc*Hc*Dc];
__device__ float g_muv[Bc*Hc*Dc];
__device__ float g_sdv[Bc*Hc*Dc];
__device__ float g_o1[Bc*Hc*Dc];
__device__ float g_S[(size_t)Bc*Hc*Dc*Dc];
__device__ float g_corr[(size_t)Bc*Hc*DCORR];
__device__ float g_outs[Bc*Hc*Ec];

__device__ __forceinline__ uint32_t smem_u32(const void* p) {
    uint32_t a;
    asm("{ .reg .u64 t; cvta.to.shared.u64 t, %1; cvt.u32.u64 %0, t; }" : "=r"(a) : "l"(p));
    return a;
}
#define CP_COMMIT()  asm volatile("cp.async.commit_group;" ::: "memory")
#define CP_WAIT(n)   asm volatile("cp.async.wait_group %0;" :: "n"(n) : "memory")
#define LDSM4(r0, r1, r2, r3, a) \
    asm volatile("ldmatrix.sync.aligned.m8n8.x4.shared.b16 {%0,%1,%2,%3}, [%4];" \
        : "=r"(r0), "=r"(r1), "=r"(r2), "=r"(r3) : "r"(a))
#define MMA_BF16(d, a, b) asm volatile( \
    "mma.sync.aligned.m16n8k16.row.col.f32.bf16.bf16.f32 " \
    "{%0,%1,%2,%3},{%4,%5,%6,%7},{%8,%9},{%0,%1,%2,%3};\n" \
    : "+f"((d)[0]), "+f"((d)[1]), "+f"((d)[2]), "+f"((d)[3]) \
    : "r"((a)[0]), "r"((a)[1]), "r"((a)[2]), "r"((a)[3]), "r"((b)[0]), "r"((b)[1]))

// hi+lo bf16 reconstruction of 4 packed values
__device__ __forceinline__ float4 un4(uint2 h, uint2 l) {
    float4 r;
    r.x = __int_as_float(h.x << 16)        + __int_as_float(l.x << 16);
    r.y = __int_as_float(h.x & 0xffff0000u) + __int_as_float(l.x & 0xffff0000u);
    r.z = __int_as_float(h.y << 16)        + __int_as_float(l.y << 16);
    r.w = __int_as_float(h.y & 0xffff0000u) + __int_as_float(l.y & 0xffff0000u);
    return r;
}

// ---------------- stage 0: softmax of mixing weights ----------------
__global__ void k_softmaxw(const float* __restrict__ wk, const float* __restrict__ wv) {
    int tid = threadIdx.x;
    if (tid >= 2*Hc) return;
    int h = tid % Hc;
    const float* src = (tid < Hc ? wk : wv) + h*Lc;
    float* dst = (tid < Hc ? g_kw : g_vw) + h*Lc;
    float m = -1e30f;
    for (int l = 0; l < Lc; l++) m = fmaxf(m, src[l]);
    float e[Lc]; float s = 0.f;
    for (int l = 0; l < Lc; l++) { e[l] = expf(src[l]-m); s += e[l]; }
    float inv = 1.f/s;
    for (int l = 0; l < Lc; l++) dst[l] = e[l]*inv;
}

// ---------------- zero S + stats ----------------
__global__ void k_zero() {
    int i = blockIdx.x*blockDim.x + threadIdx.x;
    float4 z = make_float4(0.f,0.f,0.f,0.f);
    if (i < 262144) { ((float4*)g_S)[i] = z; return; }
    int j = i - 262144;
    if (j < 4096) { ((float4*)g_s1)[j] = z; return; }
    ((float4*)g_s2)[j - 4096] = z;
}

// ---------------- pack W to bf16 hi/lo ----------------
__global__ void k_wconv(const float* __restrict__ Wk, const float* __restrict__ Wv) {
    size_t i = (size_t)blockIdx.x*256 + threadIdx.x;
    const float* W = blockIdx.y ? Wv : Wk;
    float v = W[i];
    __nv_bfloat16 h16 = __float2bfloat16(v);
    __nv_bfloat16 l16 = __float2bfloat16(v - __bfloat162float(h16));
    size_t o = (size_t)blockIdx.y*(Hc*Dc*Fc) + i;
    g_whi[o] = h16;
    g_wlo[o] = l16;
}

// ---------------- stage 1: L-contraction -> bf16 hi/lo [t][f] ----------------
// block (16 t, 8 f-pairs) = 128 threads; 2 f per thread; truncation hi split.
__global__ __launch_bounds__(128) void k_raw(const float* __restrict__ x) {
    __shared__ float2 skv[Hc*Lc];                 // (kw, vw)
    __shared__ float xs[16][212];                 // [f][t*13+l]
    __shared__ unsigned s_ohi[2][Hc][16][9];      // [kv][h][t][fword]
    __shared__ unsigned s_olo[2][Hc][16][9];
    int tx = threadIdx.x;      // t
    int ty = threadIdx.y;      // f-pair
    int tid = ty*16 + tx;
    if (tid < Hc*Lc) skv[tid] = make_float2(g_kw[tid], g_vw[tid]);

    int t0 = blockIdx.x*16;
    int f0 = blockIdx.y*16;
    int b  = blockIdx.z;

    // stage x tile: 16 f-rows x 52 float4, coalesced
    int maxf4 = (Tc - t0 >= 16) ? 52 : ((Tc - t0)*13) >> 2;
#pragma unroll
    for (int it = 0; it < 7; it++) {
        int idx = tid + it*128;
        if (idx < 832) {
            int row = idx / 52, col = idx % 52;
            if (col < maxf4) {
                const float* src = x + ((size_t)(b*Fc + f0 + row)*Tc + t0)*13;
                *(float4*)&xs[row][col*4] = ((const float4*)src)[col];
            }
        }
    }
    __syncthreads();

    float xv0[Lc], xv1[Lc];
#pragma unroll
    for (int l = 0; l < Lc; l++) {
        xv0[l] = xs[ty*2][tx*13 + l];
        xv1[l] = xs[ty*2 + 1][tx*13 + l];
    }

#pragma unroll
    for (int h = 0; h < Hc; h++) {
        float k0 = 0.f, v0 = 0.f, k1 = 0.f, v1 = 0.f;
#pragma unroll
        for (int l = 0; l < Lc; l++) {
            float2 w = skv[h*Lc + l];
            k0 += xv0[l]*w.x; v0 += xv0[l]*w.y;
            k1 += xv1[l]*w.x; v1 += xv1[l]*w.y;
        }
        // kv=0 (k0,k1): hi = truncated top16, lo = bf16(residual)
        {
            unsigned b0 = __float_as_uint(k0), b1 = __float_as_uint(k1);
            unsigned hiw = __byte_perm(b0, b1, 0x7632);
            float d0 = k0 - __uint_as_float(b0 & 0xffff0000u);
            float d1 = k1 - __uint_as_float(b1 & 0xffff0000u);
            unsigned low;
            asm("cvt.rn.bf16x2.f32 %0, %1, %2;" : "=r"(low) : "f"(d1), "f"(d0));
            s_ohi[0][h][tx][ty] = hiw;
            s_olo[0][h][tx][ty] = low;
        }
        // kv=1 (v0,v1)
        {
            unsigned b0 = __float_as_uint(v0), b1 = __float_as_uint(v1);
            unsigned hiw = __byte_perm(b0, b1, 0x7632);
            float d0 = v0 - __uint_as_float(b0 & 0xffff0000u);
            float d1 = v1 - __uint_as_float(b1 & 0xffff0000u);
            unsigned low;
            asm("cvt.rn.bf16x2.f32 %0, %1, %2;" : "=r"(low) : "f"(d1), "f"(d0));
            s_ohi[1][h][tx][ty] = hiw;
            s_olo[1][h][tx][ty] = low;
        }
    }
    __syncthreads();

    // write phase: 16 jobs (kv,h) over 4 warps
    int w = tid >> 5, lane = tid & 31;
    int f2 = lane & 7;          // f-word
    int tq = lane >> 3;         // 0..3
#pragma unroll
    for (int it = 0; it < 4; it++) {
        int job = w*4 + it;     // 0..15
        int kv = job >> 3;
        int h = job & 7;
        size_t rowbase = ((size_t)(kv*Bc + b)*Hc + h)*Tc;
#pragma unroll
        for (int ti = 0; ti < 4; ti++) {
            int tl = ti*4 + tq;
            int tt = t0 + tl;
            if (tt < Tc) {
                size_t off = (rowbase + tt)*Fc + f0 + f2*2;
                *(unsigned*)(g_ahi + off) = s_ohi[kv][h][tl][f2];
                *(unsigned*)(g_alo + off) = s_olo[kv][h][tl][f2];
            }
        }
    }
}

// ---------------- stage 2: mma.sync GEMM -> [d][t] bf16 planes + stats ----------------
#define RS 80
#define PLANE_B (128*RS)
#define STAGE_B (4*PLANE_B)
#define NSTAGE 2
#define GSMEM (NSTAGE*STAGE_B)   // 81920
#define NCH (Fc/32)

__device__ __forceinline__ void prefetch_chunk(
    int c, int stage, uint32_t sb, int t0, int tid,
    const __nv_bfloat16* __restrict__ Ahi, const __nv_bfloat16* __restrict__ Alo,
    const __nv_bfloat16* __restrict__ Bhi, const __nv_bfloat16* __restrict__ Blo) {
    int kc = c*32;
    uint32_t stb = sb + stage*STAGE_B;
#pragma unroll
    for (int it = 0; it < 8; it++) {
        int idx = tid + it*256;
        int plane = idx >> 9;
        int row = (idx >> 2) & 127;
        int seg = idx & 3;
        uint32_t dst = stb + plane*PLANE_B + row*RS + seg*16;
        const __nv_bfloat16* src;
        unsigned sz = 16;
        if (plane < 2) {
            int t = t0 + row;
            if (t >= Tc) { t = 0; sz = 0; }
            src = (plane ? Alo : Ahi) + (size_t)t*Fc + kc + seg*8;
        } else {
            src = (plane == 2 ? Bhi : Blo) + (size_t)row*Fc + kc + seg*8;
        }
        asm volatile("cp.async.cg.shared.global [%0], [%1], 16, %2;"
                     :: "r"(dst), "l"(src), "r"(sz));
    }
    CP_COMMIT();
}

__global__ __launch_bounds__(256, 2) void k_gemm(
    const float* __restrict__ bk, const float* __restrict__ bv) {
    extern __shared__ __align__(1024) char dynsmem[];
    uint32_t sb = smem_u32(dynsmem);

    int tid = threadIdx.x;
    int warp = tid >> 5, lane = tid & 31;
    int bh = blockIdx.y;
    int h = bh & 7;
    int kv = blockIdx.z;
    int t0 = blockIdx.x*128;

    const __nv_bfloat16* Ahi = g_ahi + (size_t)(kv*Bc*Hc + bh)*Tc*Fc;
    const __nv_bfloat16* Alo = g_alo + (size_t)(kv*Bc*Hc + bh)*Tc*Fc;
    const __nv_bfloat16* Bhi = g_whi + (size_t)(kv*Hc + h)*Dc*Fc;
    const __nv_bfloat16* Blo = g_wlo + (size_t)(kv*Hc + h)*Dc*Fc;
    const float* bias = (kv ? bv : bk) + h*Dc;

    int m0w = (warp >> 1)*32;
    int n0w = (warp & 1)*64;
    int arow = (lane & 7) + ((lane >> 3) & 1)*8;
    int akb  = ((lane >> 4) & 1)*16;
    int brow = (lane & 7) + ((lane >> 4) & 1)*8;
    int bkb  = ((lane >> 3) & 1)*16;

    float acc[2][8][4];
#pragma unroll
    for (int i = 0; i < 2; i++)
#pragma unroll
        for (int j = 0; j < 8; j++)
#pragma unroll
            for (int r = 0; r < 4; r++) acc[i][j][r] = 0.f;

    prefetch_chunk(0, 0, sb, t0, tid, Ahi, Alo, Bhi, Blo);
    prefetch_chunk(1, 1, sb, t0, tid, Ahi, Alo, Bhi, Blo);

#pragma unroll 1
    for (int c = 0; c < NCH; c++) {
        if (c < NCH-1) CP_WAIT(1); else CP_WAIT(0);
        __syncthreads();
        uint32_t st = sb + (c & 1)*STAGE_B;
#pragma unroll
        for (int ks = 0; ks < 2; ks++) {
            unsigned ah[2][4], al[2][4];
#pragma unroll
            for (int mi = 0; mi < 2; mi++) {
                uint32_t a0 = st + (uint32_t)((m0w + mi*16 + arow)*RS + ks*32 + akb);
                LDSM4(ah[mi][0], ah[mi][1], ah[mi][2], ah[mi][3], a0);
                LDSM4(al[mi][0], al[mi][1], al[mi][2], al[mi][3], a0 + PLANE_B);
            }
#pragma unroll
            for (int ni = 0; ni < 4; ni++) {
                uint32_t b0 = st + 2*PLANE_B + (uint32_t)((n0w + ni*16 + brow)*RS + ks*32 + bkb);
                unsigned bhv[4], blv[4];
                LDSM4(bhv[0], bhv[1], bhv[2], bhv[3], b0);
                LDSM4(blv[0], blv[1], blv[2], blv[3], b0 + PLANE_B);
#pragma unroll
                for (int mi = 0; mi < 2; mi++)
#pragma unroll
                    for (int j2 = 0; j2 < 2; j2++) {
                        int nj = ni*2 + j2;
                        MMA_BF16(acc[mi][nj], ah[mi], &bhv[j2*2]);
                        MMA_BF16(acc[mi][nj], ah[mi], &blv[j2*2]);
                        MMA_BF16(acc[mi][nj], al[mi], &bhv[j2*2]);
                    }
            }
        }
        __syncthreads();
        if (c + 2 < NCH)
            prefetch_chunk(c+2, c & 1, sb, t0, tid, Ahi, Alo, Bhi, Blo);
    }

    // epilogue: transpose through smem to [d][t], emit bf16 hi/lo planes + stats
    __syncthreads();
    float* Cs = (float*)dynsmem;           // [128 d][132]
    int g = lane >> 2, q = lane & 3;
#pragma unroll
    for (int nj = 0; nj < 8; nj++) {
        int d = n0w + nj*8 + q*2;
        float2 bb = *(const float2*)(bias + d);
#pragma unroll
        for (int mi = 0; mi < 2; mi++) {
            int r = m0w + mi*16 + g;
            Cs[d*132 + r]         = acc[mi][nj][0] + bb.x;
            Cs[(d+1)*132 + r]     = acc[mi][nj][1] + bb.y;
            Cs[d*132 + r + 8]     = acc[mi][nj][2] + bb.x;
            Cs[(d+1)*132 + r + 8] = acc[mi][nj][3] + bb.y;
        }
    }
    __syncthreads();

    __nv_bfloat16* Phi = g_chi + ((size_t)kv*64 + bh)*DT;
    __nv_bfloat16* Plo = g_clo + ((size_t)kv*64 + bh)*DT;
    size_t so = ((size_t)kv*64 + bh)*Dc;
    int tb = t0 + lane*4;
#pragma unroll 1
    for (int rr = 0; rr < 16; rr++) {
        int d = warp*16 + rr;
        float4 v = *(float4*)&Cs[d*132 + lane*4];
        v.x = (tb+0 < Tc) ? v.x : 0.f;
        v.y = (tb+1 < Tc) ? v.y : 0.f;
        v.z = (tb+2 < Tc) ? v.z : 0.f;
        v.w = (tb+3 < Tc) ? v.w : 0.f;
        __nv_bfloat162 h01 = __floats2bfloat162_rn(v.x, v.y);
        __nv_bfloat162 h23 = __floats2bfloat162_rn(v.z, v.w);
        unsigned uh01 = *(unsigned*)&h01, uh23 = *(unsigned*)&h23;
        float f0 = __int_as_float(uh01 << 16);
        float f1 = __int_as_float(uh01 & 0xffff0000u);
        float f2 = __int_as_float(uh23 << 16);
        float f3 = __int_as_float(uh23 & 0xffff0000u);
        __nv_bfloat162 l01 = __floats2bfloat162_rn(v.x - f0, v.y - f1);
        __nv_bfloat162 l23 = __floats2bfloat162_rn(v.z - f2, v.w - f3);
        *(uint2*)(Phi + (size_t)d*TP + tb) = make_uint2(uh01, uh23);
        *(uint2*)(Plo + (size_t)d*TP + tb) = make_uint2(*(unsigned*)&l01, *(unsigned*)&l23);
        float p1 = v.x + v.y + v.z + v.w;
        float p2 = v.x*v.x + v.y*v.y + v.z*v.z + v.w*v.w;
        for (int off = 16; off; off >>= 1) {
            p1 += __shfl_down_sync(~0u, p1, off);
            p2 += __shfl_down_sync(~0u, p2, off);
        }
        if (lane == 0) {
            atomicAdd(&g_s1[so + d], p1);
            atomicAdd(&g_s2[so + d], p2);
        }
    }
}

// ---------------- stats finalize + outs init ----------------
__global__ void k_statfin(const float* __restrict__ bproj) {
    int bid = blockIdx.x;
    int tid = threadIdx.x;
    if (bid < 64) {
        int kv = tid >> 7;
        int d = tid & 127;
        size_t o = ((size_t)kv*64 + bid)*Dc + d;
        float s1 = g_s1[o], s2 = g_s2[o];
        float mu = s1 * (1.f/Tc);
        float var = (s2 - (float)Tc*mu*mu) * (1.f/(Tc-1));
        var = fmaxf(var, 0.f);
        float sd = sqrtf(var) + 1e-9f;
        if (kv == 0) { g_muk[bid*Dc + d] = mu; g_sdk[bid*Dc + d] = sd; }
        else         { g_muv[bid*Dc + d] = mu; g_sdv[bid*Dc + d] = sd; }
    } else {
        for (int i = tid; i < Bc*Hc*Ec; i += 256)
            g_outs[i] = bproj[i & (Hc*Ec - 1)];
    }
}

// ---------------- stage 3a: attention + o1 (coalesced [d][t]) ----------------
__global__ __launch_bounds__(256) void k_attn(const float* __restrict__ q) {
    __shared__ float s_sc[TP];
    __shared__ float s_red[256];
    __shared__ float s_q[Dc];
    int tid = threadIdx.x;
    int bh = blockIdx.x;
    int h = bh & 7;
    const __nv_bfloat16* Khi = g_chi + (size_t)bh*DT;
    const __nv_bfloat16* Klo = g_clo + (size_t)bh*DT;
    const __nv_bfloat16* Vhi = g_chi + (size_t)(64 + bh)*DT;
    const __nv_bfloat16* Vlo = g_clo + (size_t)(64 + bh)*DT;
    if (tid < Dc) s_q[tid] = q[h*Dc + tid];
    __syncthreads();

    if (tid < 250) {
        float a0 = 0.f, a1 = 0.f, a2 = 0.f, a3 = 0.f;
#pragma unroll 4
        for (int d = 0; d < Dc; d++) {
            uint2 ph = *(const uint2*)(Khi + (size_t)d*TP + tid*4);
            uint2 pl = *(const uint2*)(Klo + (size_t)d*TP + tid*4);
            float qd = s_q[d];
            float4 kv4 = un4(ph, pl);
            a0 += qd*kv4.x; a1 += qd*kv4.y; a2 += qd*kv4.z; a3 += qd*kv4.w;
        }
        const float sc = 0.08838834764831845f;
        *(float4*)&s_sc[tid*4] = make_float4(a0*sc, a1*sc, a2*sc, a3*sc);
    }
    if (tid < 24) s_sc[1000 + tid] = 0.f;
    __syncthreads();

    float lm = -1e30f;
    for (int t = tid; t < Tc; t += 256) lm = fmaxf(lm, s_sc[t]);
    s_red[tid] = lm; __syncthreads();
    for (int s = 128; s; s >>= 1) { if (tid < s) s_red[tid] = fmaxf(s_red[tid], s_red[tid+s]); __syncthreads(); }
    float m = s_red[0];
    __syncthreads();
    float ls = 0.f;
    for (int t = tid; t < Tc; t += 256) { float e = expf(s_sc[t]-m); s_sc[t] = e; ls += e; }
    s_red[tid] = ls; __syncthreads();
    for (int s = 128; s; s >>= 1) { if (tid < s) s_red[tid] += s_red[tid+s]; __syncthreads(); }
    float inv = 1.f / s_red[0];
    __syncthreads();

    int w = tid >> 5, lane = tid & 31;
#pragma unroll 1
    for (int rr = 0; rr < 16; rr++) {
        int d = w*16 + rr;
        float acc = 0.f;
#pragma unroll
        for (int cc = 0; cc < 8; cc++) {
            int grp = lane + cc*32;
            uint2 ph = *(const uint2*)(Vhi + (size_t)d*TP + grp*4);
            uint2 pl = *(const uint2*)(Vlo + (size_t)d*TP + grp*4);
            float4 vv = un4(ph, pl);
            float4 aa = *(float4*)&s_sc[grp*4];
            acc += aa.x*vv.x + aa.y*vv.y + aa.z*vv.z + aa.w*vv.w;
        }
        for (int off = 16; off; off >>= 1) acc += __shfl_down_sync(~0u, acc, off);
        if (lane == 0) g_o1[bh*Dc + d] = acc * inv;
    }
}

// ---------------- stage 3b: S = K^T V via tensor cores on [d][t] planes ----------------
#define NCHS 16

__device__ __forceinline__ void prefetch_smat(
    int c, int stage, uint32_t sb, int tid,
    const __nv_bfloat16* __restrict__ Ahi, const __nv_bfloat16* __restrict__ Alo,
    const __nv_bfloat16* __restrict__ Bhi, const __nv_bfloat16* __restrict__ Blo) {
    int kc = c*32;
    uint32_t stb = sb + stage*STAGE_B;
#pragma unroll
    for (int it = 0; it < 8; it++) {
        int idx = tid + it*256;
        int plane = idx >> 9;
        int row = (idx >> 2) & 127;
        int seg = idx & 3;
        uint32_t dst = stb + plane*PLANE_B + row*RS + seg*16;
        const __nv_bfloat16* src =
            (plane == 0 ? Ahi : plane == 1 ? Alo : plane == 2 ? Bhi : Blo)
            + (size_t)row*TP + kc + seg*8;
        asm volatile("cp.async.cg.shared.global [%0], [%1], 16;" :: "r"(dst), "l"(src));
    }
    CP_COMMIT();
}

__global__ __launch_bounds__(256, 2) void k_smat() {
    extern __shared__ __align__(1024) char dynsmem[];
    uint32_t sb = smem_u32(dynsmem);
    int tid = threadIdx.x;
    int warp = tid >> 5, lane = tid & 31;
    int bh = blockIdx.y;
    int seg = blockIdx.x;
    const __nv_bfloat16* Ahi = g_chi + (size_t)bh*DT + seg*512;
    const __nv_bfloat16* Alo = g_clo + (size_t)bh*DT + seg*512;
    const __nv_bfloat16* Bhi = g_chi + (size_t)(64 + bh)*DT + seg*512;
    const __nv_bfloat16* Blo = g_clo + (size_t)(64 + bh)*DT + seg*512;

    int m0w = (warp >> 1)*32;
    int n0w = (warp & 1)*64;
    int arow = (lane & 7) + ((lane >> 3) & 1)*8;
    int akb  = ((lane >> 4) & 1)*16;
    int brow = (lane & 7) + ((lane >> 4) & 1)*8;
    int bkb  = ((lane >> 3) & 1)*16;

    float acc[2][8][4];
#pragma unroll
    for (int i = 0; i < 2; i++)
#pragma unroll
        for (int j = 0; j < 8; j++)
#pragma unroll
            for (int r = 0; r < 4; r++) acc[i][j][r] = 0.f;

    prefetch_smat(0, 0, sb, tid, Ahi, Alo, Bhi, Blo);
    prefetch_smat(1, 1, sb, tid, Ahi, Alo, Bhi, Blo);

#pragma unroll 1
    for (int c = 0; c < NCHS; c++) {
        if (c < NCHS-1) CP_WAIT(1); else CP_WAIT(0);
        __syncthreads();
        uint32_t st = sb + (c & 1)*STAGE_B;
#pragma unroll
        for (int ks = 0; ks < 2; ks++) {
            unsigned ah[2][4], al[2][4];
#pragma unroll
            for (int mi = 0; mi < 2; mi++) {
                uint32_t a0 = st + (uint32_t)((m0w + mi*16 + arow)*RS + ks*32 + akb);
                LDSM4(ah[mi][0], ah[mi][1], ah[mi][2], ah[mi][3], a0);
                LDSM4(al[mi][0], al[mi][1], al[mi][2], al[mi][3], a0 + PLANE_B);
            }
#pragma unroll
            for (int ni = 0; ni < 4; ni++) {
                uint32_t b0 = st + 2*PLANE_B + (uint32_t)((n0w + ni*16 + brow)*RS + ks*32 + bkb);
                unsigned bhv[4], blv[4];
                LDSM4(bhv[0], bhv[1], bhv[2], bhv[3], b0);
                LDSM4(blv[0], blv[1], blv[2], blv[3], b0 + PLANE_B);
#pragma unroll
                for (int mi = 0; mi < 2; mi++)
#pragma unroll
                    for (int j2 = 0; j2 < 2; j2++) {
                        int nj = ni*2 + j2;
                        MMA_BF16(acc[mi][nj], ah[mi], &bhv[j2*2]);
                        MMA_BF16(acc[mi][nj], ah[mi], &blv[j2*2]);
                        MMA_BF16(acc[mi][nj], al[mi], &bhv[j2*2]);
                    }
            }
        }
        __syncthreads();
        if (c + 2 < NCHS)
            prefetch_smat(c+2, c & 1, sb, tid, Ahi, Alo, Bhi, Blo);
    }

    float* Sp = g_S + (size_t)bh*Dc*Dc;
    int g = lane >> 2, q = lane & 3;
#pragma unroll
    for (int nj = 0; nj < 8; nj++) {
        int l = n0w + nj*8 + q*2;
#pragma unroll
        for (int mi = 0; mi < 2; mi++) {
            int k0 = m0w + mi*16 + g;
            atomicAdd(&Sp[k0*Dc + l],       acc[mi][nj][0]);
            atomicAdd(&Sp[k0*Dc + l + 1],   acc[mi][nj][1]);
            atomicAdd(&Sp[(k0+8)*Dc + l],   acc[mi][nj][2]);
            atomicAdd(&Sp[(k0+8)*Dc + l+1], acc[mi][nj][3]);
        }
    }
}

// ---------------- stage 3c: normalized correlation ----------------
__global__ void k_corr() {
    int c = blockIdx.x*256 + threadIdx.x;
    int bh = blockIdx.y;
    if (c >= DCORR) return;
    float disc = 65025.0f - 8.0f*(float)c;
    int k = (int)((255.0f - sqrtf(disc))*0.5f);
    if (k < 0) k = 0;
    if (k > 126) k = 126;
    while (k > 0 && k*(255-k)/2 > c) k--;
    while ((k+1)*(254-k)/2 <= c) k++;
    int l = k + 1 + (c - k*(255-k)/2);
    float muk = g_muk[bh*Dc + k], sdk = g_sdk[bh*Dc + k];
    float muv = g_muv[bh*Dc + l], sdv = g_sdv[bh*Dc + l];
    float S = g_S[(size_t)bh*Dc*Dc + k*Dc + l];
    g_corr[(size_t)bh*DCORR + c] = (S - (float)Tc*muk*muv) / ((float)Tc*sdk*sdv);
}

// ---------------- stage 4: outs += corr . Wproj ----------------
__global__ __launch_bounds__(256) void k_proj(const float* __restrict__ Wproj) {
    __shared__ float sc[8][128];
    int tid = threadIdx.x;
    int h = blockIdx.y;
    int cs = blockIdx.z;
    int el = tid & 31;
    int b = tid >> 5;
    int e = blockIdx.x*32 + el;
    int lrow = tid >> 5;
    int lc = (tid & 31)*4;
    int start = cs*2032, end = start + 2032;
    const float* wrow = Wproj + ((size_t)h*Ec + e)*DCORR;
    float acc = 0.f;
    for (int c0 = start; c0 < end; c0 += 128) {
        int lim = end - c0; if (lim > 128) lim = 128;
        float4 cv = make_float4(0.f,0.f,0.f,0.f);
        if (lc < lim) cv = *(const float4*)(g_corr + ((size_t)lrow*Hc + h)*DCORR + c0 + lc);
        *(float4*)&sc[lrow][lc] = cv;
        __syncthreads();
#pragma unroll 8
        for (int j = 0; j < lim; j += 4) {
            float4 wv = *(const float4*)(wrow + c0 + j);
            float4 sv = *(const float4*)&sc[b][j];
            acc += wv.x*sv.x + wv.y*sv.y + wv.z*sv.z + wv.w*sv.w;
        }
        __syncthreads();
    }
    atomicAdd(&g_outs[b*(Hc*Ec) + h*Ec + e], acc);
}

// ---------------- stage 5: final linears + mix ----------------
__global__ __launch_bounds__(256) void k_final(
    const float* __restrict__ WT, const float* __restrict__ bT,
    const float* __restrict__ Wp, const float* __restrict__ bp,
    float* __restrict__ out) {
    __shared__ float so1[Hc*Dc];
    __shared__ float sout[Hc*Ec];
    __shared__ float sred[256];
    int b = blockIdx.x, ec = blockIdx.y;
    int tid = threadIdx.x;
    for (int j = tid; j < Hc*Dc; j += 256) so1[j]  = g_o1[b*Hc*Dc + j];
    for (int j = tid; j < Hc*Ec; j += 256) sout[j] = g_outs[b*Hc*Ec + j];
    __syncthreads();
    int e_l = tid >> 3, js = tid & 7;
    int e = ec*32 + e_l;
    float a = 0.f;
    const float* wt = WT + (size_t)e*(Hc*Dc) + js*128;
    const float* s1p = so1 + js*128;
#pragma unroll 4
    for (int j = 0; j < 128; j += 4) {
        float4 wv = *(const float4*)(wt + j);
        float4 sv = *(const float4*)(s1p + j);
        a += wv.x*sv.x + wv.y*sv.y + wv.z*sv.z + wv.w*sv.w;
    }
    const float* wp = Wp + (size_t)e*(Hc*Ec) + js*256;
    const float* s2p = sout + js*256;
#pragma unroll 4
    for (int j = 0; j < 256; j += 4) {
        float4 wv = *(const float4*)(wp + j);
        float4 sv = *(const float4*)(s2p + j);
        a += wv.x*sv.x + wv.y*sv.y + wv.z*sv.z + wv.w*sv.w;
    }
    if (js == 0) a += bT[e] + bp[e];
    sred[tid] = a;
    __syncthreads();
    if (tid < 32) {
        float s = 0.f;
#pragma unroll
        for (int k = 0; k < 8; k++) s += sred[tid*8 + k];
        out[b*Ec + ec*32 + tid] = 0.5f*s;
    }
}

// ---------------- launch ----------------
extern "C" void kernel_launch(void* const* d_in, const int* in_sizes, int n_in,
                              void* d_out, int out_size) {
    const float* x     = (const float*)d_in[0];
    const float* wk    = (const float*)d_in[1];
    const float* wv    = (const float*)d_in[2];
    const float* q     = (const float*)d_in[3];
    const float* Wk    = (const float*)d_in[4];
    const float* bk    = (const float*)d_in[5];
    const float* Wv    = (const float*)d_in[6];
    const float* bv    = (const float*)d_in[7];
    const float* Wproj = (const float*)d_in[8];
    const float* bproj = (const float*)d_in[9];
    const float* WT    = (const float*)d_in[10];
    const float* bT    = (const float*)d_in[11];
    const float* Wp    = (const float*)d_in[12];
    const float* bp    = (const float*)d_in[13];
    float* out = (float*)d_out;

    cudaFuncSetAttribute(k_gemm, cudaFuncAttributeMaxDynamicSharedMemorySize, GSMEM);
    cudaFuncSetAttribute(k_smat, cudaFuncAttributeMaxDynamicSharedMemorySize, GSMEM);

    k_softmaxw<<<1, 32>>>(wk, wv);
    k_zero<<<1056, 256>>>();
    k_wconv<<<dim3((Hc*Dc*Fc)/256, 2), 256>>>(Wk, Wv);
    k_raw<<<dim3((Tc+15)/16, Fc/16, Bc), dim3(16, 8)>>>(x);   // 4th launch -> ncu
    k_gemm<<<dim3(8, Bc*Hc, 2), 256, GSMEM>>>(bk, bv);
    k_statfin<<<65, 256>>>(bproj);
    k_attn<<<Bc*Hc, 256>>>(q);
    k_smat<<<dim3(2, Bc*Hc), 256, GSMEM>>>();
    k_corr<<<dim3((DCORR+255)/256, Bc*Hc), 256>>>();
    k_proj<<<dim3(Ec/32, Hc, 4), 256>>>(Wproj);
    k_final<<<dim3(Bc, Ec/32), 256>>>(WT, bT, Wp, bp, out);
}

// round 8
// speedup vs baseline: 2.2963x; 1.1198x over previous
#include <cuda_runtime.h>
#include <cuda_bf16.h>
#include <math.h>
#include <stdint.h>

// Problem constants
#define Bc 8
#define Hc 8
#define Fc 768
#define Dc 128
#define Ec 256
#define Lc 13
#define Tc 1000
#define DCORR 8128
#define TP 1024                 // padded T
#define DT (128*TP)             // plane size per (kv,bh)

// ---------------- device scratch ----------------
__device__ float g_kw[Hc*Lc];
__device__ float g_vw[Hc*Lc];
__device__ __nv_bfloat16 g_ahi[(size_t)2*Bc*Hc*Tc*Fc];   // raw activations [kv][bh][t][f]
__device__ __nv_bfloat16 g_alo[(size_t)2*Bc*Hc*Tc*Fc];
__device__ __nv_bfloat16 g_whi[(size_t)2*Hc*Dc*Fc];      // weights [kv][h][d][f]
__device__ __nv_bfloat16 g_wlo[(size_t)2*Hc*Dc*Fc];
__device__ __nv_bfloat16 g_chi[(size_t)2*Bc*Hc*DT];      // GEMM out planes [kv][bh][d][t]
__device__ __nv_bfloat16 g_clo[(size_t)2*Bc*Hc*DT];
__device__ float g_s1[2*Bc*Hc*Dc];
__device__ float g_s2[2*Bc*Hc*Dc];
__device__ float g_muk[Bc*Hc*Dc];
__device__ float g_sdk[Bc*Hc*Dc];
__device__ float g_muv[Bc*Hc*Dc];
__device__ float g_sdv[Bc*Hc*Dc];
__device__ float g_o1[Bc*Hc*Dc];
__device__ float g_S[(size_t)Bc*Hc*Dc*Dc];
__device__ float g_corr[(size_t)Bc*Hc*DCORR];
__device__ float g_outs[Bc*Hc*Ec];

__device__ __forceinline__ uint32_t smem_u32(const void* p) {
    uint32_t a;
    asm("{ .reg .u64 t; cvta.to.shared.u64 t, %1; cvt.u32.u64 %0, t; }" : "=r"(a) : "l"(p));
    return a;
}
#define CP_COMMIT()  asm volatile("cp.async.commit_group;" ::: "memory")
#define CP_WAIT(n)   asm volatile("cp.async.wait_group %0;" :: "n"(n) : "memory")
#define LDSM4(r0, r1, r2, r3, a) \
    asm volatile("ldmatrix.sync.aligned.m8n8.x4.shared.b16 {%0,%1,%2,%3}, [%4];" \
        : "=r"(r0), "=r"(r1), "=r"(r2), "=r"(r3) : "r"(a))
#define MMA_BF16(d, a, b) asm volatile( \
    "mma.sync.aligned.m16n8k16.row.col.f32.bf16.bf16.f32 " \
    "{%0,%1,%2,%3},{%4,%5,%6,%7},{%8,%9},{%0,%1,%2,%3};\n" \
    : "+f"((d)[0]), "+f"((d)[1]), "+f"((d)[2]), "+f"((d)[3]) \
    : "r"((a)[0]), "r"((a)[1]), "r"((a)[2]), "r"((a)[3]), "r"((b)[0]), "r"((b)[1]))

// hi+lo bf16 reconstruction of 4 packed values
__device__ __forceinline__ float4 un4(uint2 h, uint2 l) {
    float4 r;
    r.x = __int_as_float(h.x << 16)        + __int_as_float(l.x << 16);
    r.y = __int_as_float(h.x & 0xffff0000u) + __int_as_float(l.x & 0xffff0000u);
    r.z = __int_as_float(h.y << 16)        + __int_as_float(l.y << 16);
    r.w = __int_as_float(h.y & 0xffff0000u) + __int_as_float(l.y & 0xffff0000u);
    return r;
}

// ---------------- stage 0: softmax of mixing weights ----------------
__global__ void k_softmaxw(const float* __restrict__ wk, const float* __restrict__ wv) {
    int tid = threadIdx.x;
    if (tid >= 2*Hc) return;
    int h = tid % Hc;
    const float* src = (tid < Hc ? wk : wv) + h*Lc;
    float* dst = (tid < Hc ? g_kw : g_vw) + h*Lc;
    float m = -1e30f;
    for (int l = 0; l < Lc; l++) m = fmaxf(m, src[l]);
    float e[Lc]; float s = 0.f;
    for (int l = 0; l < Lc; l++) { e[l] = expf(src[l]-m); s += e[l]; }
    float inv = 1.f/s;
    for (int l = 0; l < Lc; l++) dst[l] = e[l]*inv;
}

// ---------------- zero S + stats ----------------
__global__ void k_zero() {
    int i = blockIdx.x*blockDim.x + threadIdx.x;
    float4 z = make_float4(0.f,0.f,0.f,0.f);
    if (i < 262144) { ((float4*)g_S)[i] = z; return; }
    int j = i - 262144;
    if (j < 4096) { ((float4*)g_s1)[j] = z; return; }
    ((float4*)g_s2)[j - 4096] = z;
}

// ---------------- pack W to bf16 hi/lo ----------------
__global__ void k_wconv(const float* __restrict__ Wk, const float* __restrict__ Wv) {
    size_t i = (size_t)blockIdx.x*256 + threadIdx.x;
    const float* W = blockIdx.y ? Wv : Wk;
    float v = W[i];
    __nv_bfloat16 h16 = __float2bfloat16(v);
    __nv_bfloat16 l16 = __float2bfloat16(v - __bfloat162float(h16));
    size_t o = (size_t)blockIdx.y*(Hc*Dc*Fc) + i;
    g_whi[o] = h16;
    g_wlo[o] = l16;
}

// ---------------- stage 1: L-contraction -> bf16 hi/lo [t][f] ----------------
// block (16 t, 8 f-pairs) = 128 threads; 4 t-subtiles per block, cp.async double buffer.
__shared__ float xs_g_dummy;  // (placeholder comment anchor)

__global__ __launch_bounds__(128) void k_raw(const float* __restrict__ x) {
    __shared__ float2 skv[Hc*Lc];                 // (kw, vw)
    __shared__ float xs[2][16][212];              // [buf][f][t*13+l]
    __shared__ unsigned s_ohi[2][Hc][16][9];      // [kv][h][t][fword]
    __shared__ unsigned s_olo[2][Hc][16][9];
    int tx = threadIdx.x;      // t
    int ty = threadIdx.y;      // f-pair
    int tid = ty*16 + tx;
    if (tid < Hc*Lc) skv[tid] = make_float2(g_kw[tid], g_vw[tid]);

    int tbase = blockIdx.x*64;
    int f0 = blockIdx.y*16;
    int b  = blockIdx.z;
    const float* xb = x + (size_t)(b*Fc + f0)*Tc*13;

    // cp.async staging of one 16t x 16f subtile into xs[buf]
    auto stage_x = [&](int buf, int st0) {
        int n = Tc - st0;
        int maxf4 = (n >= 16) ? 52 : (n > 0 ? ((n*13) >> 2) : 0);
#pragma unroll
        for (int it = 0; it < 7; it++) {
            int idx = tid + it*128;
            if (idx < 832) {
                int row = idx / 52, col = idx % 52;
                unsigned sz = (col < maxf4) ? 16u : 0u;
                int scol = (col < maxf4) ? col : 0;
                uint32_t dst = smem_u32(&xs[buf][row][col*4]);
                const float* src = xb + (size_t)row*(Tc*13) + st0*13 + scol*4;
                asm volatile("cp.async.cg.shared.global [%0], [%1], 16, %2;"
                             :: "r"(dst), "l"(src), "r"(sz));
            }
        }
        CP_COMMIT();
    };

    stage_x(0, tbase);

#pragma unroll 1
    for (int s = 0; s < 4; s++) {
        int st0 = tbase + s*16;
        if (s < 3) { stage_x((s+1) & 1, st0 + 16); CP_WAIT(1); }
        else CP_WAIT(0);
        __syncthreads();

        int buf = s & 1;
        float xv0[Lc], xv1[Lc];
#pragma unroll
        for (int l = 0; l < Lc; l++) {
            xv0[l] = xs[buf][ty*2][tx*13 + l];
            xv1[l] = xs[buf][ty*2 + 1][tx*13 + l];
        }

#pragma unroll
        for (int h = 0; h < Hc; h++) {
            float k0 = 0.f, v0 = 0.f, k1 = 0.f, v1 = 0.f;
#pragma unroll
            for (int l = 0; l < Lc; l++) {
                float2 w = skv[h*Lc + l];
                k0 += xv0[l]*w.x; v0 += xv0[l]*w.y;
                k1 += xv1[l]*w.x; v1 += xv1[l]*w.y;
            }
            {
                unsigned b0 = __float_as_uint(k0), b1 = __float_as_uint(k1);
                unsigned hiw = __byte_perm(b0, b1, 0x7632);
                float d0 = k0 - __uint_as_float(b0 & 0xffff0000u);
                float d1 = k1 - __uint_as_float(b1 & 0xffff0000u);
                unsigned low;
                asm("cvt.rn.bf16x2.f32 %0, %1, %2;" : "=r"(low) : "f"(d1), "f"(d0));
                s_ohi[0][h][tx][ty] = hiw;
                s_olo[0][h][tx][ty] = low;
            }
            {
                unsigned b0 = __float_as_uint(v0), b1 = __float_as_uint(v1);
                unsigned hiw = __byte_perm(b0, b1, 0x7632);
                float d0 = v0 - __uint_as_float(b0 & 0xffff0000u);
                float d1 = v1 - __uint_as_float(b1 & 0xffff0000u);
                unsigned low;
                asm("cvt.rn.bf16x2.f32 %0, %1, %2;" : "=r"(low) : "f"(d1), "f"(d0));
                s_ohi[1][h][tx][ty] = hiw;
                s_olo[1][h][tx][ty] = low;
            }
        }
        __syncthreads();

        // write phase: 16 jobs (kv,h) over 4 warps
        int w = tid >> 5, lane = tid & 31;
        int f2 = lane & 7;
        int tq = lane >> 3;
#pragma unroll
        for (int it = 0; it < 4; it++) {
            int job = w*4 + it;
            int kv = job >> 3;
            int h = job & 7;
            size_t rowbase = ((size_t)(kv*Bc + b)*Hc + h)*Tc;
#pragma unroll
            for (int ti = 0; ti < 4; ti++) {
                int tl = ti*4 + tq;
                int tt = st0 + tl;
                if (tt < Tc) {
                    size_t off = (rowbase + tt)*Fc + f0 + f2*2;
                    *(unsigned*)(g_ahi + off) = s_ohi[kv][h][tl][f2];
                    *(unsigned*)(g_alo + off) = s_olo[kv][h][tl][f2];
                }
            }
        }
        __syncthreads();
    }
}

// ---------------- stage 2: mma.sync GEMM -> [d][t] bf16 planes + stats ----------------
#define RS 80
#define PLANE_B (128*RS)
#define STAGE_B (4*PLANE_B)
#define NSTAGE 2
#define GSMEM (NSTAGE*STAGE_B)   // 81920
#define NCH (Fc/32)

__device__ __forceinline__ void prefetch_chunk(
    int c, int stage, uint32_t sb, int t0, int tid,
    const __nv_bfloat16* __restrict__ Ahi, const __nv_bfloat16* __restrict__ Alo,
    const __nv_bfloat16* __restrict__ Bhi, const __nv_bfloat16* __restrict__ Blo) {
    int kc = c*32;
    uint32_t stb = sb + stage*STAGE_B;
#pragma unroll
    for (int it = 0; it < 8; it++) {
        int idx = tid + it*256;
        int plane = idx >> 9;
        int row = (idx >> 2) & 127;
        int seg = idx & 3;
        uint32_t dst = stb + plane*PLANE_B + row*RS + seg*16;
        const __nv_bfloat16* src;
        unsigned sz = 16;
        if (plane < 2) {
            int t = t0 + row;
            if (t >= Tc) { t = 0; sz = 0; }
            src = (plane ? Alo : Ahi) + (size_t)t*Fc + kc + seg*8;
        } else {
            src = (plane == 2 ? Bhi : Blo) + (size_t)row*Fc + kc + seg*8;
        }
        asm volatile("cp.async.cg.shared.global [%0], [%1], 16, %2;"
                     :: "r"(dst), "l"(src), "r"(sz));
    }
    CP_COMMIT();
}

__global__ __launch_bounds__(256, 2) void k_gemm(
    const float* __restrict__ bk, const float* __restrict__ bv) {
    extern __shared__ __align__(1024) char dynsmem[];
    uint32_t sb = smem_u32(dynsmem);

    int tid = threadIdx.x;
    int warp = tid >> 5, lane = tid & 31;
    int bh = blockIdx.y;
    int h = bh & 7;
    int kv = blockIdx.z;
    int t0 = blockIdx.x*128;

    const __nv_bfloat16* Ahi = g_ahi + (size_t)(kv*Bc*Hc + bh)*Tc*Fc;
    const __nv_bfloat16* Alo = g_alo + (size_t)(kv*Bc*Hc + bh)*Tc*Fc;
    const __nv_bfloat16* Bhi = g_whi + (size_t)(kv*Hc + h)*Dc*Fc;
    const __nv_bfloat16* Blo = g_wlo + (size_t)(kv*Hc + h)*Dc*Fc;
    const float* bias = (kv ? bv : bk) + h*Dc;

    int m0w = (warp >> 1)*32;
    int n0w = (warp & 1)*64;
    int arow = (lane & 7) + ((lane >> 3) & 1)*8;
    int akb  = ((lane >> 4) & 1)*16;
    int brow = (lane & 7) + ((lane >> 4) & 1)*8;
    int bkb  = ((lane >> 3) & 1)*16;

    float acc[2][8][4];
#pragma unroll
    for (int i = 0; i < 2; i++)
#pragma unroll
        for (int j = 0; j < 8; j++)
#pragma unroll
            for (int r = 0; r < 4; r++) acc[i][j][r] = 0.f;

    prefetch_chunk(0, 0, sb, t0, tid, Ahi, Alo, Bhi, Blo);
    prefetch_chunk(1, 1, sb, t0, tid, Ahi, Alo, Bhi, Blo);

#pragma unroll 1
    for (int c = 0; c < NCH; c++) {
        if (c < NCH-1) CP_WAIT(1); else CP_WAIT(0);
        __syncthreads();
        uint32_t st = sb + (c & 1)*STAGE_B;
#pragma unroll
        for (int ks = 0; ks < 2; ks++) {
            unsigned ah[2][4], al[2][4];
#pragma unroll
            for (int mi = 0; mi < 2; mi++) {
                uint32_t a0 = st + (uint32_t)((m0w + mi*16 + arow)*RS + ks*32 + akb);
                LDSM4(ah[mi][0], ah[mi][1], ah[mi][2], ah[mi][3], a0);
                LDSM4(al[mi][0], al[mi][1], al[mi][2], al[mi][3], a0 + PLANE_B);
            }
#pragma unroll
            for (int ni = 0; ni < 4; ni++) {
                uint32_t b0 = st + 2*PLANE_B + (uint32_t)((n0w + ni*16 + brow)*RS + ks*32 + bkb);
                unsigned bhv[4], blv[4];
                LDSM4(bhv[0], bhv[1], bhv[2], bhv[3], b0);
                LDSM4(blv[0], blv[1], blv[2], blv[3], b0 + PLANE_B);
#pragma unroll
                for (int mi = 0; mi < 2; mi++)
#pragma unroll
                    for (int j2 = 0; j2 < 2; j2++) {
                        int nj = ni*2 + j2;
                        MMA_BF16(acc[mi][nj], ah[mi], &bhv[j2*2]);
                        MMA_BF16(acc[mi][nj], ah[mi], &blv[j2*2]);
                        MMA_BF16(acc[mi][nj], al[mi], &bhv[j2*2]);
                    }
            }
        }
        __syncthreads();
        if (c + 2 < NCH)
            prefetch_chunk(c+2, c & 1, sb, t0, tid, Ahi, Alo, Bhi, Blo);
    }

    // epilogue: transpose through smem to [d][t], emit bf16 hi/lo planes + stats
    __syncthreads();
    float* Cs = (float*)dynsmem;           // [128 d][132]
    int g = lane >> 2, q = lane & 3;
#pragma unroll
    for (int nj = 0; nj < 8; nj++) {
        int d = n0w + nj*8 + q*2;
        float2 bb = *(const float2*)(bias + d);
#pragma unroll
        for (int mi = 0; mi < 2; mi++) {
            int r = m0w + mi*16 + g;
            Cs[d*132 + r]         = acc[mi][nj][0] + bb.x;
            Cs[(d+1)*132 + r]     = acc[mi][nj][1] + bb.y;
            Cs[d*132 + r + 8]     = acc[mi][nj][2] + bb.x;
            Cs[(d+1)*132 + r + 8] = acc[mi][nj][3] + bb.y;
        }
    }
    __syncthreads();

    __nv_bfloat16* Phi = g_chi + ((size_t)kv*64 + bh)*DT;
    __nv_bfloat16* Plo = g_clo + ((size_t)kv*64 + bh)*DT;
    size_t so = ((size_t)kv*64 + bh)*Dc;
    int tb = t0 + lane*4;
#pragma unroll 1
    for (int rr = 0; rr < 16; rr++) {
        int d = warp*16 + rr;
        float4 v = *(float4*)&Cs[d*132 + lane*4];
        v.x = (tb+0 < Tc) ? v.x : 0.f;
        v.y = (tb+1 < Tc) ? v.y : 0.f;
        v.z = (tb+2 < Tc) ? v.z : 0.f;
        v.w = (tb+3 < Tc) ? v.w : 0.f;
        __nv_bfloat162 h01 = __floats2bfloat162_rn(v.x, v.y);
        __nv_bfloat162 h23 = __floats2bfloat162_rn(v.z, v.w);
        unsigned uh01 = *(unsigned*)&h01, uh23 = *(unsigned*)&h23;
        float f0 = __int_as_float(uh01 << 16);
        float f1 = __int_as_float(uh01 & 0xffff0000u);
        float f2 = __int_as_float(uh23 << 16);
        float f3 = __int_as_float(uh23 & 0xffff0000u);
        __nv_bfloat162 l01 = __floats2bfloat162_rn(v.x - f0, v.y - f1);
        __nv_bfloat162 l23 = __floats2bfloat162_rn(v.z - f2, v.w - f3);
        *(uint2*)(Phi + (size_t)d*TP + tb) = make_uint2(uh01, uh23);
        *(uint2*)(Plo + (size_t)d*TP + tb) = make_uint2(*(unsigned*)&l01, *(unsigned*)&l23);
        float p1 = v.x + v.y + v.z + v.w;
        float p2 = v.x*v.x + v.y*v.y + v.z*v.z + v.w*v.w;
        for (int off = 16; off; off >>= 1) {
            p1 += __shfl_down_sync(~0u, p1, off);
            p2 += __shfl_down_sync(~0u, p2, off);
        }
        if (lane == 0) {
            atomicAdd(&g_s1[so + d], p1);
            atomicAdd(&g_s2[so + d], p2);
        }
    }
}

// ---------------- stats finalize + outs init ----------------
__global__ void k_statfin(const float* __restrict__ bproj) {
    int bid = blockIdx.x;
    int tid = threadIdx.x;
    if (bid < 64) {
        int kv = tid >> 7;
        int d = tid & 127;
        size_t o = ((size_t)kv*64 + bid)*Dc + d;
        float s1 = g_s1[o], s2 = g_s2[o];
        float mu = s1 * (1.f/Tc);
        float var = (s2 - (float)Tc*mu*mu) * (1.f/(Tc-1));
        var = fmaxf(var, 0.f);
        float sd = sqrtf(var) + 1e-9f;
        if (kv == 0) { g_muk[bid*Dc + d] = mu; g_sdk[bid*Dc + d] = sd; }
        else         { g_muv[bid*Dc + d] = mu; g_sdv[bid*Dc + d] = sd; }
    } else {
        for (int i = tid; i < Bc*Hc*Ec; i += 256)
            g_outs[i] = bproj[i & (Hc*Ec - 1)];
    }
}

// ---------------- stage 3a: attention + o1 (coalesced [d][t]) ----------------
__global__ __launch_bounds__(256) void k_attn(const float* __restrict__ q) {
    __shared__ float s_sc[TP];
    __shared__ float s_red[256];
    __shared__ float s_q[Dc];
    int tid = threadIdx.x;
    int bh = blockIdx.x;
    int h = bh & 7;
    const __nv_bfloat16* Khi = g_chi + (size_t)bh*DT;
    const __nv_bfloat16* Klo = g_clo + (size_t)bh*DT;
    const __nv_bfloat16* Vhi = g_chi + (size_t)(64 + bh)*DT;
    const __nv_bfloat16* Vlo = g_clo + (size_t)(64 + bh)*DT;
    if (tid < Dc) s_q[tid] = q[h*Dc + tid];
    __syncthreads();

    if (tid < 250) {
        float a0 = 0.f, a1 = 0.f, a2 = 0.f, a3 = 0.f;
#pragma unroll 4
        for (int d = 0; d < Dc; d++) {
            uint2 ph = *(const uint2*)(Khi + (size_t)d*TP + tid*4);
            uint2 pl = *(const uint2*)(Klo + (size_t)d*TP + tid*4);
            float qd = s_q[d];
            float4 kv4 = un4(ph, pl);
            a0 += qd*kv4.x; a1 += qd*kv4.y; a2 += qd*kv4.z; a3 += qd*kv4.w;
        }
        const float sc = 0.08838834764831845f;
        *(float4*)&s_sc[tid*4] = make_float4(a0*sc, a1*sc, a2*sc, a3*sc);
    }
    if (tid < 24) s_sc[1000 + tid] = 0.f;
    __syncthreads();

    float lm = -1e30f;
    for (int t = tid; t < Tc; t += 256) lm = fmaxf(lm, s_sc[t]);
    s_red[tid] = lm; __syncthreads();
    for (int s = 128; s; s >>= 1) { if (tid < s) s_red[tid] = fmaxf(s_red[tid], s_red[tid+s]); __syncthreads(); }
    float m = s_red[0];
    __syncthreads();
    float ls = 0.f;
    for (int t = tid; t < Tc; t += 256) { float e = expf(s_sc[t]-m); s_sc[t] = e; ls += e; }
    s_red[tid] = ls; __syncthreads();
    for (int s = 128; s; s >>= 1) { if (tid < s) s_red[tid] += s_red[tid+s]; __syncthreads(); }
    float inv = 1.f / s_red[0];
    __syncthreads();

    int w = tid >> 5, lane = tid & 31;
#pragma unroll 1
    for (int rr = 0; rr < 16; rr++) {
        int d = w*16 + rr;
        float acc = 0.f;
#pragma unroll
        for (int cc = 0; cc < 8; cc++) {
            int grp = lane + cc*32;
            uint2 ph = *(const uint2*)(Vhi + (size_t)d*TP + grp*4);
            uint2 pl = *(const uint2*)(Vlo + (size_t)d*TP + grp*4);
            float4 vv = un4(ph, pl);
            float4 aa = *(float4*)&s_sc[grp*4];
            acc += aa.x*vv.x + aa.y*vv.y + aa.z*vv.z + aa.w*vv.w;
        }
        for (int off = 16; off; off >>= 1) acc += __shfl_down_sync(~0u, acc, off);
        if (lane == 0) g_o1[bh*Dc + d] = acc * inv;
    }
}

// ---------------- stage 3b: S = K^T V via tensor cores on [d][t] planes ----------------
#define NCHS 16

__device__ __forceinline__ void prefetch_smat(
    int c, int stage, uint32_t sb, int tid,
    const __nv_bfloat16* __restrict__ Ahi, const __nv_bfloat16* __restrict__ Alo,
    const __nv_bfloat16* __restrict__ Bhi, const __nv_bfloat16* __restrict__ Blo) {
    int kc = c*32;
    uint32_t stb = sb + stage*STAGE_B;
#pragma unroll
    for (int it = 0; it < 8; it++) {
        int idx = tid + it*256;
        int plane = idx >> 9;
        int row = (idx >> 2) & 127;
        int seg = idx & 3;
        uint32_t dst = stb + plane*PLANE_B + row*RS + seg*16;
        const __nv_bfloat16* src =
            (plane == 0 ? Ahi : plane == 1 ? Alo : plane == 2 ? Bhi : Blo)
            + (size_t)row*TP + kc + seg*8;
        asm volatile("cp.async.cg.shared.global [%0], [%1], 16;" :: "r"(dst), "l"(src));
    }
    CP_COMMIT();
}

__global__ __launch_bounds__(256, 2) void k_smat() {
    extern __shared__ __align__(1024) char dynsmem[];
    uint32_t sb = smem_u32(dynsmem);
    int tid = threadIdx.x;
    int warp = tid >> 5, lane = tid & 31;
    int bh = blockIdx.y;
    int seg = blockIdx.x;
    const __nv_bfloat16* Ahi = g_chi + (size_t)bh*DT + seg*512;
    const __nv_bfloat16* Alo = g_clo + (size_t)bh*DT + seg*512;
    const __nv_bfloat16* Bhi = g_chi + (size_t)(64 + bh)*DT + seg*512;
    const __nv_bfloat16* Blo = g_clo + (size_t)(64 + bh)*DT + seg*512;

    int m0w = (warp >> 1)*32;
    int n0w = (warp & 1)*64;
    int arow = (lane & 7) + ((lane >> 3) & 1)*8;
    int akb  = ((lane >> 4) & 1)*16;
    int brow = (lane & 7) + ((lane >> 4) & 1)*8;
    int bkb  = ((lane >> 3) & 1)*16;

    float acc[2][8][4];
#pragma unroll
    for (int i = 0; i < 2; i++)
#pragma unroll
        for (int j = 0; j < 8; j++)
#pragma unroll
            for (int r = 0; r < 4; r++) acc[i][j][r] = 0.f;

    prefetch_smat(0, 0, sb, tid, Ahi, Alo, Bhi, Blo);
    prefetch_smat(1, 1, sb, tid, Ahi, Alo, Bhi, Blo);

#pragma unroll 1
    for (int c = 0; c < NCHS; c++) {
        if (c < NCHS-1) CP_WAIT(1); else CP_WAIT(0);
        __syncthreads();
        uint32_t st = sb + (c & 1)*STAGE_B;
#pragma unroll
        for (int ks = 0; ks < 2; ks++) {
            unsigned ah[2][4], al[2][4];
#pragma unroll
            for (int mi = 0; mi < 2; mi++) {
                uint32_t a0 = st + (uint32_t)((m0w + mi*16 + arow)*RS + ks*32 + akb);
                LDSM4(ah[mi][0], ah[mi][1], ah[mi][2], ah[mi][3], a0);
                LDSM4(al[mi][0], al[mi][1], al[mi][2], al[mi][3], a0 + PLANE_B);
            }
#pragma unroll
            for (int ni = 0; ni < 4; ni++) {
                uint32_t b0 = st + 2*PLANE_B + (uint32_t)((n0w + ni*16 + brow)*RS + ks*32 + bkb);
                unsigned bhv[4], blv[4];
                LDSM4(bhv[0], bhv[1], bhv[2], bhv[3], b0);
                LDSM4(blv[0], blv[1], blv[2], blv[3], b0 + PLANE_B);
#pragma unroll
                for (int mi = 0; mi < 2; mi++)
#pragma unroll
                    for (int j2 = 0; j2 < 2; j2++) {
                        int nj = ni*2 + j2;
                        MMA_BF16(acc[mi][nj], ah[mi], &bhv[j2*2]);
                        MMA_BF16(acc[mi][nj], ah[mi], &blv[j2*2]);
                        MMA_BF16(acc[mi][nj], al[mi], &bhv[j2*2]);
                    }
            }
        }
        __syncthreads();
        if (c + 2 < NCHS)
            prefetch_smat(c+2, c & 1, sb, tid, Ahi, Alo, Bhi, Blo);
    }

    float* Sp = g_S + (size_t)bh*Dc*Dc;
    int g = lane >> 2, q = lane & 3;
#pragma unroll
    for (int nj = 0; nj < 8; nj++) {
        int l = n0w + nj*8 + q*2;
#pragma unroll
        for (int mi = 0; mi < 2; mi++) {
            int k0 = m0w + mi*16 + g;
            atomicAdd(&Sp[k0*Dc + l],       acc[mi][nj][0]);
            atomicAdd(&Sp[k0*Dc + l + 1],   acc[mi][nj][1]);
            atomicAdd(&Sp[(k0+8)*Dc + l],   acc[mi][nj][2]);
            atomicAdd(&Sp[(k0+8)*Dc + l+1], acc[mi][nj][3]);
        }
    }
}

// ---------------- stage 3c: normalized correlation ----------------
__global__ void k_corr() {
    int c = blockIdx.x*256 + threadIdx.x;
    int bh = blockIdx.y;
    if (c >= DCORR) return;
    float disc = 65025.0f - 8.0f*(float)c;
    int k = (int)((255.0f - sqrtf(disc))*0.5f);
    if (k < 0) k = 0;
    if (k > 126) k = 126;
    while (k > 0 && k*(255-k)/2 > c) k--;
    while ((k+1)*(254-k)/2 <= c) k++;
    int l = k + 1 + (c - k*(255-k)/2);
    float muk = g_muk[bh*Dc + k], sdk = g_sdk[bh*Dc + k];
    float muv = g_muv[bh*Dc + l], sdv = g_sdv[bh*Dc + l];
    float S = g_S[(size_t)bh*Dc*Dc + k*Dc + l];
    g_corr[(size_t)bh*DCORR + c] = (S - (float)Tc*muk*muv) / ((float)Tc*sdk*sdv);
}

// ---------------- stage 4: outs += corr . Wproj ----------------
__global__ __launch_bounds__(256) void k_proj(const float* __restrict__ Wproj) {
    __shared__ float sc[8][128];
    int tid = threadIdx.x;
    int h = blockIdx.y;
    int cs = blockIdx.z;
    int el = tid & 31;
    int b = tid >> 5;
    int e = blockIdx.x*32 + el;
    int lrow = tid >> 5;
    int lc = (tid & 31)*4;
    int start = cs*2032, end = start + 2032;
    const float* wrow = Wproj + ((size_t)h*Ec + e)*DCORR;
    float acc = 0.f;
    for (int c0 = start; c0 < end; c0 += 128) {
        int lim = end - c0; if (lim > 128) lim = 128;
        float4 cv = make_float4(0.f,0.f,0.f,0.f);
        if (lc < lim) cv = *(const float4*)(g_corr + ((size_t)lrow*Hc + h)*DCORR + c0 + lc);
        *(float4*)&sc[lrow][lc] = cv;
        __syncthreads();
#pragma unroll 8
        for (int j = 0; j < lim; j += 4) {
            float4 wv = *(const float4*)(wrow + c0 + j);
            float4 sv = *(const float4*)&sc[b][j];
            acc += wv.x*sv.x + wv.y*sv.y + wv.z*sv.z + wv.w*sv.w;
        }
        __syncthreads();
    }
    atomicAdd(&g_outs[b*(Hc*Ec) + h*Ec + e], acc);
}

// ---------------- stage 5: final linears + mix ----------------
__global__ __launch_bounds__(256) void k_final(
    const float* __restrict__ WT, const float* __restrict__ bT,
    const float* __restrict__ Wp, const float* __restrict__ bp,
    float* __restrict__ out) {
    __shared__ float so1[Hc*Dc];
    __shared__ float sout[Hc*Ec];
    __shared__ float sred[256];
    int b = blockIdx.x, ec = blockIdx.y;
    int tid = threadIdx.x;
    for (int j = tid; j < Hc*Dc; j += 256) so1[j]  = g_o1[b*Hc*Dc + j];
    for (int j = tid; j < Hc*Ec; j += 256) sout[j] = g_outs[b*Hc*Ec + j];
    __syncthreads();
    int e_l = tid >> 3, js = tid & 7;
    int e = ec*32 + e_l;
    float a = 0.f;
    const float* wt = WT + (size_t)e*(Hc*Dc) + js*128;
    const float* s1p = so1 + js*128;
#pragma unroll 4
    for (int j = 0; j < 128; j += 4) {
        float4 wv = *(const float4*)(wt + j);
        float4 sv = *(const float4*)(s1p + j);
        a += wv.x*sv.x + wv.y*sv.y + wv.z*sv.z + wv.w*sv.w;
    }
    const float* wp = Wp + (size_t)e*(Hc*Ec) + js*256;
    const float* s2p = sout + js*256;
#pragma unroll 4
    for (int j = 0; j < 256; j += 4) {
        float4 wv = *(const float4*)(wp + j);
        float4 sv = *(const float4*)(s2p + j);
        a += wv.x*sv.x + wv.y*sv.y + wv.z*sv.z + wv.w*sv.w;
    }
    if (js == 0) a += bT[e] + bp[e];
    sred[tid] = a;
    __syncthreads();
    if (tid < 32) {
        float s = 0.f;
#pragma unroll
        for (int k = 0; k < 8; k++) s += sred[tid*8 + k];
        out[b*Ec + ec*32 + tid] = 0.5f*s;
    }
}

// ---------------- launch ----------------
extern "C" void kernel_launch(void* const* d_in, const int* in_sizes, int n_in,
                              void* d_out, int out_size) {
    const float* x     = (const float*)d_in[0];
    const float* wk    = (const float*)d_in[1];
    const float* wv    = (const float*)d_in[2];
    const float* q     = (const float*)d_in[3];
    const float* Wk    = (const float*)d_in[4];
    const float* bk    = (const float*)d_in[5];
    const float* Wv    = (const float*)d_in[6];
    const float* bv    = (const float*)d_in[7];
    const float* Wproj = (const float*)d_in[8];
    const float* bproj = (const float*)d_in[9];
    const float* WT    = (const float*)d_in[10];
    const float* bT    = (const float*)d_in[11];
    const float* Wp    = (const float*)d_in[12];
    const float* bp    = (const float*)d_in[13];
    float* out = (float*)d_out;

    cudaFuncSetAttribute(k_gemm, cudaFuncAttributeMaxDynamicSharedMemorySize, GSMEM);
    cudaFuncSetAttribute(k_smat, cudaFuncAttributeMaxDynamicSharedMemorySize, GSMEM);

    k_softmaxw<<<1, 32>>>(wk, wv);
    k_zero<<<1056, 256>>>();
    k_wconv<<<dim3((Hc*Dc*Fc)/256, 2), 256>>>(Wk, Wv);
    k_raw<<<dim3(16, Fc/16, Bc), dim3(16, 8)>>>(x);   // 4th launch -> ncu
    k_gemm<<<dim3(8, Bc*Hc, 2), 256, GSMEM>>>(bk, bv);
    k_statfin<<<65, 256>>>(bproj);
    k_attn<<<Bc*Hc, 256>>>(q);
    k_smat<<<dim3(2, Bc*Hc), 256, GSMEM>>>();
    k_corr<<<dim3((DCORR+255)/256, Bc*Hc), 256>>>();
    k_proj<<<dim3(Ec/32, Hc, 4), 256>>>(Wproj);
    k_final<<<dim3(Bc, Ec/32), 256>>>(WT, bT, Wp, bp, out);
}

// round 9
// speedup vs baseline: 2.3191x; 1.0099x over previous
#include <cuda_runtime.h>
#include <cuda_bf16.h>
#include <math.h>
#include <stdint.h>

// Problem constants
#define Bc 8
#define Hc 8
#define Fc 768
#define Dc 128
#define Ec 256
#define Lc 13
#define Tc 1000
#define DCORR 8128
#define TP 1024                 // padded T
#define DT (128*TP)             // plane size per (kv,bh)

// ---------------- device scratch ----------------
__device__ float g_kw[Hc*Lc];
__device__ float g_vw[Hc*Lc];
__device__ __nv_bfloat16 g_ahi[(size_t)2*Bc*Hc*Tc*Fc];   // raw activations [kv][bh][t][f]
__device__ __nv_bfloat16 g_alo[(size_t)2*Bc*Hc*Tc*Fc];
__device__ __nv_bfloat16 g_whi[(size_t)2*Hc*Dc*Fc];      // weights [kv][h][d][f]
__device__ __nv_bfloat16 g_wlo[(size_t)2*Hc*Dc*Fc];
__device__ __nv_bfloat16 g_chi[(size_t)2*Bc*Hc*DT];      // GEMM out planes [kv][bh][d][t]
__device__ __nv_bfloat16 g_clo[(size_t)2*Bc*Hc*DT];
__device__ float g_s1[2*Bc*Hc*Dc];
__device__ float g_s2[2*Bc*Hc*Dc];
__device__ float g_muk[Bc*Hc*Dc];
__device__ float g_sdk[Bc*Hc*Dc];
__device__ float g_muv[Bc*Hc*Dc];
__device__ float g_sdv[Bc*Hc*Dc];
__device__ float g_o1[Bc*Hc*Dc];
__device__ float g_S[(size_t)Bc*Hc*Dc*Dc];
__device__ float g_corr[(size_t)Bc*Hc*DCORR];
__device__ float g_outs[Bc*Hc*Ec];

__device__ __forceinline__ uint32_t smem_u32(const void* p) {
    uint32_t a;
    asm("{ .reg .u64 t; cvta.to.shared.u64 t, %1; cvt.u32.u64 %0, t; }" : "=r"(a) : "l"(p));
    return a;
}
#define CP_COMMIT()  asm volatile("cp.async.commit_group;" ::: "memory")
#define CP_WAIT(n)   asm volatile("cp.async.wait_group %0;" :: "n"(n) : "memory")
#define LDSM4(r0, r1, r2, r3, a) \
    asm volatile("ldmatrix.sync.aligned.m8n8.x4.shared.b16 {%0,%1,%2,%3}, [%4];" \
        : "=r"(r0), "=r"(r1), "=r"(r2), "=r"(r3) : "r"(a))
#define MMA_BF16(d, a, b) asm volatile( \
    "mma.sync.aligned.m16n8k16.row.col.f32.bf16.bf16.f32 " \
    "{%0,%1,%2,%3},{%4,%5,%6,%7},{%8,%9},{%0,%1,%2,%3};\n" \
    : "+f"((d)[0]), "+f"((d)[1]), "+f"((d)[2]), "+f"((d)[3]) \
    : "r"((a)[0]), "r"((a)[1]), "r"((a)[2]), "r"((a)[3]), "r"((b)[0]), "r"((b)[1]))

// hi+lo bf16 reconstruction of 4 packed values
__device__ __forceinline__ float4 un4(uint2 h, uint2 l) {
    float4 r;
    r.x = __int_as_float(h.x << 16)        + __int_as_float(l.x << 16);
    r.y = __int_as_float(h.x & 0xffff0000u) + __int_as_float(l.x & 0xffff0000u);
    r.z = __int_as_float(h.y << 16)        + __int_as_float(l.y << 16);
    r.w = __int_as_float(h.y & 0xffff0000u) + __int_as_float(l.y & 0xffff0000u);
    return r;
}

// ---------------- stage 0: init (zero accumulators + softmax weights) ----------------
// grid 1056 x 256: 262144 f4 -> g_S, 4096 -> g_s1, 4096 -> g_s2; block0 also softmax.
__global__ void k_init(const float* __restrict__ wk, const float* __restrict__ wv) {
    int i = blockIdx.x*blockDim.x + threadIdx.x;
    float4 z = make_float4(0.f,0.f,0.f,0.f);
    if (i < 262144) ((float4*)g_S)[i] = z;
    else {
        int j = i - 262144;
        if (j < 4096) ((float4*)g_s1)[j] = z;
        else ((float4*)g_s2)[j - 4096] = z;
    }
    if (blockIdx.x == 0 && threadIdx.x < 2*Hc) {
        int tid = threadIdx.x;
        int h = tid % Hc;
        const float* src = (tid < Hc ? wk : wv) + h*Lc;
        float* dst = (tid < Hc ? g_kw : g_vw) + h*Lc;
        float m = -1e30f;
        for (int l = 0; l < Lc; l++) m = fmaxf(m, src[l]);
        float e[Lc]; float s = 0.f;
        for (int l = 0; l < Lc; l++) { e[l] = expf(src[l]-m); s += e[l]; }
        float inv = 1.f/s;
        for (int l = 0; l < Lc; l++) dst[l] = e[l]*inv;
    }
}

// ---------------- pack W to bf16 hi/lo ----------------
__global__ void k_wconv(const float* __restrict__ Wk, const float* __restrict__ Wv) {
    size_t i = (size_t)blockIdx.x*256 + threadIdx.x;
    const float* W = blockIdx.y ? Wv : Wk;
    float v = W[i];
    __nv_bfloat16 h16 = __float2bfloat16(v);
    __nv_bfloat16 l16 = __float2bfloat16(v - __bfloat162float(h16));
    size_t o = (size_t)blockIdx.y*(Hc*Dc*Fc) + i;
    g_whi[o] = h16;
    g_wlo[o] = l16;
}

// ---------------- stage 1: L-contraction -> bf16 hi/lo [t][f] ----------------
// block (16 t, 8 f-pairs); 4 t-subtiles per block, cp.async double buffer; STG.64 writes.
__global__ __launch_bounds__(128) void k_raw(const float* __restrict__ x) {
    __shared__ float2 skv[Hc*Lc];                 // (kw, vw)
    __shared__ float xs[2][16][212];              // [buf][f][t*13+l]
    __shared__ __align__(8) unsigned s_ohi[2][Hc][16][10];  // [kv][h][t][fword] (stride 10)
    __shared__ __align__(8) unsigned s_olo[2][Hc][16][10];
    int tx = threadIdx.x;      // t
    int ty = threadIdx.y;      // f-pair
    int tid = ty*16 + tx;
    if (tid < Hc*Lc) skv[tid] = make_float2(g_kw[tid], g_vw[tid]);

    int tbase = blockIdx.x*64;
    int f0 = blockIdx.y*16;
    int b  = blockIdx.z;
    const float* xb = x + (size_t)(b*Fc + f0)*Tc*13;

    auto stage_x = [&](int buf, int st0) {
        int n = Tc - st0;
        int maxf4 = (n >= 16) ? 52 : (n > 0 ? ((n*13) >> 2) : 0);
#pragma unroll
        for (int it = 0; it < 7; it++) {
            int idx = tid + it*128;
            if (idx < 832) {
                int row = idx / 52, col = idx % 52;
                unsigned sz = (col < maxf4) ? 16u : 0u;
                int scol = (col < maxf4) ? col : 0;
                uint32_t dst = smem_u32(&xs[buf][row][col*4]);
                const float* src = xb + (size_t)row*(Tc*13) + st0*13 + scol*4;
                asm volatile("cp.async.cg.shared.global [%0], [%1], 16, %2;"
                             :: "r"(dst), "l"(src), "r"(sz));
            }
        }
        CP_COMMIT();
    };

    stage_x(0, tbase);

#pragma unroll 1
    for (int s = 0; s < 4; s++) {
        int st0 = tbase + s*16;
        if (s < 3) { stage_x((s+1) & 1, st0 + 16); CP_WAIT(1); }
        else CP_WAIT(0);
        __syncthreads();

        int buf = s & 1;
        float xv0[Lc], xv1[Lc];
#pragma unroll
        for (int l = 0; l < Lc; l++) {
            xv0[l] = xs[buf][ty*2][tx*13 + l];
            xv1[l] = xs[buf][ty*2 + 1][tx*13 + l];
        }

#pragma unroll
        for (int h = 0; h < Hc; h++) {
            float k0 = 0.f, v0 = 0.f, k1 = 0.f, v1 = 0.f;
#pragma unroll
            for (int l = 0; l < Lc; l++) {
                float2 w = skv[h*Lc + l];
                k0 += xv0[l]*w.x; v0 += xv0[l]*w.y;
                k1 += xv1[l]*w.x; v1 += xv1[l]*w.y;
            }
            {
                unsigned b0 = __float_as_uint(k0), b1 = __float_as_uint(k1);
                unsigned hiw = __byte_perm(b0, b1, 0x7632);
                float d0 = k0 - __uint_as_float(b0 & 0xffff0000u);
                float d1 = k1 - __uint_as_float(b1 & 0xffff0000u);
                unsigned low;
                asm("cvt.rn.bf16x2.f32 %0, %1, %2;" : "=r"(low) : "f"(d1), "f"(d0));
                s_ohi[0][h][tx][ty] = hiw;
                s_olo[0][h][tx][ty] = low;
            }
            {
                unsigned b0 = __float_as_uint(v0), b1 = __float_as_uint(v1);
                unsigned hiw = __byte_perm(b0, b1, 0x7632);
                float d0 = v0 - __uint_as_float(b0 & 0xffff0000u);
                float d1 = v1 - __uint_as_float(b1 & 0xffff0000u);
                unsigned low;
                asm("cvt.rn.bf16x2.f32 %0, %1, %2;" : "=r"(low) : "f"(d1), "f"(d0));
                s_ohi[1][h][tx][ty] = hiw;
                s_olo[1][h][tx][ty] = low;
            }
        }
        __syncthreads();

        // write phase: 16 jobs (kv,h) over 4 warps; STG.64 (4 bf16 per store)
        int w = tid >> 5, lane = tid & 31;
        int f4 = lane & 3;          // uint2 index (4 bf16)
        int tq = lane >> 2;         // 0..7
#pragma unroll
        for (int it = 0; it < 4; it++) {
            int job = w*4 + it;
            int kv = job >> 3;
            int h = job & 7;
            size_t rowbase = ((size_t)(kv*Bc + b)*Hc + h)*Tc;
#pragma unroll
            for (int ti = 0; ti < 2; ti++) {
                int tl = ti*8 + tq;
                int tt = st0 + tl;
                if (tt < Tc) {
                    size_t off = (rowbase + tt)*Fc + f0 + f4*4;
                    *(uint2*)(g_ahi + off) = *(uint2*)&s_ohi[kv][h][tl][f4*2];
                    *(uint2*)(g_alo + off) = *(uint2*)&s_olo[kv][h][tl][f4*2];
                }
            }
        }
        __syncthreads();
    }
}

// ---------------- stage 2: mma.sync GEMM -> [d][t] bf16 planes + stats ----------------
#define RS 80
#define PLANE_B (128*RS)
#define STAGE_B (4*PLANE_B)
#define NSTAGE 2
#define GSMEM (NSTAGE*STAGE_B)   // 81920
#define NCH (Fc/32)

__device__ __forceinline__ void prefetch_chunk(
    int c, int stage, uint32_t sb, int t0, int tid,
    const __nv_bfloat16* __restrict__ Ahi, const __nv_bfloat16* __restrict__ Alo,
    const __nv_bfloat16* __restrict__ Bhi, const __nv_bfloat16* __restrict__ Blo) {
    int kc = c*32;
    uint32_t stb = sb + stage*STAGE_B;
#pragma unroll
    for (int it = 0; it < 8; it++) {
        int idx = tid + it*256;
        int plane = idx >> 9;
        int row = (idx >> 2) & 127;
        int seg = idx & 3;
        uint32_t dst = stb + plane*PLANE_B + row*RS + seg*16;
        const __nv_bfloat16* src;
        unsigned sz = 16;
        if (plane < 2) {
            int t = t0 + row;
            if (t >= Tc) { t = 0; sz = 0; }
            src = (plane ? Alo : Ahi) + (size_t)t*Fc + kc + seg*8;
        } else {
            src = (plane == 2 ? Bhi : Blo) + (size_t)row*Fc + kc + seg*8;
        }
        asm volatile("cp.async.cg.shared.global [%0], [%1], 16, %2;"
                     :: "r"(dst), "l"(src), "r"(sz));
    }
    CP_COMMIT();
}

__global__ __launch_bounds__(256, 2) void k_gemm(
    const float* __restrict__ bk, const float* __restrict__ bv) {
    extern __shared__ __align__(1024) char dynsmem[];
    uint32_t sb = smem_u32(dynsmem);

    int tid = threadIdx.x;
    int warp = tid >> 5, lane = tid & 31;
    int bh = blockIdx.y;
    int h = bh & 7;
    int kv = blockIdx.z;
    int t0 = blockIdx.x*128;

    const __nv_bfloat16* Ahi = g_ahi + (size_t)(kv*Bc*Hc + bh)*Tc*Fc;
    const __nv_bfloat16* Alo = g_alo + (size_t)(kv*Bc*Hc + bh)*Tc*Fc;
    const __nv_bfloat16* Bhi = g_whi + (size_t)(kv*Hc + h)*Dc*Fc;
    const __nv_bfloat16* Blo = g_wlo + (size_t)(kv*Hc + h)*Dc*Fc;
    const float* bias = (kv ? bv : bk) + h*Dc;

    int m0w = (warp >> 1)*32;
    int n0w = (warp & 1)*64;
    int arow = (lane & 7) + ((lane >> 3) & 1)*8;
    int akb  = ((lane >> 4) & 1)*16;
    int brow = (lane & 7) + ((lane >> 4) & 1)*8;
    int bkb  = ((lane >> 3) & 1)*16;

    float acc[2][8][4];
#pragma unroll
    for (int i = 0; i < 2; i++)
#pragma unroll
        for (int j = 0; j < 8; j++)
#pragma unroll
            for (int r = 0; r < 4; r++) acc[i][j][r] = 0.f;

    prefetch_chunk(0, 0, sb, t0, tid, Ahi, Alo, Bhi, Blo);
    prefetch_chunk(1, 1, sb, t0, tid, Ahi, Alo, Bhi, Blo);

#pragma unroll 1
    for (int c = 0; c < NCH; c++) {
        if (c < NCH-1) CP_WAIT(1); else CP_WAIT(0);
        __syncthreads();
        uint32_t st = sb + (c & 1)*STAGE_B;
#pragma unroll
        for (int ks = 0; ks < 2; ks++) {
            unsigned ah[2][4], al[2][4];
#pragma unroll
            for (int mi = 0; mi < 2; mi++) {
                uint32_t a0 = st + (uint32_t)((m0w + mi*16 + arow)*RS + ks*32 + akb);
                LDSM4(ah[mi][0], ah[mi][1], ah[mi][2], ah[mi][3], a0);
                LDSM4(al[mi][0], al[mi][1], al[mi][2], al[mi][3], a0 + PLANE_B);
            }
#pragma unroll
            for (int ni = 0; ni < 4; ni++) {
                uint32_t b0 = st + 2*PLANE_B + (uint32_t)((n0w + ni*16 + brow)*RS + ks*32 + bkb);
                unsigned bhv[4], blv[4];
                LDSM4(bhv[0], bhv[1], bhv[2], bhv[3], b0);
                LDSM4(blv[0], blv[1], blv[2], blv[3], b0 + PLANE_B);
#pragma unroll
                for (int mi = 0; mi < 2; mi++)
#pragma unroll
                    for (int j2 = 0; j2 < 2; j2++) {
                        int nj = ni*2 + j2;
                        MMA_BF16(acc[mi][nj], ah[mi], &bhv[j2*2]);
                        MMA_BF16(acc[mi][nj], ah[mi], &blv[j2*2]);
                        MMA_BF16(acc[mi][nj], al[mi], &bhv[j2*2]);
                    }
            }
        }
        __syncthreads();
        if (c + 2 < NCH)
            prefetch_chunk(c+2, c & 1, sb, t0, tid, Ahi, Alo, Bhi, Blo);
    }

    // epilogue: transpose through smem to [d][t], emit bf16 hi/lo planes + stats
    __syncthreads();
    float* Cs = (float*)dynsmem;           // [128 d][132]
    int g = lane >> 2, q = lane & 3;
#pragma unroll
    for (int nj = 0; nj < 8; nj++) {
        int d = n0w + nj*8 + q*2;
        float2 bb = *(const float2*)(bias + d);
#pragma unroll
        for (int mi = 0; mi < 2; mi++) {
            int r = m0w + mi*16 + g;
            Cs[d*132 + r]         = acc[mi][nj][0] + bb.x;
            Cs[(d+1)*132 + r]     = acc[mi][nj][1] + bb.y;
            Cs[d*132 + r + 8]     = acc[mi][nj][2] + bb.x;
            Cs[(d+1)*132 + r + 8] = acc[mi][nj][3] + bb.y;
        }
    }
    __syncthreads();

    __nv_bfloat16* Phi = g_chi + ((size_t)kv*64 + bh)*DT;
    __nv_bfloat16* Plo = g_clo + ((size_t)kv*64 + bh)*DT;
    size_t so = ((size_t)kv*64 + bh)*Dc;
    int tb = t0 + lane*4;
#pragma unroll 1
    for (int rr = 0; rr < 16; rr++) {
        int d = warp*16 + rr;
        float4 v = *(float4*)&Cs[d*132 + lane*4];
        v.x = (tb+0 < Tc) ? v.x : 0.f;
        v.y = (tb+1 < Tc) ? v.y : 0.f;
        v.z = (tb+2 < Tc) ? v.z : 0.f;
        v.w = (tb+3 < Tc) ? v.w : 0.f;
        __nv_bfloat162 h01 = __floats2bfloat162_rn(v.x, v.y);
        __nv_bfloat162 h23 = __floats2bfloat162_rn(v.z, v.w);
        unsigned uh01 = *(unsigned*)&h01, uh23 = *(unsigned*)&h23;
        float f0 = __int_as_float(uh01 << 16);
        float f1 = __int_as_float(uh01 & 0xffff0000u);
        float f2 = __int_as_float(uh23 << 16);
        float f3 = __int_as_float(uh23 & 0xffff0000u);
        __nv_bfloat162 l01 = __floats2bfloat162_rn(v.x - f0, v.y - f1);
        __nv_bfloat162 l23 = __floats2bfloat162_rn(v.z - f2, v.w - f3);
        *(uint2*)(Phi + (size_t)d*TP + tb) = make_uint2(uh01, uh23);
        *(uint2*)(Plo + (size_t)d*TP + tb) = make_uint2(*(unsigned*)&l01, *(unsigned*)&l23);
        float p1 = v.x + v.y + v.z + v.w;
        float p2 = v.x*v.x + v.y*v.y + v.z*v.z + v.w*v.w;
        for (int off = 16; off; off >>= 1) {
            p1 += __shfl_down_sync(~0u, p1, off);
            p2 += __shfl_down_sync(~0u, p2, off);
        }
        if (lane == 0) {
            atomicAdd(&g_s1[so + d], p1);
            atomicAdd(&g_s2[so + d], p2);
        }
    }
}

// ---------------- stats finalize + outs init ----------------
__global__ void k_statfin(const float* __restrict__ bproj) {
    int bid = blockIdx.x;
    int tid = threadIdx.x;
    if (bid < 64) {
        int kv = tid >> 7;
        int d = tid & 127;
        size_t o = ((size_t)kv*64 + bid)*Dc + d;
        float s1 = g_s1[o], s2 = g_s2[o];
        float mu = s1 * (1.f/Tc);
        float var = (s2 - (float)Tc*mu*mu) * (1.f/(Tc-1));
        var = fmaxf(var, 0.f);
        float sd = sqrtf(var) + 1e-9f;
        if (kv == 0) { g_muk[bid*Dc + d] = mu; g_sdk[bid*Dc + d] = sd; }
        else         { g_muv[bid*Dc + d] = mu; g_sdv[bid*Dc + d] = sd; }
    } else {
        for (int i = tid; i < Bc*Hc*Ec; i += 256)
            g_outs[i] = bproj[i & (Hc*Ec - 1)];
    }
}

// ---------------- stage 3a: attention + o1 (coalesced [d][t]) ----------------
__global__ __launch_bounds__(256) void k_attn(const float* __restrict__ q) {
    __shared__ float s_sc[TP];
    __shared__ float s_red[256];
    __shared__ float s_q[Dc];
    int tid = threadIdx.x;
    int bh = blockIdx.x;
    int h = bh & 7;
    const __nv_bfloat16* Khi = g_chi + (size_t)bh*DT;
    const __nv_bfloat16* Klo = g_clo + (size_t)bh*DT;
    const __nv_bfloat16* Vhi = g_chi + (size_t)(64 + bh)*DT;
    const __nv_bfloat16* Vlo = g_clo + (size_t)(64 + bh)*DT;
    if (tid < Dc) s_q[tid] = q[h*Dc + tid];
    __syncthreads();

    if (tid < 250) {
        float a0 = 0.f, a1 = 0.f, a2 = 0.f, a3 = 0.f;
#pragma unroll 4
        for (int d = 0; d < Dc; d++) {
            uint2 ph = *(const uint2*)(Khi + (size_t)d*TP + tid*4);
            uint2 pl = *(const uint2*)(Klo + (size_t)d*TP + tid*4);
            float qd = s_q[d];
            float4 kv4 = un4(ph, pl);
            a0 += qd*kv4.x; a1 += qd*kv4.y; a2 += qd*kv4.z; a3 += qd*kv4.w;
        }
        const float sc = 0.08838834764831845f;
        *(float4*)&s_sc[tid*4] = make_float4(a0*sc, a1*sc, a2*sc, a3*sc);
    }
    if (tid < 24) s_sc[1000 + tid] = 0.f;
    __syncthreads();

    float lm = -1e30f;
    for (int t = tid; t < Tc; t += 256) lm = fmaxf(lm, s_sc[t]);
    s_red[tid] = lm; __syncthreads();
    for (int s = 128; s; s >>= 1) { if (tid < s) s_red[tid] = fmaxf(s_red[tid], s_red[tid+s]); __syncthreads(); }
    float m = s_red[0];
    __syncthreads();
    float ls = 0.f;
    for (int t = tid; t < Tc; t += 256) { float e = expf(s_sc[t]-m); s_sc[t] = e; ls += e; }
    s_red[tid] = ls; __syncthreads();
    for (int s = 128; s; s >>= 1) { if (tid < s) s_red[tid] += s_red[tid+s]; __syncthreads(); }
    float inv = 1.f / s_red[0];
    __syncthreads();

    int w = tid >> 5, lane = tid & 31;
#pragma unroll 1
    for (int rr = 0; rr < 16; rr++) {
        int d = w*16 + rr;
        float acc = 0.f;
#pragma unroll
        for (int cc = 0; cc < 8; cc++) {
            int grp = lane + cc*32;
            uint2 ph = *(const uint2*)(Vhi + (size_t)d*TP + grp*4);
            uint2 pl = *(const uint2*)(Vlo + (size_t)d*TP + grp*4);
            float4 vv = un4(ph, pl);
            float4 aa = *(float4*)&s_sc[grp*4];
            acc += aa.x*vv.x + aa.y*vv.y + aa.z*vv.z + aa.w*vv.w;
        }
        for (int off = 16; off; off >>= 1) acc += __shfl_down_sync(~0u, acc, off);
        if (lane == 0) g_o1[bh*Dc + d] = acc * inv;
    }
}

// ---------------- stage 3b: S = K^T V via tensor cores on [d][t] planes ----------------
#define NCHS 16

__device__ __forceinline__ void prefetch_smat(
    int c, int stage, uint32_t sb, int tid,
    const __nv_bfloat16* __restrict__ Ahi, const __nv_bfloat16* __restrict__ Alo,
    const __nv_bfloat16* __restrict__ Bhi, const __nv_bfloat16* __restrict__ Blo) {
    int kc = c*32;
    uint32_t stb = sb + stage*STAGE_B;
#pragma unroll
    for (int it = 0; it < 8; it++) {
        int idx = tid + it*256;
        int plane = idx >> 9;
        int row = (idx >> 2) & 127;
        int seg = idx & 3;
        uint32_t dst = stb + plane*PLANE_B + row*RS + seg*16;
        const __nv_bfloat16* src =
            (plane == 0 ? Ahi : plane == 1 ? Alo : plane == 2 ? Bhi : Blo)
            + (size_t)row*TP + kc + seg*8;
        asm volatile("cp.async.cg.shared.global [%0], [%1], 16;" :: "r"(dst), "l"(src));
    }
    CP_COMMIT();
}

__global__ __launch_bounds__(256, 2) void k_smat() {
    extern __shared__ __align__(1024) char dynsmem[];
    uint32_t sb = smem_u32(dynsmem);
    int tid = threadIdx.x;
    int warp = tid >> 5, lane = tid & 31;
    int bh = blockIdx.y;
    int seg = blockIdx.x;
    const __nv_bfloat16* Ahi = g_chi + (size_t)bh*DT + seg*512;
    const __nv_bfloat16* Alo = g_clo + (size_t)bh*DT + seg*512;
    const __nv_bfloat16* Bhi = g_chi + (size_t)(64 + bh)*DT + seg*512;
    const __nv_bfloat16* Blo = g_clo + (size_t)(64 + bh)*DT + seg*512;

    int m0w = (warp >> 1)*32;
    int n0w = (warp & 1)*64;
    int arow = (lane & 7) + ((lane >> 3) & 1)*8;
    int akb  = ((lane >> 4) & 1)*16;
    int brow = (lane & 7) + ((lane >> 4) & 1)*8;
    int bkb  = ((lane >> 3) & 1)*16;

    float acc[2][8][4];
#pragma unroll
    for (int i = 0; i < 2; i++)
#pragma unroll
        for (int j = 0; j < 8; j++)
#pragma unroll
            for (int r = 0; r < 4; r++) acc[i][j][r] = 0.f;

    prefetch_smat(0, 0, sb, tid, Ahi, Alo, Bhi, Blo);
    prefetch_smat(1, 1, sb, tid, Ahi, Alo, Bhi, Blo);

#pragma unroll 1
    for (int c = 0; c < NCHS; c++) {
        if (c < NCHS-1) CP_WAIT(1); else CP_WAIT(0);
        __syncthreads();
        uint32_t st = sb + (c & 1)*STAGE_B;
#pragma unroll
        for (int ks = 0; ks < 2; ks++) {
            unsigned ah[2][4], al[2][4];
#pragma unroll
            for (int mi = 0; mi < 2; mi++) {
                uint32_t a0 = st + (uint32_t)((m0w + mi*16 + arow)*RS + ks*32 + akb);
                LDSM4(ah[mi][0], ah[mi][1], ah[mi][2], ah[mi][3], a0);
                LDSM4(al[mi][0], al[mi][1], al[mi][2], al[mi][3], a0 + PLANE_B);
            }
#pragma unroll
            for (int ni = 0; ni < 4; ni++) {
                uint32_t b0 = st + 2*PLANE_B + (uint32_t)((n0w + ni*16 + brow)*RS + ks*32 + bkb);
                unsigned bhv[4], blv[4];
                LDSM4(bhv[0], bhv[1], bhv[2], bhv[3], b0);
                LDSM4(blv[0], blv[1], blv[2], blv[3], b0 + PLANE_B);
#pragma unroll
                for (int mi = 0; mi < 2; mi++)
#pragma unroll
                    for (int j2 = 0; j2 < 2; j2++) {
                        int nj = ni*2 + j2;
                        MMA_BF16(acc[mi][nj], ah[mi], &bhv[j2*2]);
                        MMA_BF16(acc[mi][nj], ah[mi], &blv[j2*2]);
                        MMA_BF16(acc[mi][nj], al[mi], &bhv[j2*2]);
                    }
            }
        }
        __syncthreads();
        if (c + 2 < NCHS)
            prefetch_smat(c+2, c & 1, sb, tid, Ahi, Alo, Bhi, Blo);
    }

    float* Sp = g_S + (size_t)bh*Dc*Dc;
    int g = lane >> 2, q = lane & 3;
#pragma unroll
    for (int nj = 0; nj < 8; nj++) {
        int l = n0w + nj*8 + q*2;
#pragma unroll
        for (int mi = 0; mi < 2; mi++) {
            int k0 = m0w + mi*16 + g;
            atomicAdd(&Sp[k0*Dc + l],       acc[mi][nj][0]);
            atomicAdd(&Sp[k0*Dc + l + 1],   acc[mi][nj][1]);
            atomicAdd(&Sp[(k0+8)*Dc + l],   acc[mi][nj][2]);
            atomicAdd(&Sp[(k0+8)*Dc + l+1], acc[mi][nj][3]);
        }
    }
}

// ---------------- stage 3c: normalized correlation ----------------
__global__ void k_corr() {
    int c = blockIdx.x*256 + threadIdx.x;
    int bh = blockIdx.y;
    if (c >= DCORR) return;
    float disc = 65025.0f - 8.0f*(float)c;
    int k = (int)((255.0f - sqrtf(disc))*0.5f);
    if (k < 0) k = 0;
    if (k > 126) k = 126;
    while (k > 0 && k*(255-k)/2 > c) k--;
    while ((k+1)*(254-k)/2 <= c) k++;
    int l = k + 1 + (c - k*(255-k)/2);
    float muk = g_muk[bh*Dc + k], sdk = g_sdk[bh*Dc + k];
    float muv = g_muv[bh*Dc + l], sdv = g_sdv[bh*Dc + l];
    float S = g_S[(size_t)bh*Dc*Dc + k*Dc + l];
    g_corr[(size_t)bh*DCORR + c] = (S - (float)Tc*muk*muv) / ((float)Tc*sdk*sdv);
}

// ---------------- stage 4: outs += corr . Wproj ----------------
__global__ __launch_bounds__(256) void k_proj(const float* __restrict__ Wproj) {
    __shared__ float sc[8][128];
    int tid = threadIdx.x;
    int h = blockIdx.y;
    int cs = blockIdx.z;
    int el = tid & 31;
    int b = tid >> 5;
    int e = blockIdx.x*32 + el;
    int lrow = tid >> 5;
    int lc = (tid & 31)*4;
    int start = cs*2032, end = start + 2032;
    const float* wrow = Wproj + ((size_t)h*Ec + e)*DCORR;
    float acc = 0.f;
    for (int c0 = start; c0 < end; c0 += 128) {
        int lim = end - c0; if (lim > 128) lim = 128;
        float4 cv = make_float4(0.f,0.f,0.f,0.f);
        if (lc < lim) cv = *(const float4*)(g_corr + ((size_t)lrow*Hc + h)*DCORR + c0 + lc);
        *(float4*)&sc[lrow][lc] = cv;
        __syncthreads();
#pragma unroll 8
        for (int j = 0; j < lim; j += 4) {
            float4 wv = *(const float4*)(wrow + c0 + j);
            float4 sv = *(const float4*)&sc[b][j];
            acc += wv.x*sv.x + wv.y*sv.y + wv.z*sv.z + wv.w*sv.w;
        }
        __syncthreads();
    }
    atomicAdd(&g_outs[b*(Hc*Ec) + h*Ec + e], acc);
}

// ---------------- stage 5: final linears + mix ----------------
__global__ __launch_bounds__(256) void k_final(
    const float* __restrict__ WT, const float* __restrict__ bT,
    const float* __restrict__ Wp, const float* __restrict__ bp,
    float* __restrict__ out) {
    __shared__ float so1[Hc*Dc];
    __shared__ float sout[Hc*Ec];
    __shared__ float sred[256];
    int b = blockIdx.x, ec = blockIdx.y;
    int tid = threadIdx.x;
    for (int j = tid; j < Hc*Dc; j += 256) so1[j]  = g_o1[b*Hc*Dc + j];
    for (int j = tid; j < Hc*Ec; j += 256) sout[j] = g_outs[b*Hc*Ec + j];
    __syncthreads();
    int e_l = tid >> 3, js = tid & 7;
    int e = ec*32 + e_l;
    float a = 0.f;
    const float* wt = WT + (size_t)e*(Hc*Dc) + js*128;
    const float* s1p = so1 + js*128;
#pragma unroll 4
    for (int j = 0; j < 128; j += 4) {
        float4 wv = *(const float4*)(wt + j);
        float4 sv = *(const float4*)(s1p + j);
        a += wv.x*sv.x + wv.y*sv.y + wv.z*sv.z + wv.w*sv.w;
    }
    const float* wp = Wp + (size_t)e*(Hc*Ec) + js*256;
    const float* s2p = sout + js*256;
#pragma unroll 4
    for (int j = 0; j < 256; j += 4) {
        float4 wv = *(const float4*)(wp + j);
        float4 sv = *(const float4*)(s2p + j);
        a += wv.x*sv.x + wv.y*sv.y + wv.z*sv.z + wv.w*sv.w;
    }
    if (js == 0) a += bT[e] + bp[e];
    sred[tid] = a;
    __syncthreads();
    if (tid < 32) {
        float s = 0.f;
#pragma unroll
        for (int k = 0; k < 8; k++) s += sred[tid*8 + k];
        out[b*Ec + ec*32 + tid] = 0.5f*s;
    }
}

// ---------------- launch ----------------
extern "C" void kernel_launch(void* const* d_in, const int* in_sizes, int n_in,
                              void* d_out, int out_size) {
    const float* x     = (const float*)d_in[0];
    const float* wk    = (const float*)d_in[1];
    const float* wv    = (const float*)d_in[2];
    const float* q     = (const float*)d_in[3];
    const float* Wk    = (const float*)d_in[4];
    const float* bk    = (const float*)d_in[5];
    const float* Wv    = (const float*)d_in[6];
    const float* bv    = (const float*)d_in[7];
    const float* Wproj = (const float*)d_in[8];
    const float* bproj = (const float*)d_in[9];
    const float* WT    = (const float*)d_in[10];
    const float* bT    = (const float*)d_in[11];
    const float* Wp    = (const float*)d_in[12];
    const float* bp    = (const float*)d_in[13];
    float* out = (float*)d_out;

    cudaFuncSetAttribute(k_gemm, cudaFuncAttributeMaxDynamicSharedMemorySize, GSMEM);
    cudaFuncSetAttribute(k_smat, cudaFuncAttributeMaxDynamicSharedMemorySize, GSMEM);

    k_init<<<1056, 256>>>(wk, wv);
    k_raw<<<dim3(16, Fc/16, Bc), dim3(16, 8)>>>(x);
    k_wconv<<<dim3((Hc*Dc*Fc)/256, 2), 256>>>(Wk, Wv);
    k_gemm<<<dim3(8, Bc*Hc, 2), 256, GSMEM>>>(bk, bv);   // 4th launch -> ncu target
    k_statfin<<<65, 256>>>(bproj);
    k_attn<<<Bc*Hc, 256>>>(q);
    k_smat<<<dim3(2, Bc*Hc), 256, GSMEM>>>();
    k_corr<<<dim3((DCORR+255)/256, Bc*Hc), 256>>>();
    k_proj<<<dim3(Ec/32, Hc, 4), 256>>>(Wproj);
    k_final<<<dim3(Bc, Ec/32), 256>>>(WT, bT, Wp, bp, out);
}